// round 7
// baseline (speedup 1.0000x reference)
#include <cuda_runtime.h>
#include <cuda_bf16.h>
#include <math.h>
#include <stdint.h>

// ---------------- problem constants ----------------
#define BB   2
#define TT   2048
#define DM   512
#define NH   8
#define DH   64
#define DFF  2048
#define MM   (BB*TT)        // 4096 rows
#define CHK  64
#define NC   (TT/CHK)       // 32
#define BH   (BB*NH)        // 16
#define STR  68
#define K3DM (3*DM)         // 1536
#define K3FF (3*DFF)        // 6144

// ---------------- scratch (device globals) ----------------
__device__ __align__(256) __nv_bfloat16 g_h3   [MM*K3DM];
__device__ __align__(256) float          g_q    [MM*DM];
__device__ __align__(256) float          g_k    [MM*DM];
__device__ __align__(256) float          g_v    [MM*DM];
__device__ __align__(256) __nv_bfloat16 g_attn3[MM*K3DM];
__device__ __align__(256) float          g_x2   [MM*DM];
__device__ __align__(256) __nv_bfloat16 g_h23  [MM*K3DM];
__device__ __align__(256) __nv_bfloat16 g_ffn3 [MM*K3FF];
__device__ __align__(256) __nv_bfloat16 g_wqkv3[3*DM*K3DM];   // rows: [Wq|Wk|Wv]
__device__ __align__(256) __nv_bfloat16 g_wo3  [DM*K3DM];
__device__ __align__(256) __nv_bfloat16 g_w13  [DFF*K3DM];
__device__ __align__(256) __nv_bfloat16 g_w23  [DM*K3FF];
__device__ __align__(256) float g_ckv[BH*NC*DH*DH];
__device__ __align__(256) float g_cz [BH*NC*DH];
__device__ __align__(256) float g_Sp [BH*NC*DH*DH];
__device__ __align__(256) float g_zp [BH*NC*DH];

// ---------------- helpers ----------------
__device__ __forceinline__ uint32_t smem_u32(const void* p){
    uint32_t a;
    asm("{ .reg .u64 t; cvta.to.shared.u64 t, %1; cvt.u32.u64 %0, t; }"
        : "=r"(a) : "l"(p));
    return a;
}
__device__ __forceinline__ void cp16(uint32_t dst, const void* src){
    asm volatile("cp.async.cg.shared.global [%0], [%1], 16;" :: "r"(dst), "l"(src));
}
__device__ __forceinline__ void cp_commit(){
    asm volatile("cp.async.commit_group;");
}
template<int N> __device__ __forceinline__ void cp_wait(){
    asm volatile("cp.async.wait_group %0;" :: "n"(N));
}
__device__ __forceinline__ void bsplit(float v, __nv_bfloat16& h, __nv_bfloat16& l){
    h = __float2bfloat16(v);
    l = __float2bfloat16(v - __bfloat162float(h));
}
__device__ __forceinline__ void mma_bf16(float* d, const uint32_t* a, const uint32_t* b){
    asm volatile(
        "mma.sync.aligned.m16n8k16.row.col.f32.bf16.bf16.f32 "
        "{%0,%1,%2,%3}, {%4,%5,%6,%7}, {%8,%9}, {%0,%1,%2,%3};"
        : "+f"(d[0]), "+f"(d[1]), "+f"(d[2]), "+f"(d[3])
        : "r"(a[0]), "r"(a[1]), "r"(a[2]), "r"(a[3]), "r"(b[0]), "r"(b[1]));
}
__device__ __forceinline__ void ldsm4(uint32_t& r0, uint32_t& r1, uint32_t& r2,
                                      uint32_t& r3, uint32_t addr){
    asm volatile("ldmatrix.sync.aligned.m8n8.x4.shared.b16 {%0,%1,%2,%3}, [%4];"
                 : "=r"(r0), "=r"(r1), "=r"(r2), "=r"(r3) : "r"(addr));
}

// ---------------- layernorm -> triple-bf16 (A-side [hi,lo,hi]) ----------------
__global__ __launch_bounds__(256) void ln3_kernel(
    const float* __restrict__ x, const float* __restrict__ g,
    const float* __restrict__ b, __nv_bfloat16* __restrict__ o3)
{
    int row = blockIdx.x;
    const float* xr = x + (size_t)row*DM;
    int tid = threadIdx.x;
    float v0 = xr[tid], v1 = xr[tid+256];
    float s = v0+v1, s2 = v0*v0+v1*v1;
#pragma unroll
    for (int off=16; off; off>>=1){
        s  += __shfl_xor_sync(0xffffffffu, s,  off);
        s2 += __shfl_xor_sync(0xffffffffu, s2, off);
    }
    __shared__ float rs[8], rs2[8], mu_s, rstd_s;
    if ((tid&31)==0){ rs[tid>>5]=s; rs2[tid>>5]=s2; }
    __syncthreads();
    if (tid==0){
        float a=0.f,c=0.f;
#pragma unroll
        for (int i=0;i<8;i++){ a+=rs[i]; c+=rs2[i]; }
        float mu = a*(1.0f/DM);
        float var = c*(1.0f/DM) - mu*mu;
        mu_s = mu; rstd_s = rsqrtf(var + 1e-5f);
    }
    __syncthreads();
    float mu = mu_s, rstd = rstd_s;
    __nv_bfloat16* orow = o3 + (size_t)row*K3DM;
    {
        float y = (v0-mu)*rstd*g[tid] + b[tid];
        __nv_bfloat16 h,l; bsplit(y,h,l);
        orow[tid] = h; orow[tid+DM] = l; orow[tid+2*DM] = h;
    }
    {
        int c1 = tid+256;
        float y = (v1-mu)*rstd*g[c1] + b[c1];
        __nv_bfloat16 h,l; bsplit(y,h,l);
        orow[c1] = h; orow[c1+DM] = l; orow[c1+2*DM] = h;
    }
}

// -------- fused weight transpose+split: all 6 weights in ONE launch ----------
__global__ __launch_bounds__(256) void wconv_all_kernel(
    const float* __restrict__ Wq, const float* __restrict__ Wk,
    const float* __restrict__ Wv, const float* __restrict__ Wo,
    const float* __restrict__ W1, const float* __restrict__ W2,
    __nv_bfloat16* __restrict__ wqkv3, __nv_bfloat16* __restrict__ wo3,
    __nv_bfloat16* __restrict__ w13,   __nv_bfloat16* __restrict__ w23)
{
    int bid = blockIdx.x;
    const float* W; __nv_bfloat16* B3;
    int Kd, Nd, nx, local;
    if (bid < 512){
        int seg = bid >> 7; local = bid & 127; nx = 16; Kd = 512; Nd = 512;
        W  = (seg==0)?Wq:(seg==1)?Wk:(seg==2)?Wv:Wo;
        B3 = (seg==0)?wqkv3:(seg==1)?(wqkv3+512*K3DM):(seg==2)?(wqkv3+1024*K3DM):wo3;
    } else if (bid < 1024){
        local = bid - 512; nx = 64; Kd = 512; Nd = 2048; W = W1; B3 = w13;
    } else {
        local = bid - 1024; nx = 16; Kd = 2048; Nd = 512; W = W2; B3 = w23;
    }
    int n0 = (local % nx)*32, k0 = (local / nx)*64;

    __shared__ float t[64][33];
    int tx = threadIdx.x, ty = threadIdx.y;
#pragma unroll
    for (int i=ty;i<64;i+=8)
        t[i][tx] = W[(size_t)(k0+i)*Nd + n0 + tx];
    __syncthreads();
#pragma unroll
    for (int i=ty;i<32;i+=8){
        float va = t[2*tx][i], vb = t[2*tx+1][i];
        __nv_bfloat16 ha,la,hb,lb;
        bsplit(va,ha,la); bsplit(vb,hb,lb);
        uint32_t hw = ((uint32_t)__bfloat16_as_ushort(hb)<<16) | __bfloat16_as_ushort(ha);
        uint32_t lw = ((uint32_t)__bfloat16_as_ushort(lb)<<16) | __bfloat16_as_ushort(la);
        size_t base = (size_t)(n0+i)*(3*Kd) + k0 + 2*tx;
        *(uint32_t*)&B3[base]        = hw;
        *(uint32_t*)&B3[base+Kd]     = hw;
        *(uint32_t*)&B3[base+2*Kd]   = lw;
    }
}

// ---------------- mma.sync bf16 GEMM (templated tile), 2 CTAs/SM ----------------
// TMv in {128, 64}; TN=128, K-chunk 64. 8 warps: wm=wid>>1 (4), wn=wid&1 (2).
// Warp tile: (TMv/4) x 64; MF = TMv/64 m-fragments of 16 rows.
// modes: 2 +bias0+res -> C0; 3 relu(+bias0) -> triple bf16 C3;
//        4 qkv split: n<512 -> C0(elu+1,bias0), <1024 -> C1(elu+1,bias1), else C2(bias2)
#define TN 128
#define RS 72                       // padded smem row (elements)
#define SMEM_MM 110592              // both variants use this (2 CTAs/SM)

template<int TMv, int NSTGv>
__global__ __launch_bounds__(256, 2) void mm_kernel(
    const __nv_bfloat16* __restrict__ Ap, const __nv_bfloat16* __restrict__ Bp,
    const float* __restrict__ bias0, const float* __restrict__ bias1,
    const float* __restrict__ bias2, const float* __restrict__ res,
    float* __restrict__ C0, float* __restrict__ C1, float* __restrict__ C2,
    __nv_bfloat16* __restrict__ C3,
    int Np, int Kp, int mode)
{
    constexpr int MF   = TMv/64;            // m-fragments (16 rows each) per warp
    constexpr int ABYv = TMv*RS*2;
    constexpr int STGv = (TMv+TN)*RS*2;
    extern __shared__ char smc[];
    uint32_t sb = smem_u32(smc);

    int tid = threadIdx.x;
    int lane = tid & 31, wid = tid >> 5;
    int wm = wid >> 1, wn = wid & 1;
    int g = lane >> 2, qp = lane & 3;
    int bm = blockIdx.y * TMv;
    int bn = blockIdx.x * TN;

    const char* Abase = (const char*)(Ap + (size_t)bm*Kp);
    const char* Bbase = (const char*)(Bp + (size_t)bn*Kp);
    const size_t rowb = (size_t)Kp*2;

    int lr_ = tid >> 3, lc_ = (tid & 7)*16;
    auto loadStage = [&](int c, int s){
        uint32_t da = sb + (uint32_t)s*STGv;
        uint32_t db = da + ABYv;
        const char* sa = Abase + (size_t)c*128 + (size_t)lr_*rowb + lc_;
        const char* sbp= Bbase + (size_t)c*128 + (size_t)lr_*rowb + lc_;
        uint32_t so = (uint32_t)(lr_*(RS*2) + lc_);
#pragma unroll
        for (int t=0;t<TMv/32;t++)
            cp16(da + so + t*32*(RS*2), sa + (size_t)t*32*rowb);
#pragma unroll
        for (int t=0;t<TN/32;t++)
            cp16(db + so + t*32*(RS*2), sbp + (size_t)t*32*rowb);
        cp_commit();
    };

    // per-lane ldmatrix base offsets (within a stage)
    uint32_t a_off[MF], b_off[4];
#pragma unroll
    for (int mf=0; mf<MF; mf++){
        int arow = wm*(MF*16) + mf*16 + (lane & 15);
        a_off[mf] = (uint32_t)(arow*(RS*2) + ((lane & 16) ? 16 : 0));
    }
#pragma unroll
    for (int p=0; p<4; p++){
        int nrow = wn*64 + p*16 + (lane & 7) + ((lane & 16) >> 1);
        b_off[p] = (uint32_t)(nrow*(RS*2) + ((lane & 8) ? 16 : 0)) + ABYv;
    }

    float acc[MF][8][4];
#pragma unroll
    for (int i=0;i<MF;i++)
#pragma unroll
        for (int j=0;j<8;j++)
#pragma unroll
            for (int k=0;k<4;k++) acc[i][j][k]=0.f;

    const int nch = Kp >> 6;
#pragma unroll
    for (int s=0;s<NSTGv-1;s++) loadStage(s, s);

    int cur = 0, nxt = NSTGv-1;
    for (int i=0;i<nch;i++){
        cp_wait<NSTGv-2>();
        __syncthreads();
        if (i+NSTGv-1 < nch) loadStage(i+NSTGv-1, nxt);
        else cp_commit();   // keep outstanding-group count invariant
        uint32_t S = sb + (uint32_t)cur*STGv;
#pragma unroll
        for (int ks=0; ks<4; ks++){
            uint32_t koff = (uint32_t)(ks*32);
            uint32_t a[MF][4];
#pragma unroll
            for (int mf=0; mf<MF; mf++)
                ldsm4(a[mf][0],a[mf][1],a[mf][2],a[mf][3], S + a_off[mf] + koff);
            uint32_t b[8][2];
#pragma unroll
            for (int p=0; p<4; p++)
                ldsm4(b[2*p][0],b[2*p][1],b[2*p+1][0],b[2*p+1][1],
                      S + b_off[p] + koff);
#pragma unroll
            for (int mf=0; mf<MF; mf++)
#pragma unroll
                for (int nf=0; nf<8; nf++)
                    mma_bf16(acc[mf][nf], a[mf], b[nf]);
        }
        cur = (cur==NSTGv-1) ? 0 : cur+1;
        nxt = (nxt==NSTGv-1) ? 0 : nxt+1;
    }

    // ---- epilogue ----
#pragma unroll
    for (int mf=0; mf<MF; mf++){
#pragma unroll
        for (int half=0; half<2; half++){
            int m = bm + wm*(MF*16) + mf*16 + g + half*8;
#pragma unroll
            for (int nf=0; nf<8; nf++){
                int n = bn + wn*64 + nf*8 + qp*2;
                float v0 = acc[mf][nf][half*2+0];
                float v1 = acc[mf][nf][half*2+1];
                if (mode==4){
                    int sel = n >> 9;           // 0:q 1:k 2:v
                    int col = n & 511;
                    const float* bs = (sel==0) ? bias0 : (sel==1) ? bias1 : bias2;
                    v0 += bs[col]; v1 += bs[col+1];
                    if (sel < 2){
                        v0 = (v0 > 0.f) ? (v0+1.f) : expf(v0);
                        v1 = (v1 > 0.f) ? (v1+1.f) : expf(v1);
                    }
                    float* Cs = (sel==0) ? C0 : (sel==1) ? C1 : C2;
                    *(float2*)&Cs[(size_t)m*512 + col] = make_float2(v0, v1);
                } else {
                    v0 += bias0[n]; v1 += bias0[n+1];
                    if (mode==3){
                        v0 = fmaxf(v0, 0.f); v1 = fmaxf(v1, 0.f);
                        __nv_bfloat16 h0,l0,h1,l1;
                        bsplit(v0,h0,l0); bsplit(v1,h1,l1);
                        uint32_t hw = ((uint32_t)__bfloat16_as_ushort(h1)<<16) | __bfloat16_as_ushort(h0);
                        uint32_t lw = ((uint32_t)__bfloat16_as_ushort(l1)<<16) | __bfloat16_as_ushort(l0);
                        __nv_bfloat16* p0 = C3 + (size_t)m*3*Np + n;
                        *(uint32_t*)(p0)        = hw;
                        *(uint32_t*)(p0 + Np)   = lw;
                        *(uint32_t*)(p0 + 2*Np) = hw;
                    } else {
                        if (mode==2){
                            float2 rr = *(const float2*)&res[(size_t)m*Np + n];
                            v0 += rr.x; v1 += rr.y;
                        }
                        *(float2*)&C0[(size_t)m*Np + n] = make_float2(v0, v1);
                    }
                }
            }
        }
    }
}

// ---------------- per-chunk K^T V and K sums ----------------
__global__ __launch_bounds__(256) void chunk_sums_kernel(
    const float* __restrict__ Kf, const float* __restrict__ Vf,
    float* __restrict__ ckv, float* __restrict__ cz)
{
    __shared__ float Ks[CHK*DH];
    __shared__ float Vs[CHK*DH];
    int blk = blockIdx.x;
    int c = blk % NC, bh = blk / NC;
    int b = bh / NH, h = bh % NH;
    int t0 = c*CHK;
    int tid = threadIdx.x;
    int lr = tid >> 4;
    int lc = (tid & 15) * 4;
    for (int r = lr; r < CHK; r += 16){
        size_t gi = ((size_t)(b*TT + t0 + r))*DM + h*DH + lc;
        *(float4*)&Ks[r*DH+lc] = *(const float4*)(Kf+gi);
        *(float4*)&Vs[r*DH+lc] = *(const float4*)(Vf+gi);
    }
    __syncthreads();
    int ti = (tid>>4)*4, tj = (tid&15)*4;
    float acc[4][4];
#pragma unroll
    for (int i=0;i<4;i++)
#pragma unroll
        for (int j=0;j<4;j++) acc[i][j]=0.f;
    for (int t=0;t<CHK;t++){
        float4 kv = *(const float4*)&Ks[t*DH+ti];
        float4 vv = *(const float4*)&Vs[t*DH+tj];
        float kk[4]={kv.x,kv.y,kv.z,kv.w}, vf[4]={vv.x,vv.y,vv.z,vv.w};
#pragma unroll
        for (int i=0;i<4;i++)
#pragma unroll
            for (int j=0;j<4;j++) acc[i][j] += kk[i]*vf[j];
    }
    float* outp = ckv + (size_t)blk*DH*DH;
#pragma unroll
    for (int i=0;i<4;i++)
        *(float4*)&outp[(ti+i)*DH + tj] =
            make_float4(acc[i][0],acc[i][1],acc[i][2],acc[i][3]);
    if (tid < DH){
        float zsum = 0.f;
        for (int t=0;t<CHK;t++) zsum += Ks[t*DH+tid];
        cz[(size_t)blk*DH + tid] = zsum;
    }
}

// --------- parallel exclusive scan over chunk states: 1 elem / thread ---------
__global__ __launch_bounds__(256) void scan_kernel(
    const float* __restrict__ ckv, const float* __restrict__ cz,
    float* __restrict__ Sp, float* __restrict__ zp)
{
    int bh = blockIdx.x >> 4;
    int e  = ((blockIdx.x & 15) << 8) + threadIdx.x;   // 0..4095
    size_t base = ((size_t)bh*NC)*(DH*DH) + e;
    float v[NC];
#pragma unroll
    for (int c=0;c<NC;c++) v[c] = ckv[base + (size_t)c*(DH*DH)];
    float s = 0.f;
#pragma unroll
    for (int c=0;c<NC;c++){ Sp[base + (size_t)c*(DH*DH)] = s; s += v[c]; }

    if ((blockIdx.x & 15)==0 && threadIdx.x < DH){
        size_t zb = (size_t)bh*NC*DH + threadIdx.x;
        float zv[NC];
#pragma unroll
        for (int c=0;c<NC;c++) zv[c] = cz[zb + (size_t)c*DH];
        float z = 0.f;
#pragma unroll
        for (int c=0;c<NC;c++){ zp[zb + (size_t)c*DH] = z; z += zv[c]; }
    }
}

// ---------------- intra-chunk attention -> triple bf16 output ----------------
__global__ __launch_bounds__(256) void intra_kernel(
    const float* __restrict__ Qf, const float* __restrict__ Kf,
    const float* __restrict__ Vf, const float* __restrict__ Sp,
    const float* __restrict__ zp, __nv_bfloat16* __restrict__ attn3)
{
    extern __shared__ float smf[];
    float* Qt = smf;
    float* Kt = Qt + 64*STR;
    float* Vs = Kt + 64*STR;
    float* Ss = Vs + 64*STR;
    float* At = Ss + 64*STR;
    float* zs = At + 64*STR;
    float* dn = zs + 64;

    int blk = blockIdx.x;
    int c = blk % NC, bh = blk / NC;
    int b = bh / NH, h = bh % NH;
    int t0 = c*CHK;
    int tid = threadIdx.x;
    int lr = tid >> 4;
    int lc = (tid & 15) * 4;

    for (int r = lr; r < 64; r += 16){
        size_t gi = ((size_t)(b*TT + t0 + r))*DM + h*DH + lc;
        float4 q = *(const float4*)(Qf+gi);
        float4 k = *(const float4*)(Kf+gi);
        float4 v = *(const float4*)(Vf+gi);
        Qt[(lc+0)*STR+r]=q.x; Qt[(lc+1)*STR+r]=q.y; Qt[(lc+2)*STR+r]=q.z; Qt[(lc+3)*STR+r]=q.w;
        Kt[(lc+0)*STR+r]=k.x; Kt[(lc+1)*STR+r]=k.y; Kt[(lc+2)*STR+r]=k.z; Kt[(lc+3)*STR+r]=k.w;
        *(float4*)&Vs[r*STR+lc] = v;
    }
    {
        size_t base = (size_t)blk*(DH*DH);
        for (int e = tid*4; e < DH*DH; e += 1024){
            float4 sv = *(const float4*)(Sp + base + e);
            int d = e >> 6, m = e & 63;
            *(float4*)&Ss[d*STR+m] = sv;
        }
    }
    if (tid < DH) zs[tid] = zp[(size_t)blk*DH + tid];
    __syncthreads();

    int ti = (tid>>4)*4;
    int tj = (tid&15)*4;

    float a[4][4];
#pragma unroll
    for (int i=0;i<4;i++)
#pragma unroll
        for (int j=0;j<4;j++) a[i][j]=0.f;
    for (int d=0; d<64; d++){
        float4 qv = *(const float4*)&Qt[d*STR+ti];
        float4 kv = *(const float4*)&Kt[d*STR+tj];
        float qq[4]={qv.x,qv.y,qv.z,qv.w}, kk[4]={kv.x,kv.y,kv.z,kv.w};
#pragma unroll
        for (int i=0;i<4;i++)
#pragma unroll
            for (int j=0;j<4;j++) a[i][j] += qq[i]*kk[j];
    }
#pragma unroll
    for (int i=0;i<4;i++)
#pragma unroll
        for (int j=0;j<4;j++)
            At[(tj+j)*STR + (ti+i)] = ((tj+j) <= (ti+i)) ? a[i][j] : 0.f;
    __syncthreads();

    if (tid < 64){
        int t = tid;
        float dsum = 0.f;
        for (int j=0;j<64;j++) dsum += At[j*STR + t];
        for (int d=0;d<64;d++) dsum += Qt[d*STR + t]*zs[d];
        dn[t] = fmaxf(dsum, 1e-6f);
    }
    __syncthreads();

    float nacc[4][4];
#pragma unroll
    for (int i=0;i<4;i++)
#pragma unroll
        for (int j=0;j<4;j++) nacc[i][j]=0.f;
    for (int j=0;j<64;j++){
        float4 av = *(const float4*)&At[j*STR+ti];
        float4 vv = *(const float4*)&Vs[j*STR+tj];
        float af[4]={av.x,av.y,av.z,av.w}, vf[4]={vv.x,vv.y,vv.z,vv.w};
#pragma unroll
        for (int i=0;i<4;i++)
#pragma unroll
            for (int m=0;m<4;m++) nacc[i][m] += af[i]*vf[m];
    }
    for (int d=0;d<64;d++){
        float4 qv = *(const float4*)&Qt[d*STR+ti];
        float4 sv = *(const float4*)&Ss[d*STR+tj];
        float qq[4]={qv.x,qv.y,qv.z,qv.w}, sf[4]={sv.x,sv.y,sv.z,sv.w};
#pragma unroll
        for (int i=0;i<4;i++)
#pragma unroll
            for (int m=0;m<4;m++) nacc[i][m] += qq[i]*sf[m];
    }
#pragma unroll
    for (int i=0;i<4;i++){
        float inv = 1.0f / dn[ti+i];
        size_t gm = (size_t)(b*TT + t0 + ti + i);
        __nv_bfloat16* p = attn3 + gm*K3DM + h*DH + tj;
        uint32_t hw[2], lw[2];
#pragma unroll
        for (int q=0;q<2;q++){
            float a0 = nacc[i][2*q]*inv, a1 = nacc[i][2*q+1]*inv;
            __nv_bfloat16 h0,l0,h1,l1;
            bsplit(a0,h0,l0); bsplit(a1,h1,l1);
            hw[q] = ((uint32_t)__bfloat16_as_ushort(h1)<<16) | __bfloat16_as_ushort(h0);
            lw[q] = ((uint32_t)__bfloat16_as_ushort(l1)<<16) | __bfloat16_as_ushort(l0);
        }
        *(uint2*)(p)        = make_uint2(hw[0],hw[1]);
        *(uint2*)(p+DM)     = make_uint2(lw[0],lw[1]);
        *(uint2*)(p+2*DM)   = make_uint2(hw[0],hw[1]);
    }
}

// ---------------- launch ----------------
#define SMEM_INTRA ((5*64*STR + 128) * sizeof(float))

extern "C" void kernel_launch(void* const* d_in, const int* in_sizes, int n_in,
                              void* d_out, int out_size)
{
    (void)in_sizes; (void)n_in; (void)out_size;
    const float* x     = (const float*)d_in[0];
    const float* ln1_g = (const float*)d_in[1];
    const float* ln1_b = (const float*)d_in[2];
    const float* Wq    = (const float*)d_in[3];
    const float* bq    = (const float*)d_in[4];
    const float* Wk    = (const float*)d_in[5];
    const float* bk    = (const float*)d_in[6];
    const float* Wv    = (const float*)d_in[7];
    const float* bv    = (const float*)d_in[8];
    const float* Wo    = (const float*)d_in[9];
    const float* bo    = (const float*)d_in[10];
    const float* ln2_g = (const float*)d_in[11];
    const float* ln2_b = (const float*)d_in[12];
    const float* W1    = (const float*)d_in[13];
    const float* b1    = (const float*)d_in[14];
    const float* W2    = (const float*)d_in[15];
    const float* b2    = (const float*)d_in[16];
    float* out = (float*)d_out;

    static bool attr_done = false;
    if (!attr_done){
        cudaFuncSetAttribute(intra_kernel, cudaFuncAttributeMaxDynamicSharedMemorySize,
                             (int)SMEM_INTRA);
        cudaFuncSetAttribute(mm_kernel<128,3>, cudaFuncAttributeMaxDynamicSharedMemorySize,
                             SMEM_MM);
        cudaFuncSetAttribute(mm_kernel<64,4>, cudaFuncAttributeMaxDynamicSharedMemorySize,
                             SMEM_MM);
        attr_done = true;
    }

    __nv_bfloat16 *h3b,*attn3b,*h23b,*ffn3b,*wqkv3,*wo3,*w13,*w23;
    float *qb,*kb,*vb,*x2b,*ckvb,*czb,*Spb,*zpb;
    cudaGetSymbolAddress((void**)&h3b,   g_h3);
    cudaGetSymbolAddress((void**)&qb,    g_q);
    cudaGetSymbolAddress((void**)&kb,    g_k);
    cudaGetSymbolAddress((void**)&vb,    g_v);
    cudaGetSymbolAddress((void**)&attn3b,g_attn3);
    cudaGetSymbolAddress((void**)&x2b,   g_x2);
    cudaGetSymbolAddress((void**)&h23b,  g_h23);
    cudaGetSymbolAddress((void**)&ffn3b, g_ffn3);
    cudaGetSymbolAddress((void**)&wqkv3, g_wqkv3);
    cudaGetSymbolAddress((void**)&wo3,   g_wo3);
    cudaGetSymbolAddress((void**)&w13,   g_w13);
    cudaGetSymbolAddress((void**)&w23,   g_w23);
    cudaGetSymbolAddress((void**)&ckvb,  g_ckv);
    cudaGetSymbolAddress((void**)&czb,   g_cz);
    cudaGetSymbolAddress((void**)&Spb,   g_Sp);
    cudaGetSymbolAddress((void**)&zpb,   g_zp);

    dim3 wcb(32,8);
    wconv_all_kernel<<<1536, wcb>>>(Wq, Wk, Wv, Wo, W1, W2,
                                    wqkv3, wo3, w13, w23);

    dim3 gQKV(3*DM/TN, MM/128);     // (12, 32) TM=128
    dim3 gFF(DFF/TN, MM/128);       // (16, 32) TM=128
    dim3 gDM64(DM/TN, MM/64);       // (4, 64)  TM=64  -> 256 CTAs

    // sublayer 1
    ln3_kernel<<<MM, 256>>>(x, ln1_g, ln1_b, h3b);
    mm_kernel<128,3><<<gQKV, 256, SMEM_MM>>>(h3b, wqkv3, bq, bk, bv, nullptr,
                                             qb, kb, vb, nullptr, DM, K3DM, 4);
    chunk_sums_kernel<<<BH*NC, 256>>>(kb, vb, ckvb, czb);
    scan_kernel<<<BH*16, 256>>>(ckvb, czb, Spb, zpb);
    intra_kernel<<<BH*NC, 256, SMEM_INTRA>>>(qb, kb, vb, Spb, zpb, attn3b);
    mm_kernel<64,4><<<gDM64, 256, SMEM_MM>>>(attn3b, wo3, bo, nullptr, nullptr, x,
                                             x2b, nullptr, nullptr, nullptr, DM, K3DM, 2);

    // sublayer 2
    ln3_kernel<<<MM, 256>>>(x2b, ln2_g, ln2_b, h23b);
    mm_kernel<128,3><<<gFF, 256, SMEM_MM>>>(h23b, w13, b1, nullptr, nullptr, nullptr,
                                            nullptr, nullptr, nullptr, ffn3b, DFF, K3DM, 3);
    mm_kernel<64,4><<<gDM64, 256, SMEM_MM>>>(ffn3b, w23, b2, nullptr, nullptr, x2b,
                                             out, nullptr, nullptr, nullptr, DM, K3FF, 2);
}

// round 8
// speedup vs baseline: 1.0799x; 1.0799x over previous
#include <cuda_runtime.h>
#include <cuda_bf16.h>
#include <math.h>
#include <stdint.h>

// ---------------- problem constants ----------------
#define BB   2
#define TT   2048
#define DM   512
#define NH   8
#define DH   64
#define DFF  2048
#define MM   (BB*TT)        // 4096 rows
#define CHK  64
#define NC   (TT/CHK)       // 32
#define BH   (BB*NH)        // 16
#define STR  68
#define K3DM (3*DM)         // 1536
#define K3FF (3*DFF)        // 6144

// ---------------- scratch (device globals) ----------------
__device__ __align__(256) __nv_bfloat16 g_h3   [MM*K3DM];
__device__ __align__(256) float          g_q    [MM*DM];
__device__ __align__(256) float          g_k    [MM*DM];
__device__ __align__(256) float          g_v    [MM*DM];
__device__ __align__(256) __nv_bfloat16 g_attn3[MM*K3DM];
__device__ __align__(256) float          g_x2   [MM*DM];
__device__ __align__(256) __nv_bfloat16 g_h23  [MM*K3DM];
__device__ __align__(256) __nv_bfloat16 g_ffn3 [MM*K3FF];
__device__ __align__(256) float          g_part [2*MM*DM];     // split-K partials
__device__ __align__(256) __nv_bfloat16 g_wqkv3[3*DM*K3DM];   // rows: [Wq|Wk|Wv]
__device__ __align__(256) __nv_bfloat16 g_wo3  [DM*K3DM];
__device__ __align__(256) __nv_bfloat16 g_w13  [DFF*K3DM];
__device__ __align__(256) __nv_bfloat16 g_w23  [DM*K3FF];
__device__ __align__(256) float g_ckv[BH*NC*DH*DH];
__device__ __align__(256) float g_cz [BH*NC*DH];
__device__ __align__(256) float g_Sp [BH*NC*DH*DH];
__device__ __align__(256) float g_zp [BH*NC*DH];

// ---------------- helpers ----------------
__device__ __forceinline__ uint32_t smem_u32(const void* p){
    uint32_t a;
    asm("{ .reg .u64 t; cvta.to.shared.u64 t, %1; cvt.u32.u64 %0, t; }"
        : "=r"(a) : "l"(p));
    return a;
}
__device__ __forceinline__ void cp16(uint32_t dst, const void* src){
    asm volatile("cp.async.cg.shared.global [%0], [%1], 16;" :: "r"(dst), "l"(src));
}
__device__ __forceinline__ void cp_commit(){
    asm volatile("cp.async.commit_group;");
}
template<int N> __device__ __forceinline__ void cp_wait(){
    asm volatile("cp.async.wait_group %0;" :: "n"(N));
}
__device__ __forceinline__ void bsplit(float v, __nv_bfloat16& h, __nv_bfloat16& l){
    h = __float2bfloat16(v);
    l = __float2bfloat16(v - __bfloat162float(h));
}
__device__ __forceinline__ void mma_bf16(float* d, const uint32_t* a, const uint32_t* b){
    asm volatile(
        "mma.sync.aligned.m16n8k16.row.col.f32.bf16.bf16.f32 "
        "{%0,%1,%2,%3}, {%4,%5,%6,%7}, {%8,%9}, {%0,%1,%2,%3};"
        : "+f"(d[0]), "+f"(d[1]), "+f"(d[2]), "+f"(d[3])
        : "r"(a[0]), "r"(a[1]), "r"(a[2]), "r"(a[3]), "r"(b[0]), "r"(b[1]));
}
__device__ __forceinline__ void ldsm4(uint32_t& r0, uint32_t& r1, uint32_t& r2,
                                      uint32_t& r3, uint32_t addr){
    asm volatile("ldmatrix.sync.aligned.m8n8.x4.shared.b16 {%0,%1,%2,%3}, [%4];"
                 : "=r"(r0), "=r"(r1), "=r"(r2), "=r"(r3) : "r"(addr));
}

// ---------------- layernorm -> triple-bf16 (A-side [hi,lo,hi]) ----------------
__global__ __launch_bounds__(256) void ln3_kernel(
    const float* __restrict__ x, const float* __restrict__ g,
    const float* __restrict__ b, __nv_bfloat16* __restrict__ o3)
{
    int row = blockIdx.x;
    const float* xr = x + (size_t)row*DM;
    int tid = threadIdx.x;
    float v0 = xr[tid], v1 = xr[tid+256];
    float s = v0+v1, s2 = v0*v0+v1*v1;
#pragma unroll
    for (int off=16; off; off>>=1){
        s  += __shfl_xor_sync(0xffffffffu, s,  off);
        s2 += __shfl_xor_sync(0xffffffffu, s2, off);
    }
    __shared__ float rs[8], rs2[8], mu_s, rstd_s;
    if ((tid&31)==0){ rs[tid>>5]=s; rs2[tid>>5]=s2; }
    __syncthreads();
    if (tid==0){
        float a=0.f,c=0.f;
#pragma unroll
        for (int i=0;i<8;i++){ a+=rs[i]; c+=rs2[i]; }
        float mu = a*(1.0f/DM);
        float var = c*(1.0f/DM) - mu*mu;
        mu_s = mu; rstd_s = rsqrtf(var + 1e-5f);
    }
    __syncthreads();
    float mu = mu_s, rstd = rstd_s;
    __nv_bfloat16* orow = o3 + (size_t)row*K3DM;
    {
        float y = (v0-mu)*rstd*g[tid] + b[tid];
        __nv_bfloat16 h,l; bsplit(y,h,l);
        orow[tid] = h; orow[tid+DM] = l; orow[tid+2*DM] = h;
    }
    {
        int c1 = tid+256;
        float y = (v1-mu)*rstd*g[c1] + b[c1];
        __nv_bfloat16 h,l; bsplit(y,h,l);
        orow[c1] = h; orow[c1+DM] = l; orow[c1+2*DM] = h;
    }
}

// -------- fused weight transpose+split: all 6 weights in ONE launch ----------
__global__ __launch_bounds__(256) void wconv_all_kernel(
    const float* __restrict__ Wq, const float* __restrict__ Wk,
    const float* __restrict__ Wv, const float* __restrict__ Wo,
    const float* __restrict__ W1, const float* __restrict__ W2,
    __nv_bfloat16* __restrict__ wqkv3, __nv_bfloat16* __restrict__ wo3,
    __nv_bfloat16* __restrict__ w13,   __nv_bfloat16* __restrict__ w23)
{
    int bid = blockIdx.x;
    const float* W; __nv_bfloat16* B3;
    int Kd, Nd, nx, local;
    if (bid < 512){
        int seg = bid >> 7; local = bid & 127; nx = 16; Kd = 512; Nd = 512;
        W  = (seg==0)?Wq:(seg==1)?Wk:(seg==2)?Wv:Wo;
        B3 = (seg==0)?wqkv3:(seg==1)?(wqkv3+512*K3DM):(seg==2)?(wqkv3+1024*K3DM):wo3;
    } else if (bid < 1024){
        local = bid - 512; nx = 64; Kd = 512; Nd = 2048; W = W1; B3 = w13;
    } else {
        local = bid - 1024; nx = 16; Kd = 2048; Nd = 512; W = W2; B3 = w23;
    }
    int n0 = (local % nx)*32, k0 = (local / nx)*64;

    __shared__ float t[64][33];
    int tx = threadIdx.x, ty = threadIdx.y;
#pragma unroll
    for (int i=ty;i<64;i+=8)
        t[i][tx] = W[(size_t)(k0+i)*Nd + n0 + tx];
    __syncthreads();
#pragma unroll
    for (int i=ty;i<32;i+=8){
        float va = t[2*tx][i], vb = t[2*tx+1][i];
        __nv_bfloat16 ha,la,hb,lb;
        bsplit(va,ha,la); bsplit(vb,hb,lb);
        uint32_t hw = ((uint32_t)__bfloat16_as_ushort(hb)<<16) | __bfloat16_as_ushort(ha);
        uint32_t lw = ((uint32_t)__bfloat16_as_ushort(lb)<<16) | __bfloat16_as_ushort(la);
        size_t base = (size_t)(n0+i)*(3*Kd) + k0 + 2*tx;
        *(uint32_t*)&B3[base]        = hw;
        *(uint32_t*)&B3[base+Kd]     = hw;
        *(uint32_t*)&B3[base+2*Kd]   = lw;
    }
}

// ---------------- mma.sync bf16 GEMM, 3-stage pipeline, 2 CTAs/SM ----------------
// tile 128x128, 8 warps (warp tile 32x64), K-chunk 64. gridDim.z = split-K factor.
// modes: 2 +bias0+res -> C0; 3 relu(+bias0) -> triple bf16 C3;
//        4 qkv split: n<512 -> C0(elu+1,bias0), <1024 -> C1(elu+1,bias1), else C2(bias2)
//        5 raw partial fp32 -> C0 + kz*MM*Np  (split-K; combine kernel finishes)
#define TM 128
#define TN 128
#define RS 72                       // padded smem row (elements)
#define ABY (TM*RS*2)               // 18432 (one operand, one stage)
#define STGB (2*ABY)                // 36864 per stage (A+B)
#define NSTG 3
#define SMEM_MM (NSTG*STGB)         // 110592 -> two CTAs fit per SM

__global__ __launch_bounds__(256, 2) void mm_kernel(
    const __nv_bfloat16* __restrict__ Ap, const __nv_bfloat16* __restrict__ Bp,
    const float* __restrict__ bias0, const float* __restrict__ bias1,
    const float* __restrict__ bias2, const float* __restrict__ res,
    float* __restrict__ C0, float* __restrict__ C1, float* __restrict__ C2,
    __nv_bfloat16* __restrict__ C3,
    int Np, int Kp, int mode)
{
    extern __shared__ char smc[];
    uint32_t sb = smem_u32(smc);

    int tid = threadIdx.x;
    int lane = tid & 31, wid = tid >> 5;
    int wm = wid >> 1, wn = wid & 1;
    int g = lane >> 2, qp = lane & 3;
    int bm = blockIdx.y * TM;
    int bn = blockIdx.x * TN;
    int kz = blockIdx.z;
    int Keff = Kp / (int)gridDim.z;        // K-range per z-slice

    const char* Abase = (const char*)(Ap + (size_t)bm*Kp + (size_t)kz*Keff);
    const char* Bbase = (const char*)(Bp + (size_t)bn*Kp + (size_t)kz*Keff);
    const size_t rowb = (size_t)Kp*2;

    int lr_ = tid >> 3, lc_ = (tid & 7)*16;
    auto loadStage = [&](int c, int s){
        uint32_t da = sb + (uint32_t)s*STGB;
        uint32_t db = da + ABY;
        const char* sa = Abase + (size_t)c*128 + (size_t)lr_*rowb + lc_;
        const char* sbp= Bbase + (size_t)c*128 + (size_t)lr_*rowb + lc_;
        uint32_t so = (uint32_t)(lr_*(RS*2) + lc_);
#pragma unroll
        for (int t=0;t<4;t++){
            cp16(da + so + t*32*(RS*2), sa + (size_t)t*32*rowb);
            cp16(db + so + t*32*(RS*2), sbp + (size_t)t*32*rowb);
        }
        cp_commit();
    };

    // per-lane ldmatrix base offsets (within a stage)
    uint32_t a_off[2], b_off[4];
#pragma unroll
    for (int mf=0; mf<2; mf++){
        int arow = wm*32 + mf*16 + (lane & 15);
        a_off[mf] = (uint32_t)(arow*(RS*2) + ((lane & 16) ? 16 : 0));
    }
#pragma unroll
    for (int p=0; p<4; p++){
        int nrow = wn*64 + p*16 + (lane & 7) + ((lane & 16) >> 1);
        b_off[p] = (uint32_t)(nrow*(RS*2) + ((lane & 8) ? 16 : 0)) + ABY;
    }

    float acc[2][8][4];
#pragma unroll
    for (int i=0;i<2;i++)
#pragma unroll
        for (int j=0;j<8;j++)
#pragma unroll
            for (int k=0;k<4;k++) acc[i][j][k]=0.f;

    const int nch = Keff >> 6;
    loadStage(0,0); loadStage(1,1);

    int cur = 0, nxt = 2;
    for (int i=0;i<nch;i++){
        cp_wait<NSTG-2>();
        __syncthreads();
        if (i+2 < nch) loadStage(i+2, nxt);
        else cp_commit();   // keep outstanding-group count invariant
        uint32_t S = sb + (uint32_t)cur*STGB;
#pragma unroll
        for (int ks=0; ks<4; ks++){
            uint32_t koff = (uint32_t)(ks*32);
            uint32_t a[2][4];
            ldsm4(a[0][0],a[0][1],a[0][2],a[0][3], S + a_off[0] + koff);
            ldsm4(a[1][0],a[1][1],a[1][2],a[1][3], S + a_off[1] + koff);
            uint32_t b[8][2];
#pragma unroll
            for (int p=0; p<4; p++)
                ldsm4(b[2*p][0],b[2*p][1],b[2*p+1][0],b[2*p+1][1],
                      S + b_off[p] + koff);
#pragma unroll
            for (int mf=0; mf<2; mf++)
#pragma unroll
                for (int nf=0; nf<8; nf++)
                    mma_bf16(acc[mf][nf], a[mf], b[nf]);
        }
        cur = (cur==NSTG-1) ? 0 : cur+1;
        nxt = (nxt==NSTG-1) ? 0 : nxt+1;
    }

    // ---- epilogue ----
    float* Cpart = C0 + (size_t)kz*MM*Np;   // mode 5 target
#pragma unroll
    for (int mf=0; mf<2; mf++){
#pragma unroll
        for (int half=0; half<2; half++){
            int m = bm + wm*32 + mf*16 + g + half*8;
#pragma unroll
            for (int nf=0; nf<8; nf++){
                int n = bn + wn*64 + nf*8 + qp*2;
                float v0 = acc[mf][nf][half*2+0];
                float v1 = acc[mf][nf][half*2+1];
                if (mode==5){
                    *(float2*)&Cpart[(size_t)m*Np + n] = make_float2(v0, v1);
                } else if (mode==4){
                    int sel = n >> 9;           // 0:q 1:k 2:v
                    int col = n & 511;
                    const float* bs = (sel==0) ? bias0 : (sel==1) ? bias1 : bias2;
                    v0 += bs[col]; v1 += bs[col+1];
                    if (sel < 2){
                        v0 = (v0 > 0.f) ? (v0+1.f) : expf(v0);
                        v1 = (v1 > 0.f) ? (v1+1.f) : expf(v1);
                    }
                    float* Cs = (sel==0) ? C0 : (sel==1) ? C1 : C2;
                    *(float2*)&Cs[(size_t)m*512 + col] = make_float2(v0, v1);
                } else {
                    v0 += bias0[n]; v1 += bias0[n+1];
                    if (mode==3){
                        v0 = fmaxf(v0, 0.f); v1 = fmaxf(v1, 0.f);
                        __nv_bfloat16 h0,l0,h1,l1;
                        bsplit(v0,h0,l0); bsplit(v1,h1,l1);
                        uint32_t hw = ((uint32_t)__bfloat16_as_ushort(h1)<<16) | __bfloat16_as_ushort(h0);
                        uint32_t lw = ((uint32_t)__bfloat16_as_ushort(l1)<<16) | __bfloat16_as_ushort(l0);
                        __nv_bfloat16* p0 = C3 + (size_t)m*3*Np + n;
                        *(uint32_t*)(p0)        = hw;
                        *(uint32_t*)(p0 + Np)   = lw;
                        *(uint32_t*)(p0 + 2*Np) = hw;
                    } else {
                        if (mode==2){
                            float2 rr = *(const float2*)&res[(size_t)m*Np + n];
                            v0 += rr.x; v1 += rr.y;
                        }
                        *(float2*)&C0[(size_t)m*Np + n] = make_float2(v0, v1);
                    }
                }
            }
        }
    }
}

// ------- split-K combine: out = p0 + p1 + bias + res  (N fixed at DM=512) -------
__global__ __launch_bounds__(256) void combine_kernel(
    const float* __restrict__ part, const float* __restrict__ bias,
    const float* __restrict__ res, float* __restrict__ outp)
{
    int idx = (blockIdx.x*256 + threadIdx.x)*4;     // over MM*DM
    int n = idx & (DM-1);
    float4 p0 = *(const float4*)&part[idx];
    float4 p1 = *(const float4*)&part[MM*DM + idx];
    float4 bv = *(const float4*)&bias[n];
    float4 rv = *(const float4*)&res[idx];
    float4 o;
    o.x = p0.x+p1.x+bv.x+rv.x;
    o.y = p0.y+p1.y+bv.y+rv.y;
    o.z = p0.z+p1.z+bv.z+rv.z;
    o.w = p0.w+p1.w+bv.w+rv.w;
    *(float4*)&outp[idx] = o;
}

// ---------------- per-chunk K^T V and K sums ----------------
__global__ __launch_bounds__(256) void chunk_sums_kernel(
    const float* __restrict__ Kf, const float* __restrict__ Vf,
    float* __restrict__ ckv, float* __restrict__ cz)
{
    __shared__ float Ks[CHK*DH];
    __shared__ float Vs[CHK*DH];
    int blk = blockIdx.x;
    int c = blk % NC, bh = blk / NC;
    int b = bh / NH, h = bh % NH;
    int t0 = c*CHK;
    int tid = threadIdx.x;
    int lr = tid >> 4;
    int lc = (tid & 15) * 4;
    for (int r = lr; r < CHK; r += 16){
        size_t gi = ((size_t)(b*TT + t0 + r))*DM + h*DH + lc;
        *(float4*)&Ks[r*DH+lc] = *(const float4*)(Kf+gi);
        *(float4*)&Vs[r*DH+lc] = *(const float4*)(Vf+gi);
    }
    __syncthreads();
    int ti = (tid>>4)*4, tj = (tid&15)*4;
    float acc[4][4];
#pragma unroll
    for (int i=0;i<4;i++)
#pragma unroll
        for (int j=0;j<4;j++) acc[i][j]=0.f;
    for (int t=0;t<CHK;t++){
        float4 kv = *(const float4*)&Ks[t*DH+ti];
        float4 vv = *(const float4*)&Vs[t*DH+tj];
        float kk[4]={kv.x,kv.y,kv.z,kv.w}, vf[4]={vv.x,vv.y,vv.z,vv.w};
#pragma unroll
        for (int i=0;i<4;i++)
#pragma unroll
            for (int j=0;j<4;j++) acc[i][j] += kk[i]*vf[j];
    }
    float* outp = ckv + (size_t)blk*DH*DH;
#pragma unroll
    for (int i=0;i<4;i++)
        *(float4*)&outp[(ti+i)*DH + tj] =
            make_float4(acc[i][0],acc[i][1],acc[i][2],acc[i][3]);
    if (tid < DH){
        float zsum = 0.f;
        for (int t=0;t<CHK;t++) zsum += Ks[t*DH+tid];
        cz[(size_t)blk*DH + tid] = zsum;
    }
}

// --------- parallel exclusive scan over chunk states: 1 elem / thread ---------
__global__ __launch_bounds__(256) void scan_kernel(
    const float* __restrict__ ckv, const float* __restrict__ cz,
    float* __restrict__ Sp, float* __restrict__ zp)
{
    int bh = blockIdx.x >> 4;
    int e  = ((blockIdx.x & 15) << 8) + threadIdx.x;   // 0..4095
    size_t base = ((size_t)bh*NC)*(DH*DH) + e;
    float v[NC];
#pragma unroll
    for (int c=0;c<NC;c++) v[c] = ckv[base + (size_t)c*(DH*DH)];
    float s = 0.f;
#pragma unroll
    for (int c=0;c<NC;c++){ Sp[base + (size_t)c*(DH*DH)] = s; s += v[c]; }

    if ((blockIdx.x & 15)==0 && threadIdx.x < DH){
        size_t zb = (size_t)bh*NC*DH + threadIdx.x;
        float zv[NC];
#pragma unroll
        for (int c=0;c<NC;c++) zv[c] = cz[zb + (size_t)c*DH];
        float z = 0.f;
#pragma unroll
        for (int c=0;c<NC;c++){ zp[zb + (size_t)c*DH] = z; z += zv[c]; }
    }
}

// ---------------- intra-chunk attention -> triple bf16 output ----------------
__global__ __launch_bounds__(256) void intra_kernel(
    const float* __restrict__ Qf, const float* __restrict__ Kf,
    const float* __restrict__ Vf, const float* __restrict__ Sp,
    const float* __restrict__ zp, __nv_bfloat16* __restrict__ attn3)
{
    extern __shared__ float smf[];
    float* Qt = smf;
    float* Kt = Qt + 64*STR;
    float* Vs = Kt + 64*STR;
    float* Ss = Vs + 64*STR;
    float* At = Ss + 64*STR;
    float* zs = At + 64*STR;
    float* dn = zs + 64;

    int blk = blockIdx.x;
    int c = blk % NC, bh = blk / NC;
    int b = bh / NH, h = bh % NH;
    int t0 = c*CHK;
    int tid = threadIdx.x;
    int lr = tid >> 4;
    int lc = (tid & 15) * 4;

    for (int r = lr; r < 64; r += 16){
        size_t gi = ((size_t)(b*TT + t0 + r))*DM + h*DH + lc;
        float4 q = *(const float4*)(Qf+gi);
        float4 k = *(const float4*)(Kf+gi);
        float4 v = *(const float4*)(Vf+gi);
        Qt[(lc+0)*STR+r]=q.x; Qt[(lc+1)*STR+r]=q.y; Qt[(lc+2)*STR+r]=q.z; Qt[(lc+3)*STR+r]=q.w;
        Kt[(lc+0)*STR+r]=k.x; Kt[(lc+1)*STR+r]=k.y; Kt[(lc+2)*STR+r]=k.z; Kt[(lc+3)*STR+r]=k.w;
        *(float4*)&Vs[r*STR+lc] = v;
    }
    {
        size_t base = (size_t)blk*(DH*DH);
        for (int e = tid*4; e < DH*DH; e += 1024){
            float4 sv = *(const float4*)(Sp + base + e);
            int d = e >> 6, m = e & 63;
            *(float4*)&Ss[d*STR+m] = sv;
        }
    }
    if (tid < DH) zs[tid] = zp[(size_t)blk*DH + tid];
    __syncthreads();

    int ti = (tid>>4)*4;
    int tj = (tid&15)*4;

    float a[4][4];
#pragma unroll
    for (int i=0;i<4;i++)
#pragma unroll
        for (int j=0;j<4;j++) a[i][j]=0.f;
    for (int d=0; d<64; d++){
        float4 qv = *(const float4*)&Qt[d*STR+ti];
        float4 kv = *(const float4*)&Kt[d*STR+tj];
        float qq[4]={qv.x,qv.y,qv.z,qv.w}, kk[4]={kv.x,kv.y,kv.z,kv.w};
#pragma unroll
        for (int i=0;i<4;i++)
#pragma unroll
            for (int j=0;j<4;j++) a[i][j] += qq[i]*kk[j];
    }
#pragma unroll
    for (int i=0;i<4;i++)
#pragma unroll
        for (int j=0;j<4;j++)
            At[(tj+j)*STR + (ti+i)] = ((tj+j) <= (ti+i)) ? a[i][j] : 0.f;
    __syncthreads();

    if (tid < 64){
        int t = tid;
        float dsum = 0.f;
        for (int j=0;j<64;j++) dsum += At[j*STR + t];
        for (int d=0;d<64;d++) dsum += Qt[d*STR + t]*zs[d];
        dn[t] = fmaxf(dsum, 1e-6f);
    }
    __syncthreads();

    float nacc[4][4];
#pragma unroll
    for (int i=0;i<4;i++)
#pragma unroll
        for (int j=0;j<4;j++) nacc[i][j]=0.f;
    for (int j=0;j<64;j++){
        float4 av = *(const float4*)&At[j*STR+ti];
        float4 vv = *(const float4*)&Vs[j*STR+tj];
        float af[4]={av.x,av.y,av.z,av.w}, vf[4]={vv.x,vv.y,vv.z,vv.w};
#pragma unroll
        for (int i=0;i<4;i++)
#pragma unroll
            for (int m=0;m<4;m++) nacc[i][m] += af[i]*vf[m];
    }
    for (int d=0;d<64;d++){
        float4 qv = *(const float4*)&Qt[d*STR+ti];
        float4 sv = *(const float4*)&Ss[d*STR+tj];
        float qq[4]={qv.x,qv.y,qv.z,qv.w}, sf[4]={sv.x,sv.y,sv.z,sv.w};
#pragma unroll
        for (int i=0;i<4;i++)
#pragma unroll
            for (int m=0;m<4;m++) nacc[i][m] += qq[i]*sf[m];
    }
#pragma unroll
    for (int i=0;i<4;i++){
        float inv = 1.0f / dn[ti+i];
        size_t gm = (size_t)(b*TT + t0 + ti + i);
        __nv_bfloat16* p = attn3 + gm*K3DM + h*DH + tj;
        uint32_t hw[2], lw[2];
#pragma unroll
        for (int q=0;q<2;q++){
            float a0 = nacc[i][2*q]*inv, a1 = nacc[i][2*q+1]*inv;
            __nv_bfloat16 h0,l0,h1,l1;
            bsplit(a0,h0,l0); bsplit(a1,h1,l1);
            hw[q] = ((uint32_t)__bfloat16_as_ushort(h1)<<16) | __bfloat16_as_ushort(h0);
            lw[q] = ((uint32_t)__bfloat16_as_ushort(l1)<<16) | __bfloat16_as_ushort(l0);
        }
        *(uint2*)(p)        = make_uint2(hw[0],hw[1]);
        *(uint2*)(p+DM)     = make_uint2(lw[0],lw[1]);
        *(uint2*)(p+2*DM)   = make_uint2(hw[0],hw[1]);
    }
}

// ---------------- launch ----------------
#define SMEM_INTRA ((5*64*STR + 128) * sizeof(float))

extern "C" void kernel_launch(void* const* d_in, const int* in_sizes, int n_in,
                              void* d_out, int out_size)
{
    (void)in_sizes; (void)n_in; (void)out_size;
    const float* x     = (const float*)d_in[0];
    const float* ln1_g = (const float*)d_in[1];
    const float* ln1_b = (const float*)d_in[2];
    const float* Wq    = (const float*)d_in[3];
    const float* bq    = (const float*)d_in[4];
    const float* Wk    = (const float*)d_in[5];
    const float* bk    = (const float*)d_in[6];
    const float* Wv    = (const float*)d_in[7];
    const float* bv    = (const float*)d_in[8];
    const float* Wo    = (const float*)d_in[9];
    const float* bo    = (const float*)d_in[10];
    const float* ln2_g = (const float*)d_in[11];
    const float* ln2_b = (const float*)d_in[12];
    const float* W1    = (const float*)d_in[13];
    const float* b1    = (const float*)d_in[14];
    const float* W2    = (const float*)d_in[15];
    const float* b2    = (const float*)d_in[16];
    float* out = (float*)d_out;

    static bool attr_done = false;
    if (!attr_done){
        cudaFuncSetAttribute(intra_kernel, cudaFuncAttributeMaxDynamicSharedMemorySize,
                             (int)SMEM_INTRA);
        cudaFuncSetAttribute(mm_kernel, cudaFuncAttributeMaxDynamicSharedMemorySize,
                             SMEM_MM);
        attr_done = true;
    }

    __nv_bfloat16 *h3b,*attn3b,*h23b,*ffn3b,*wqkv3,*wo3,*w13,*w23;
    float *qb,*kb,*vb,*x2b,*partb,*ckvb,*czb,*Spb,*zpb;
    cudaGetSymbolAddress((void**)&h3b,   g_h3);
    cudaGetSymbolAddress((void**)&qb,    g_q);
    cudaGetSymbolAddress((void**)&kb,    g_k);
    cudaGetSymbolAddress((void**)&vb,    g_v);
    cudaGetSymbolAddress((void**)&attn3b,g_attn3);
    cudaGetSymbolAddress((void**)&x2b,   g_x2);
    cudaGetSymbolAddress((void**)&h23b,  g_h23);
    cudaGetSymbolAddress((void**)&ffn3b, g_ffn3);
    cudaGetSymbolAddress((void**)&partb, g_part);
    cudaGetSymbolAddress((void**)&wqkv3, g_wqkv3);
    cudaGetSymbolAddress((void**)&wo3,   g_wo3);
    cudaGetSymbolAddress((void**)&w13,   g_w13);
    cudaGetSymbolAddress((void**)&w23,   g_w23);
    cudaGetSymbolAddress((void**)&ckvb,  g_ckv);
    cudaGetSymbolAddress((void**)&czb,   g_cz);
    cudaGetSymbolAddress((void**)&Spb,   g_Sp);
    cudaGetSymbolAddress((void**)&zpb,   g_zp);

    dim3 wcb(32,8);
    wconv_all_kernel<<<1536, wcb>>>(Wq, Wk, Wv, Wo, W1, W2,
                                    wqkv3, wo3, w13, w23);

    dim3 gQKV(3*DM/TN, MM/TM);      // (12, 32)
    dim3 gFF(DFF/TN, MM/TM);        // (16, 32)
    dim3 gDMz(DM/TN, MM/TM, 2);     // (4, 32, 2) split-K=2 -> 256 CTAs
    const int CMB = (MM*DM/4)/256;  // 2048 blocks

    // sublayer 1
    ln3_kernel<<<MM, 256>>>(x, ln1_g, ln1_b, h3b);
    mm_kernel<<<gQKV, 256, SMEM_MM>>>(h3b, wqkv3, bq, bk, bv, nullptr,
                                      qb, kb, vb, nullptr, DM, K3DM, 4);
    chunk_sums_kernel<<<BH*NC, 256>>>(kb, vb, ckvb, czb);
    scan_kernel<<<BH*16, 256>>>(ckvb, czb, Spb, zpb);
    intra_kernel<<<BH*NC, 256, SMEM_INTRA>>>(qb, kb, vb, Spb, zpb, attn3b);
    mm_kernel<<<gDMz, 256, SMEM_MM>>>(attn3b, wo3, nullptr, nullptr, nullptr, nullptr,
                                      partb, nullptr, nullptr, nullptr, DM, K3DM, 5);
    combine_kernel<<<CMB, 256>>>(partb, bo, x, x2b);

    // sublayer 2
    ln3_kernel<<<MM, 256>>>(x2b, ln2_g, ln2_b, h23b);
    mm_kernel<<<gFF, 256, SMEM_MM>>>(h23b, w13, b1, nullptr, nullptr, nullptr,
                                     nullptr, nullptr, nullptr, ffn3b, DFF, K3DM, 3);
    mm_kernel<<<gDMz, 256, SMEM_MM>>>(ffn3b, w23, nullptr, nullptr, nullptr, nullptr,
                                      partb, nullptr, nullptr, nullptr, DM, K3FF, 5);
    combine_kernel<<<CMB, 256>>>(partb, b2, x2b, out);
}

// round 9
// speedup vs baseline: 1.4181x; 1.3133x over previous
#include <cuda_runtime.h>
#include <cuda_fp16.h>
#include <math.h>
#include <stdint.h>

// ---------------- problem constants ----------------
#define BB   2
#define TT   2048
#define DM   512
#define NH   8
#define DH   64
#define DFF  2048
#define MM   (BB*TT)        // 4096 rows
#define CHK  64
#define NC   (TT/CHK)       // 32
#define BH   (BB*NH)        // 16
#define STR  68
#define K2DM (2*DM)         // 1024 (A-side row length, K=512)
#define K2FF (2*DFF)        // 4096 (A-side row length, K=2048)

// ---------------- scratch (device globals) ----------------
__device__ __align__(256) __half g_h2   [MM*K2DM];
__device__ __align__(256) float  g_q    [MM*DM];
__device__ __align__(256) float  g_k    [MM*DM];
__device__ __align__(256) float  g_v    [MM*DM];
__device__ __align__(256) __half g_attn2[MM*K2DM];
__device__ __align__(256) float  g_x2   [MM*DM];
__device__ __align__(256) __half g_h22  [MM*K2DM];
__device__ __align__(256) __half g_ffn2 [MM*K2FF];
__device__ __align__(256) float  g_part [2*MM*DM];     // split-K partials
__device__ __align__(256) __half g_wqkv [3*DM*DM];     // [Wq|Wk|Wv] rows, K=512 (hi only)
__device__ __align__(256) __half g_wo   [DM*DM];
__device__ __align__(256) __half g_w1   [DFF*DM];
__device__ __align__(256) __half g_w2   [DM*DFF];
__device__ __align__(256) float g_ckv[BH*NC*DH*DH];
__device__ __align__(256) float g_cz [BH*NC*DH];
__device__ __align__(256) float g_Sp [BH*NC*DH*DH];
__device__ __align__(256) float g_zp [BH*NC*DH];

// ---------------- helpers ----------------
__device__ __forceinline__ uint32_t smem_u32(const void* p){
    uint32_t a;
    asm("{ .reg .u64 t; cvta.to.shared.u64 t, %1; cvt.u32.u64 %0, t; }"
        : "=r"(a) : "l"(p));
    return a;
}
__device__ __forceinline__ void cp16(uint32_t dst, const void* src){
    asm volatile("cp.async.cg.shared.global [%0], [%1], 16;" :: "r"(dst), "l"(src));
}
__device__ __forceinline__ void cp_commit(){
    asm volatile("cp.async.commit_group;");
}
template<int N> __device__ __forceinline__ void cp_wait(){
    asm volatile("cp.async.wait_group %0;" :: "n"(N));
}
__device__ __forceinline__ void hsplit(float v, __half& h, __half& l){
    h = __float2half_rn(v);
    l = __float2half_rn(v - __half2float(h));
}
__device__ __forceinline__ void mma_f16(float* d, const uint32_t* a, const uint32_t* b){
    asm volatile(
        "mma.sync.aligned.m16n8k16.row.col.f32.f16.f16.f32 "
        "{%0,%1,%2,%3}, {%4,%5,%6,%7}, {%8,%9}, {%0,%1,%2,%3};"
        : "+f"(d[0]), "+f"(d[1]), "+f"(d[2]), "+f"(d[3])
        : "r"(a[0]), "r"(a[1]), "r"(a[2]), "r"(a[3]), "r"(b[0]), "r"(b[1]));
}
__device__ __forceinline__ void ldsm4(uint32_t& r0, uint32_t& r1, uint32_t& r2,
                                      uint32_t& r3, uint32_t addr){
    asm volatile("ldmatrix.sync.aligned.m8n8.x4.shared.b16 {%0,%1,%2,%3}, [%4];"
                 : "=r"(r0), "=r"(r1), "=r"(r2), "=r"(r3) : "r"(addr));
}
__device__ __forceinline__ uint32_t pack2h(__half a, __half b){
    return ((uint32_t)__half_as_ushort(b) << 16) | __half_as_ushort(a);
}

// ---------------- layernorm -> dual-fp16 (A-side [hi|lo]) ----------------
__global__ __launch_bounds__(256) void ln2_kernel(
    const float* __restrict__ x, const float* __restrict__ g,
    const float* __restrict__ b, __half* __restrict__ o2)
{
    int row = blockIdx.x;
    const float* xr = x + (size_t)row*DM;
    int tid = threadIdx.x;
    float v0 = xr[tid], v1 = xr[tid+256];
    float s = v0+v1, s2 = v0*v0+v1*v1;
#pragma unroll
    for (int off=16; off; off>>=1){
        s  += __shfl_xor_sync(0xffffffffu, s,  off);
        s2 += __shfl_xor_sync(0xffffffffu, s2, off);
    }
    __shared__ float rs[8], rs2[8], mu_s, rstd_s;
    if ((tid&31)==0){ rs[tid>>5]=s; rs2[tid>>5]=s2; }
    __syncthreads();
    if (tid==0){
        float a=0.f,c=0.f;
#pragma unroll
        for (int i=0;i<8;i++){ a+=rs[i]; c+=rs2[i]; }
        float mu = a*(1.0f/DM);
        float var = c*(1.0f/DM) - mu*mu;
        mu_s = mu; rstd_s = rsqrtf(var + 1e-5f);
    }
    __syncthreads();
    float mu = mu_s, rstd = rstd_s;
    __half* orow = o2 + (size_t)row*K2DM;
    {
        float y = (v0-mu)*rstd*g[tid] + b[tid];
        __half h,l; hsplit(y,h,l);
        orow[tid] = h; orow[tid+DM] = l;
    }
    {
        int c1 = tid+256;
        float y = (v1-mu)*rstd*g[c1] + b[c1];
        __half h,l; hsplit(y,h,l);
        orow[c1] = h; orow[c1+DM] = l;
    }
}

// -------- fused weight transpose to fp16 (hi only): all 6 weights, ONE launch ----
__global__ __launch_bounds__(256) void wconv_all_kernel(
    const float* __restrict__ Wq, const float* __restrict__ Wk,
    const float* __restrict__ Wv, const float* __restrict__ Wo,
    const float* __restrict__ W1, const float* __restrict__ W2,
    __half* __restrict__ wqkv, __half* __restrict__ wo,
    __half* __restrict__ w1,   __half* __restrict__ w2)
{
    int bid = blockIdx.x;
    const float* W; __half* Bt;
    int Kd, Nd, nx, local;
    if (bid < 512){
        int seg = bid >> 7; local = bid & 127; nx = 16; Kd = 512; Nd = 512;
        W  = (seg==0)?Wq:(seg==1)?Wk:(seg==2)?Wv:Wo;
        Bt = (seg==0)?wqkv:(seg==1)?(wqkv+512*DM):(seg==2)?(wqkv+1024*DM):wo;
    } else if (bid < 1024){
        local = bid - 512; nx = 64; Kd = 512; Nd = 2048; W = W1; Bt = w1;
    } else {
        local = bid - 1024; nx = 16; Kd = 2048; Nd = 512; W = W2; Bt = w2;
    }
    int n0 = (local % nx)*32, k0 = (local / nx)*64;

    __shared__ float t[64][33];
    int tx = threadIdx.x, ty = threadIdx.y;
#pragma unroll
    for (int i=ty;i<64;i+=8)
        t[i][tx] = W[(size_t)(k0+i)*Nd + n0 + tx];
    __syncthreads();
#pragma unroll
    for (int i=ty;i<32;i+=8){
        __half ha = __float2half_rn(t[2*tx][i]);
        __half hb = __float2half_rn(t[2*tx+1][i]);
        size_t base = (size_t)(n0+i)*Kd + k0 + 2*tx;
        *(uint32_t*)&Bt[base] = pack2h(ha, hb);
    }
}

// ------------- mma.sync fp16 GEMM, 3-stage pipeline, 2 CTAs/SM -------------
// A[M, KA=2K] = [hi|lo]; B[N, KB=K] = hi.  A chunk c pairs with B chunk c mod (KB/64).
// tile 128x128, 8 warps, K-chunk 64. gridDim.z = split-K factor on A's chunks.
// modes: 2 +bias0+res -> C0; 3 relu(+bias0) -> dual fp16 C3 (rows 2*Np);
//        4 qkv split: n<512 -> C0(elu+1,bias0), <1024 -> C1(elu+1,bias1), else C2(bias2)
//        5 raw partial fp32 -> C0 + kz*MM*Np
#define TM 128
#define TN 128
#define RS 72
#define ABY (TM*RS*2)               // 18432
#define STGB (2*ABY)                // 36864 per stage (A+B)
#define NSTG 3
#define SMEM_MM (NSTG*STGB)         // 110592

__global__ __launch_bounds__(256, 2) void mm_kernel(
    const __half* __restrict__ Ap, const __half* __restrict__ Bp,
    const float* __restrict__ bias0, const float* __restrict__ bias1,
    const float* __restrict__ bias2, const float* __restrict__ res,
    float* __restrict__ C0, float* __restrict__ C1, float* __restrict__ C2,
    __half* __restrict__ C3,
    int Np, int KA, int KB, int mode)
{
    extern __shared__ char smc[];
    uint32_t sb = smem_u32(smc);

    int tid = threadIdx.x;
    int lane = tid & 31, wid = tid >> 5;
    int wm = wid >> 1, wn = wid & 1;
    int g = lane >> 2, qp = lane & 3;
    int bm = blockIdx.y * TM;
    int bn = blockIdx.x * TN;
    int nch  = (KA >> 6) / (int)gridDim.z;
    int gc0  = blockIdx.z * nch;
    int nchH = KB >> 6;

    const char* Abase = (const char*)(Ap + (size_t)bm*KA);
    const char* Bbase = (const char*)(Bp + (size_t)bn*KB);
    const size_t rowA = (size_t)KA*2;
    const size_t rowB = (size_t)KB*2;

    int lr_ = tid >> 3, lc_ = (tid & 7)*16;
    auto loadStage = [&](int c, int s){
        int gc = gc0 + c;
        int bc = (gc >= nchH) ? gc - nchH : gc;
        uint32_t da = sb + (uint32_t)s*STGB;
        uint32_t db = da + ABY;
        const char* sa = Abase + (size_t)gc*128 + (size_t)lr_*rowA + lc_;
        const char* sbp= Bbase + (size_t)bc*128 + (size_t)lr_*rowB + lc_;
        uint32_t so = (uint32_t)(lr_*(RS*2) + lc_);
#pragma unroll
        for (int t=0;t<4;t++){
            cp16(da + so + t*32*(RS*2), sa + (size_t)t*32*rowA);
            cp16(db + so + t*32*(RS*2), sbp + (size_t)t*32*rowB);
        }
        cp_commit();
    };

    uint32_t a_off[2], b_off[4];
#pragma unroll
    for (int mf=0; mf<2; mf++){
        int arow = wm*32 + mf*16 + (lane & 15);
        a_off[mf] = (uint32_t)(arow*(RS*2) + ((lane & 16) ? 16 : 0));
    }
#pragma unroll
    for (int p=0; p<4; p++){
        int nrow = wn*64 + p*16 + (lane & 7) + ((lane & 16) >> 1);
        b_off[p] = (uint32_t)(nrow*(RS*2) + ((lane & 8) ? 16 : 0)) + ABY;
    }

    float acc[2][8][4];
#pragma unroll
    for (int i=0;i<2;i++)
#pragma unroll
        for (int j=0;j<8;j++)
#pragma unroll
            for (int k=0;k<4;k++) acc[i][j][k]=0.f;

    loadStage(0,0); loadStage(1,1);

    int cur = 0, nxt = 2;
    for (int i=0;i<nch;i++){
        cp_wait<NSTG-2>();
        __syncthreads();
        if (i+2 < nch) loadStage(i+2, nxt);
        else cp_commit();
        uint32_t S = sb + (uint32_t)cur*STGB;
#pragma unroll
        for (int ks=0; ks<4; ks++){
            uint32_t koff = (uint32_t)(ks*32);
            uint32_t a[2][4];
            ldsm4(a[0][0],a[0][1],a[0][2],a[0][3], S + a_off[0] + koff);
            ldsm4(a[1][0],a[1][1],a[1][2],a[1][3], S + a_off[1] + koff);
            uint32_t b[8][2];
#pragma unroll
            for (int p=0; p<4; p++)
                ldsm4(b[2*p][0],b[2*p][1],b[2*p+1][0],b[2*p+1][1],
                      S + b_off[p] + koff);
#pragma unroll
            for (int mf=0; mf<2; mf++)
#pragma unroll
                for (int nf=0; nf<8; nf++)
                    mma_f16(acc[mf][nf], a[mf], b[nf]);
        }
        cur = (cur==NSTG-1) ? 0 : cur+1;
        nxt = (nxt==NSTG-1) ? 0 : nxt+1;
    }

    // ---- epilogue ----
    float* Cpart = C0 + (size_t)blockIdx.z*MM*Np;
#pragma unroll
    for (int mf=0; mf<2; mf++){
#pragma unroll
        for (int half=0; half<2; half++){
            int m = bm + wm*32 + mf*16 + g + half*8;
#pragma unroll
            for (int nf=0; nf<8; nf++){
                int n = bn + wn*64 + nf*8 + qp*2;
                float v0 = acc[mf][nf][half*2+0];
                float v1 = acc[mf][nf][half*2+1];
                if (mode==5){
                    *(float2*)&Cpart[(size_t)m*Np + n] = make_float2(v0, v1);
                } else if (mode==4){
                    int sel = n >> 9;
                    int col = n & 511;
                    const float* bs = (sel==0) ? bias0 : (sel==1) ? bias1 : bias2;
                    v0 += bs[col]; v1 += bs[col+1];
                    if (sel < 2){
                        v0 = (v0 > 0.f) ? (v0+1.f) : expf(v0);
                        v1 = (v1 > 0.f) ? (v1+1.f) : expf(v1);
                    }
                    float* Cs = (sel==0) ? C0 : (sel==1) ? C1 : C2;
                    *(float2*)&Cs[(size_t)m*512 + col] = make_float2(v0, v1);
                } else {
                    v0 += bias0[n]; v1 += bias0[n+1];
                    if (mode==3){
                        v0 = fmaxf(v0, 0.f); v1 = fmaxf(v1, 0.f);
                        __half h0,l0,h1,l1;
                        hsplit(v0,h0,l0); hsplit(v1,h1,l1);
                        __half* p0 = C3 + (size_t)m*2*Np + n;
                        *(uint32_t*)(p0)      = pack2h(h0,h1);
                        *(uint32_t*)(p0 + Np) = pack2h(l0,l1);
                    } else {
                        if (mode==2){
                            float2 rr = *(const float2*)&res[(size_t)m*Np + n];
                            v0 += rr.x; v1 += rr.y;
                        }
                        *(float2*)&C0[(size_t)m*Np + n] = make_float2(v0, v1);
                    }
                }
            }
        }
    }
}

// ------- split-K combine: out = p0 + p1 + bias + res  (N fixed at DM=512) -------
__global__ __launch_bounds__(256) void combine_kernel(
    const float* __restrict__ part, const float* __restrict__ bias,
    const float* __restrict__ res, float* __restrict__ outp)
{
    int idx = (blockIdx.x*256 + threadIdx.x)*4;
    int n = idx & (DM-1);
    float4 p0 = *(const float4*)&part[idx];
    float4 p1 = *(const float4*)&part[MM*DM + idx];
    float4 bv = *(const float4*)&bias[n];
    float4 rv = *(const float4*)&res[idx];
    float4 o;
    o.x = p0.x+p1.x+bv.x+rv.x;
    o.y = p0.y+p1.y+bv.y+rv.y;
    o.z = p0.z+p1.z+bv.z+rv.z;
    o.w = p0.w+p1.w+bv.w+rv.w;
    *(float4*)&outp[idx] = o;
}

// ---------------- per-chunk K^T V and K sums ----------------
__global__ __launch_bounds__(256) void chunk_sums_kernel(
    const float* __restrict__ Kf, const float* __restrict__ Vf,
    float* __restrict__ ckv, float* __restrict__ cz)
{
    __shared__ float Ks[CHK*DH];
    __shared__ float Vs[CHK*DH];
    int blk = blockIdx.x;
    int c = blk % NC, bh = blk / NC;
    int b = bh / NH, h = bh % NH;
    int t0 = c*CHK;
    int tid = threadIdx.x;
    int lr = tid >> 4;
    int lc = (tid & 15) * 4;
    for (int r = lr; r < CHK; r += 16){
        size_t gi = ((size_t)(b*TT + t0 + r))*DM + h*DH + lc;
        *(float4*)&Ks[r*DH+lc] = *(const float4*)(Kf+gi);
        *(float4*)&Vs[r*DH+lc] = *(const float4*)(Vf+gi);
    }
    __syncthreads();
    int ti = (tid>>4)*4, tj = (tid&15)*4;
    float acc[4][4];
#pragma unroll
    for (int i=0;i<4;i++)
#pragma unroll
        for (int j=0;j<4;j++) acc[i][j]=0.f;
    for (int t=0;t<CHK;t++){
        float4 kv = *(const float4*)&Ks[t*DH+ti];
        float4 vv = *(const float4*)&Vs[t*DH+tj];
        float kk[4]={kv.x,kv.y,kv.z,kv.w}, vf[4]={vv.x,vv.y,vv.z,vv.w};
#pragma unroll
        for (int i=0;i<4;i++)
#pragma unroll
            for (int j=0;j<4;j++) acc[i][j] += kk[i]*vf[j];
    }
    float* outp = ckv + (size_t)blk*DH*DH;
#pragma unroll
    for (int i=0;i<4;i++)
        *(float4*)&outp[(ti+i)*DH + tj] =
            make_float4(acc[i][0],acc[i][1],acc[i][2],acc[i][3]);
    if (tid < DH){
        float zsum = 0.f;
        for (int t=0;t<CHK;t++) zsum += Ks[t*DH+tid];
        cz[(size_t)blk*DH + tid] = zsum;
    }
}

// --------- parallel exclusive scan over chunk states ---------
__global__ __launch_bounds__(256) void scan_kernel(
    const float* __restrict__ ckv, const float* __restrict__ cz,
    float* __restrict__ Sp, float* __restrict__ zp)
{
    int bh = blockIdx.x >> 4;
    int e  = ((blockIdx.x & 15) << 8) + threadIdx.x;
    size_t base = ((size_t)bh*NC)*(DH*DH) + e;
    float v[NC];
#pragma unroll
    for (int c=0;c<NC;c++) v[c] = ckv[base + (size_t)c*(DH*DH)];
    float s = 0.f;
#pragma unroll
    for (int c=0;c<NC;c++){ Sp[base + (size_t)c*(DH*DH)] = s; s += v[c]; }

    if ((blockIdx.x & 15)==0 && threadIdx.x < DH){
        size_t zb = (size_t)bh*NC*DH + threadIdx.x;
        float zv[NC];
#pragma unroll
        for (int c=0;c<NC;c++) zv[c] = cz[zb + (size_t)c*DH];
        float z = 0.f;
#pragma unroll
        for (int c=0;c<NC;c++){ zp[zb + (size_t)c*DH] = z; z += zv[c]; }
    }
}

// ---------------- intra-chunk attention -> dual fp16 output ----------------
__global__ __launch_bounds__(256) void intra_kernel(
    const float* __restrict__ Qf, const float* __restrict__ Kf,
    const float* __restrict__ Vf, const float* __restrict__ Sp,
    const float* __restrict__ zp, __half* __restrict__ attn2)
{
    extern __shared__ float smf[];
    float* Qt = smf;
    float* Kt = Qt + 64*STR;
    float* Vs = Kt + 64*STR;
    float* Ss = Vs + 64*STR;
    float* At = Ss + 64*STR;
    float* zs = At + 64*STR;
    float* dn = zs + 64;

    int blk = blockIdx.x;
    int c = blk % NC, bh = blk / NC;
    int b = bh / NH, h = bh % NH;
    int t0 = c*CHK;
    int tid = threadIdx.x;
    int lr = tid >> 4;
    int lc = (tid & 15) * 4;

    for (int r = lr; r < 64; r += 16){
        size_t gi = ((size_t)(b*TT + t0 + r))*DM + h*DH + lc;
        float4 q = *(const float4*)(Qf+gi);
        float4 k = *(const float4*)(Kf+gi);
        float4 v = *(const float4*)(Vf+gi);
        Qt[(lc+0)*STR+r]=q.x; Qt[(lc+1)*STR+r]=q.y; Qt[(lc+2)*STR+r]=q.z; Qt[(lc+3)*STR+r]=q.w;
        Kt[(lc+0)*STR+r]=k.x; Kt[(lc+1)*STR+r]=k.y; Kt[(lc+2)*STR+r]=k.z; Kt[(lc+3)*STR+r]=k.w;
        *(float4*)&Vs[r*STR+lc] = v;
    }
    {
        size_t base = (size_t)blk*(DH*DH);
        for (int e = tid*4; e < DH*DH; e += 1024){
            float4 sv = *(const float4*)(Sp + base + e);
            int d = e >> 6, m = e & 63;
            *(float4*)&Ss[d*STR+m] = sv;
        }
    }
    if (tid < DH) zs[tid] = zp[(size_t)blk*DH + tid];
    __syncthreads();

    int ti = (tid>>4)*4;
    int tj = (tid&15)*4;

    float a[4][4];
#pragma unroll
    for (int i=0;i<4;i++)
#pragma unroll
        for (int j=0;j<4;j++) a[i][j]=0.f;
    for (int d=0; d<64; d++){
        float4 qv = *(const float4*)&Qt[d*STR+ti];
        float4 kv = *(const float4*)&Kt[d*STR+tj];
        float qq[4]={qv.x,qv.y,qv.z,qv.w}, kk[4]={kv.x,kv.y,kv.z,kv.w};
#pragma unroll
        for (int i=0;i<4;i++)
#pragma unroll
            for (int j=0;j<4;j++) a[i][j] += qq[i]*kk[j];
    }
#pragma unroll
    for (int i=0;i<4;i++)
#pragma unroll
        for (int j=0;j<4;j++)
            At[(tj+j)*STR + (ti+i)] = ((tj+j) <= (ti+i)) ? a[i][j] : 0.f;
    __syncthreads();

    if (tid < 64){
        int t = tid;
        float dsum = 0.f;
        for (int j=0;j<64;j++) dsum += At[j*STR + t];
        for (int d=0;d<64;d++) dsum += Qt[d*STR + t]*zs[d];
        dn[t] = fmaxf(dsum, 1e-6f);
    }
    __syncthreads();

    float nacc[4][4];
#pragma unroll
    for (int i=0;i<4;i++)
#pragma unroll
        for (int j=0;j<4;j++) nacc[i][j]=0.f;
    for (int j=0;j<64;j++){
        float4 av = *(const float4*)&At[j*STR+ti];
        float4 vv = *(const float4*)&Vs[j*STR+tj];
        float af[4]={av.x,av.y,av.z,av.w}, vf[4]={vv.x,vv.y,vv.z,vv.w};
#pragma unroll
        for (int i=0;i<4;i++)
#pragma unroll
            for (int m=0;m<4;m++) nacc[i][m] += af[i]*vf[m];
    }
    for (int d=0;d<64;d++){
        float4 qv = *(const float4*)&Qt[d*STR+ti];
        float4 sv = *(const float4*)&Ss[d*STR+tj];
        float qq[4]={qv.x,qv.y,qv.z,qv.w}, sf[4]={sv.x,sv.y,sv.z,sv.w};
#pragma unroll
        for (int i=0;i<4;i++)
#pragma unroll
            for (int m=0;m<4;m++) nacc[i][m] += qq[i]*sf[m];
    }
#pragma unroll
    for (int i=0;i<4;i++){
        float inv = 1.0f / dn[ti+i];
        size_t gm = (size_t)(b*TT + t0 + ti + i);
        __half* p = attn2 + gm*K2DM + h*DH + tj;
        uint32_t hw[2], lw[2];
#pragma unroll
        for (int q=0;q<2;q++){
            float a0 = nacc[i][2*q]*inv, a1 = nacc[i][2*q+1]*inv;
            __half h0,l0,h1,l1;
            hsplit(a0,h0,l0); hsplit(a1,h1,l1);
            hw[q] = pack2h(h0,h1);
            lw[q] = pack2h(l0,l1);
        }
        *(uint2*)(p)      = make_uint2(hw[0],hw[1]);
        *(uint2*)(p+DM)   = make_uint2(lw[0],lw[1]);
    }
}

// ---------------- launch ----------------
#define SMEM_INTRA ((5*64*STR + 128) * sizeof(float))

extern "C" void kernel_launch(void* const* d_in, const int* in_sizes, int n_in,
                              void* d_out, int out_size)
{
    (void)in_sizes; (void)n_in; (void)out_size;
    const float* x     = (const float*)d_in[0];
    const float* ln1_g = (const float*)d_in[1];
    const float* ln1_b = (const float*)d_in[2];
    const float* Wq    = (const float*)d_in[3];
    const float* bq    = (const float*)d_in[4];
    const float* Wk    = (const float*)d_in[5];
    const float* bk    = (const float*)d_in[6];
    const float* Wv    = (const float*)d_in[7];
    const float* bv    = (const float*)d_in[8];
    const float* Wo    = (const float*)d_in[9];
    const float* bo    = (const float*)d_in[10];
    const float* ln2_g = (const float*)d_in[11];
    const float* ln2_b = (const float*)d_in[12];
    const float* W1    = (const float*)d_in[13];
    const float* b1    = (const float*)d_in[14];
    const float* W2    = (const float*)d_in[15];
    const float* b2    = (const float*)d_in[16];
    float* out = (float*)d_out;

    static bool attr_done = false;
    if (!attr_done){
        cudaFuncSetAttribute(intra_kernel, cudaFuncAttributeMaxDynamicSharedMemorySize,
                             (int)SMEM_INTRA);
        cudaFuncSetAttribute(mm_kernel, cudaFuncAttributeMaxDynamicSharedMemorySize,
                             SMEM_MM);
        attr_done = true;
    }

    __half *h2b,*attn2b,*h22b,*ffn2b,*wqkvb,*wob,*w1b,*w2b;
    float *qb,*kb,*vb,*x2b,*partb,*ckvb,*czb,*Spb,*zpb;
    cudaGetSymbolAddress((void**)&h2b,   g_h2);
    cudaGetSymbolAddress((void**)&qb,    g_q);
    cudaGetSymbolAddress((void**)&kb,    g_k);
    cudaGetSymbolAddress((void**)&vb,    g_v);
    cudaGetSymbolAddress((void**)&attn2b,g_attn2);
    cudaGetSymbolAddress((void**)&x2b,   g_x2);
    cudaGetSymbolAddress((void**)&h22b,  g_h22);
    cudaGetSymbolAddress((void**)&ffn2b, g_ffn2);
    cudaGetSymbolAddress((void**)&partb, g_part);
    cudaGetSymbolAddress((void**)&wqkvb, g_wqkv);
    cudaGetSymbolAddress((void**)&wob,   g_wo);
    cudaGetSymbolAddress((void**)&w1b,   g_w1);
    cudaGetSymbolAddress((void**)&w2b,   g_w2);
    cudaGetSymbolAddress((void**)&ckvb,  g_ckv);
    cudaGetSymbolAddress((void**)&czb,   g_cz);
    cudaGetSymbolAddress((void**)&Spb,   g_Sp);
    cudaGetSymbolAddress((void**)&zpb,   g_zp);

    dim3 wcb(32,8);
    wconv_all_kernel<<<1536, wcb>>>(Wq, Wk, Wv, Wo, W1, W2,
                                    wqkvb, wob, w1b, w2b);

    dim3 gQKV(3*DM/TN, MM/TM);      // (12, 32)
    dim3 gFF(DFF/TN, MM/TM);        // (16, 32)
    dim3 gDMz(DM/TN, MM/TM, 2);     // (4, 32, 2) split-K=2 -> 256 CTAs
    const int CMB = (MM*DM/4)/256;

    // sublayer 1
    ln2_kernel<<<MM, 256>>>(x, ln1_g, ln1_b, h2b);
    mm_kernel<<<gQKV, 256, SMEM_MM>>>(h2b, wqkvb, bq, bk, bv, nullptr,
                                      qb, kb, vb, nullptr, DM, K2DM, DM, 4);
    chunk_sums_kernel<<<BH*NC, 256>>>(kb, vb, ckvb, czb);
    scan_kernel<<<BH*16, 256>>>(ckvb, czb, Spb, zpb);
    intra_kernel<<<BH*NC, 256, SMEM_INTRA>>>(qb, kb, vb, Spb, zpb, attn2b);
    mm_kernel<<<gDMz, 256, SMEM_MM>>>(attn2b, wob, nullptr, nullptr, nullptr, nullptr,
                                      partb, nullptr, nullptr, nullptr, DM, K2DM, DM, 5);
    combine_kernel<<<CMB, 256>>>(partb, bo, x, x2b);

    // sublayer 2
    ln2_kernel<<<MM, 256>>>(x2b, ln2_g, ln2_b, h22b);
    mm_kernel<<<gFF, 256, SMEM_MM>>>(h22b, w1b, b1, nullptr, nullptr, nullptr,
                                     nullptr, nullptr, nullptr, ffn2b, DFF, K2DM, DM, 3);
    mm_kernel<<<gDMz, 256, SMEM_MM>>>(ffn2b, w2b, nullptr, nullptr, nullptr, nullptr,
                                      partb, nullptr, nullptr, nullptr, DM, K2FF, DFF, 5);
    combine_kernel<<<CMB, 256>>>(partb, b2, x2b, out);
}

// round 10
// speedup vs baseline: 1.5415x; 1.0870x over previous
#include <cuda_runtime.h>
#include <cuda_fp16.h>
#include <math.h>
#include <stdint.h>

// ---------------- problem constants ----------------
#define BB   2
#define TT   2048
#define DM   512
#define NH   8
#define DH   64
#define DFF  2048
#define MM   (BB*TT)        // 4096 rows
#define CHK  64
#define NC   (TT/CHK)       // 32
#define BH   (BB*NH)        // 16
#define STR  68
#define K2DM (2*DM)         // 1024
#define K2FF (2*DFF)        // 4096

// ---------------- scratch (device globals) ----------------
__device__ __align__(256) __half g_h1   [MM*DM];       // ln1 out, single fp16
__device__ __align__(256) __half g_q    [MM*DM];
__device__ __align__(256) __half g_k    [MM*DM];
__device__ __align__(256) __half g_v    [MM*DM];
__device__ __align__(256) __half g_attn2[MM*K2DM];     // dual fp16
__device__ __align__(256) float  g_x2   [MM*DM];
__device__ __align__(256) __half g_h22  [MM*K2DM];     // ln2 out, dual fp16
__device__ __align__(256) __half g_ffn2 [MM*K2FF];     // relu out, dual fp16
__device__ __align__(256) float  g_part [2*MM*DM];     // split-K partials
__device__ __align__(256) __half g_wqkv [3*DM*DM];     // [Wq|Wk|Wv] rows, K=512
__device__ __align__(256) __half g_wo   [DM*DM];
__device__ __align__(256) __half g_w1   [DFF*DM];
__device__ __align__(256) __half g_w2   [DM*DFF];
__device__ __align__(256) float g_ckv[BH*NC*DH*DH];
__device__ __align__(256) float g_cz [BH*NC*DH];
__device__ __align__(256) float g_Sp [BH*NC*DH*DH];
__device__ __align__(256) float g_zp [BH*NC*DH];

// ---------------- helpers ----------------
__device__ __forceinline__ uint32_t smem_u32(const void* p){
    uint32_t a;
    asm("{ .reg .u64 t; cvta.to.shared.u64 t, %1; cvt.u32.u64 %0, t; }"
        : "=r"(a) : "l"(p));
    return a;
}
__device__ __forceinline__ void cp16(uint32_t dst, const void* src){
    asm volatile("cp.async.cg.shared.global [%0], [%1], 16;" :: "r"(dst), "l"(src));
}
__device__ __forceinline__ void cp_commit(){
    asm volatile("cp.async.commit_group;");
}
template<int N> __device__ __forceinline__ void cp_wait(){
    asm volatile("cp.async.wait_group %0;" :: "n"(N));
}
__device__ __forceinline__ void hsplit(float v, __half& h, __half& l){
    h = __float2half_rn(v);
    l = __float2half_rn(v - __half2float(h));
}
__device__ __forceinline__ void mma_f16(float* d, const uint32_t* a, const uint32_t* b){
    asm volatile(
        "mma.sync.aligned.m16n8k16.row.col.f32.f16.f16.f32 "
        "{%0,%1,%2,%3}, {%4,%5,%6,%7}, {%8,%9}, {%0,%1,%2,%3};"
        : "+f"(d[0]), "+f"(d[1]), "+f"(d[2]), "+f"(d[3])
        : "r"(a[0]), "r"(a[1]), "r"(a[2]), "r"(a[3]), "r"(b[0]), "r"(b[1]));
}
__device__ __forceinline__ void ldsm4(uint32_t& r0, uint32_t& r1, uint32_t& r2,
                                      uint32_t& r3, uint32_t addr){
    asm volatile("ldmatrix.sync.aligned.m8n8.x4.shared.b16 {%0,%1,%2,%3}, [%4];"
                 : "=r"(r0), "=r"(r1), "=r"(r2), "=r"(r3) : "r"(addr));
}
__device__ __forceinline__ uint32_t pack2h(__half a, __half b){
    return ((uint32_t)__half_as_ushort(b) << 16) | __half_as_ushort(a);
}
__device__ __forceinline__ float4 h4_to_f4(uint2 u){
    __half2 p0 = *(__half2*)&u.x, p1 = *(__half2*)&u.y;
    float2 f0 = __half22float2(p0), f1 = __half22float2(p1);
    return make_float4(f0.x, f0.y, f1.x, f1.y);
}

// ---------------- layernorm 1 -> single fp16 ----------------
__global__ __launch_bounds__(256) void ln1h_kernel(
    const float* __restrict__ x, const float* __restrict__ g,
    const float* __restrict__ b, __half* __restrict__ o)
{
    int row = blockIdx.x;
    const float* xr = x + (size_t)row*DM;
    int tid = threadIdx.x;
    float v0 = xr[tid], v1 = xr[tid+256];
    float s = v0+v1, s2 = v0*v0+v1*v1;
#pragma unroll
    for (int off=16; off; off>>=1){
        s  += __shfl_xor_sync(0xffffffffu, s,  off);
        s2 += __shfl_xor_sync(0xffffffffu, s2, off);
    }
    __shared__ float rs[8], rs2[8], mu_s, rstd_s;
    if ((tid&31)==0){ rs[tid>>5]=s; rs2[tid>>5]=s2; }
    __syncthreads();
    if (tid==0){
        float a=0.f,c=0.f;
#pragma unroll
        for (int i=0;i<8;i++){ a+=rs[i]; c+=rs2[i]; }
        float mu = a*(1.0f/DM);
        float var = c*(1.0f/DM) - mu*mu;
        mu_s = mu; rstd_s = rsqrtf(var + 1e-5f);
    }
    __syncthreads();
    float mu = mu_s, rstd = rstd_s;
    __half* orow = o + (size_t)row*DM;
    orow[tid]     = __float2half_rn((v0-mu)*rstd*g[tid]     + b[tid]);
    orow[tid+256] = __float2half_rn((v1-mu)*rstd*g[tid+256] + b[tid+256]);
}

// ------- fused: x2 = p0+p1+bo+x ; LN2(x2) -> dual fp16 ; also writes x2 -------
__global__ __launch_bounds__(256) void ln2f_kernel(
    const float* __restrict__ part, const float* __restrict__ bo,
    const float* __restrict__ x, const float* __restrict__ g,
    const float* __restrict__ b, float* __restrict__ x2o,
    __half* __restrict__ o2)
{
    int row = blockIdx.x;
    int tid = threadIdx.x;
    size_t i0 = (size_t)row*DM + tid, i1 = i0 + 256;
    float v0 = part[i0] + part[(size_t)MM*DM + i0] + bo[tid]     + x[i0];
    float v1 = part[i1] + part[(size_t)MM*DM + i1] + bo[tid+256] + x[i1];
    x2o[i0] = v0; x2o[i1] = v1;
    float s = v0+v1, s2 = v0*v0+v1*v1;
#pragma unroll
    for (int off=16; off; off>>=1){
        s  += __shfl_xor_sync(0xffffffffu, s,  off);
        s2 += __shfl_xor_sync(0xffffffffu, s2, off);
    }
    __shared__ float rs[8], rs2[8], mu_s, rstd_s;
    if ((tid&31)==0){ rs[tid>>5]=s; rs2[tid>>5]=s2; }
    __syncthreads();
    if (tid==0){
        float a=0.f,c=0.f;
#pragma unroll
        for (int i=0;i<8;i++){ a+=rs[i]; c+=rs2[i]; }
        float mu = a*(1.0f/DM);
        float var = c*(1.0f/DM) - mu*mu;
        mu_s = mu; rstd_s = rsqrtf(var + 1e-5f);
    }
    __syncthreads();
    float mu = mu_s, rstd = rstd_s;
    __half* orow = o2 + (size_t)row*K2DM;
    {
        float y = (v0-mu)*rstd*g[tid] + b[tid];
        __half h,l; hsplit(y,h,l);
        orow[tid] = h; orow[tid+DM] = l;
    }
    {
        int c1 = tid+256;
        float y = (v1-mu)*rstd*g[c1] + b[c1];
        __half h,l; hsplit(y,h,l);
        orow[c1] = h; orow[c1+DM] = l;
    }
}

// -------- fused weight transpose to fp16: all 6 weights, ONE launch ----------
__global__ __launch_bounds__(256) void wconv_all_kernel(
    const float* __restrict__ Wq, const float* __restrict__ Wk,
    const float* __restrict__ Wv, const float* __restrict__ Wo,
    const float* __restrict__ W1, const float* __restrict__ W2,
    __half* __restrict__ wqkv, __half* __restrict__ wo,
    __half* __restrict__ w1,   __half* __restrict__ w2)
{
    int bid = blockIdx.x;
    const float* W; __half* Bt;
    int Kd, Nd, nx, local;
    if (bid < 512){
        int seg = bid >> 7; local = bid & 127; nx = 16; Kd = 512; Nd = 512;
        W  = (seg==0)?Wq:(seg==1)?Wk:(seg==2)?Wv:Wo;
        Bt = (seg==0)?wqkv:(seg==1)?(wqkv+512*DM):(seg==2)?(wqkv+1024*DM):wo;
    } else if (bid < 1024){
        local = bid - 512; nx = 64; Kd = 512; Nd = 2048; W = W1; Bt = w1;
    } else {
        local = bid - 1024; nx = 16; Kd = 2048; Nd = 512; W = W2; Bt = w2;
    }
    int n0 = (local % nx)*32, k0 = (local / nx)*64;

    __shared__ float t[64][33];
    int tx = threadIdx.x, ty = threadIdx.y;
#pragma unroll
    for (int i=ty;i<64;i+=8)
        t[i][tx] = W[(size_t)(k0+i)*Nd + n0 + tx];
    __syncthreads();
#pragma unroll
    for (int i=ty;i<32;i+=8){
        __half ha = __float2half_rn(t[2*tx][i]);
        __half hb = __float2half_rn(t[2*tx+1][i]);
        size_t base = (size_t)(n0+i)*Kd + k0 + 2*tx;
        *(uint32_t*)&Bt[base] = pack2h(ha, hb);
    }
}

// ------------- mma.sync fp16 GEMM, 3-stage pipeline, 2 CTAs/SM -------------
// A[M, KA]; B[N, KB] (KA = KB or 2*KB; A chunk c pairs with B chunk c mod (KB/64)).
// modes: 3 relu(+bias0) -> dual fp16 C3 (row stride 2*Np);
//        4 qkv split fp16 out: n<512 -> H0(elu+1,bias0), <1024 -> H1(elu+1,bias1),
//          else H2(bias2);
//        5 raw partial fp32 -> C0 + z*MM*Np
#define TM 128
#define TN 128
#define RS 72
#define ABY (TM*RS*2)
#define STGB (2*ABY)
#define NSTG 3
#define SMEM_MM (NSTG*STGB)

__global__ __launch_bounds__(256, 2) void mm_kernel(
    const __half* __restrict__ Ap, const __half* __restrict__ Bp,
    const float* __restrict__ bias0, const float* __restrict__ bias1,
    const float* __restrict__ bias2,
    float* __restrict__ C0, __half* __restrict__ H0, __half* __restrict__ H1,
    __half* __restrict__ H2, __half* __restrict__ C3,
    int Np, int KA, int KB, int mode)
{
    extern __shared__ char smc[];
    uint32_t sb = smem_u32(smc);

    int tid = threadIdx.x;
    int lane = tid & 31, wid = tid >> 5;
    int wm = wid >> 1, wn = wid & 1;
    int g = lane >> 2, qp = lane & 3;
    int bm = blockIdx.y * TM;
    int bn = blockIdx.x * TN;
    int nch  = (KA >> 6) / (int)gridDim.z;
    int gc0  = blockIdx.z * nch;
    int nchH = KB >> 6;

    const char* Abase = (const char*)(Ap + (size_t)bm*KA);
    const char* Bbase = (const char*)(Bp + (size_t)bn*KB);
    const size_t rowA = (size_t)KA*2;
    const size_t rowB = (size_t)KB*2;

    int lr_ = tid >> 3, lc_ = (tid & 7)*16;
    auto loadStage = [&](int c, int s){
        int gc = gc0 + c;
        int bc = (gc >= nchH) ? gc - nchH : gc;
        uint32_t da = sb + (uint32_t)s*STGB;
        uint32_t db = da + ABY;
        const char* sa = Abase + (size_t)gc*128 + (size_t)lr_*rowA + lc_;
        const char* sbp= Bbase + (size_t)bc*128 + (size_t)lr_*rowB + lc_;
        uint32_t so = (uint32_t)(lr_*(RS*2) + lc_);
#pragma unroll
        for (int t=0;t<4;t++){
            cp16(da + so + t*32*(RS*2), sa + (size_t)t*32*rowA);
            cp16(db + so + t*32*(RS*2), sbp + (size_t)t*32*rowB);
        }
        cp_commit();
    };

    uint32_t a_off[2], b_off[4];
#pragma unroll
    for (int mf=0; mf<2; mf++){
        int arow = wm*32 + mf*16 + (lane & 15);
        a_off[mf] = (uint32_t)(arow*(RS*2) + ((lane & 16) ? 16 : 0));
    }
#pragma unroll
    for (int p=0; p<4; p++){
        int nrow = wn*64 + p*16 + (lane & 7) + ((lane & 16) >> 1);
        b_off[p] = (uint32_t)(nrow*(RS*2) + ((lane & 8) ? 16 : 0)) + ABY;
    }

    float acc[2][8][4];
#pragma unroll
    for (int i=0;i<2;i++)
#pragma unroll
        for (int j=0;j<8;j++)
#pragma unroll
            for (int k=0;k<4;k++) acc[i][j][k]=0.f;

    loadStage(0,0); loadStage(1,1);

    int cur = 0, nxt = 2;
    for (int i=0;i<nch;i++){
        cp_wait<NSTG-2>();
        __syncthreads();
        if (i+2 < nch) loadStage(i+2, nxt);
        else cp_commit();
        uint32_t S = sb + (uint32_t)cur*STGB;
#pragma unroll
        for (int ks=0; ks<4; ks++){
            uint32_t koff = (uint32_t)(ks*32);
            uint32_t a[2][4];
            ldsm4(a[0][0],a[0][1],a[0][2],a[0][3], S + a_off[0] + koff);
            ldsm4(a[1][0],a[1][1],a[1][2],a[1][3], S + a_off[1] + koff);
            uint32_t b[8][2];
#pragma unroll
            for (int p=0; p<4; p++)
                ldsm4(b[2*p][0],b[2*p][1],b[2*p+1][0],b[2*p+1][1],
                      S + b_off[p] + koff);
#pragma unroll
            for (int mf=0; mf<2; mf++)
#pragma unroll
                for (int nf=0; nf<8; nf++)
                    mma_f16(acc[mf][nf], a[mf], b[nf]);
        }
        cur = (cur==NSTG-1) ? 0 : cur+1;
        nxt = (nxt==NSTG-1) ? 0 : nxt+1;
    }

    // ---- epilogue ----
    float* Cpart = C0 + (size_t)blockIdx.z*MM*Np;
#pragma unroll
    for (int mf=0; mf<2; mf++){
#pragma unroll
        for (int half=0; half<2; half++){
            int m = bm + wm*32 + mf*16 + g + half*8;
#pragma unroll
            for (int nf=0; nf<8; nf++){
                int n = bn + wn*64 + nf*8 + qp*2;
                float v0 = acc[mf][nf][half*2+0];
                float v1 = acc[mf][nf][half*2+1];
                if (mode==5){
                    *(float2*)&Cpart[(size_t)m*Np + n] = make_float2(v0, v1);
                } else if (mode==4){
                    int sel = n >> 9;
                    int col = n & 511;
                    const float* bs = (sel==0) ? bias0 : (sel==1) ? bias1 : bias2;
                    v0 += bs[col]; v1 += bs[col+1];
                    if (sel < 2){
                        v0 = (v0 > 0.f) ? (v0+1.f) : expf(v0);
                        v1 = (v1 > 0.f) ? (v1+1.f) : expf(v1);
                    }
                    __half* Hs = (sel==0) ? H0 : (sel==1) ? H1 : H2;
                    *(uint32_t*)&Hs[(size_t)m*512 + col] =
                        pack2h(__float2half_rn(v0), __float2half_rn(v1));
                } else { // mode 3
                    v0 = fmaxf(v0 + bias0[n],   0.f);
                    v1 = fmaxf(v1 + bias0[n+1], 0.f);
                    __half h0,l0,h1,l1;
                    hsplit(v0,h0,l0); hsplit(v1,h1,l1);
                    __half* p0 = C3 + (size_t)m*2*Np + n;
                    *(uint32_t*)(p0)      = pack2h(h0,h1);
                    *(uint32_t*)(p0 + Np) = pack2h(l0,l1);
                }
            }
        }
    }
}

// ------- split-K combine: out = p0 + p1 + bias + res  (N fixed at DM=512) -------
__global__ __launch_bounds__(256) void combine_kernel(
    const float* __restrict__ part, const float* __restrict__ bias,
    const float* __restrict__ res, float* __restrict__ outp)
{
    int idx = (blockIdx.x*256 + threadIdx.x)*4;
    int n = idx & (DM-1);
    float4 p0 = *(const float4*)&part[idx];
    float4 p1 = *(const float4*)&part[MM*DM + idx];
    float4 bv = *(const float4*)&bias[n];
    float4 rv = *(const float4*)&res[idx];
    float4 o;
    o.x = p0.x+p1.x+bv.x+rv.x;
    o.y = p0.y+p1.y+bv.y+rv.y;
    o.z = p0.z+p1.z+bv.z+rv.z;
    o.w = p0.w+p1.w+bv.w+rv.w;
    *(float4*)&outp[idx] = o;
}

// ---------------- per-chunk K^T V and K sums (fp16 inputs) ----------------
__global__ __launch_bounds__(256) void chunk_sums_kernel(
    const __half* __restrict__ Kf, const __half* __restrict__ Vf,
    float* __restrict__ ckv, float* __restrict__ cz)
{
    __shared__ float Ks[CHK*DH];
    __shared__ float Vs[CHK*DH];
    int blk = blockIdx.x;
    int c = blk % NC, bh = blk / NC;
    int b = bh / NH, h = bh % NH;
    int t0 = c*CHK;
    int tid = threadIdx.x;
    int lr = tid >> 4;
    int lc = (tid & 15) * 4;
    for (int r = lr; r < CHK; r += 16){
        size_t gi = ((size_t)(b*TT + t0 + r))*DM + h*DH + lc;
        *(float4*)&Ks[r*DH+lc] = h4_to_f4(*(const uint2*)(Kf+gi));
        *(float4*)&Vs[r*DH+lc] = h4_to_f4(*(const uint2*)(Vf+gi));
    }
    __syncthreads();
    int ti = (tid>>4)*4, tj = (tid&15)*4;
    float acc[4][4];
#pragma unroll
    for (int i=0;i<4;i++)
#pragma unroll
        for (int j=0;j<4;j++) acc[i][j]=0.f;
    for (int t=0;t<CHK;t++){
        float4 kv = *(const float4*)&Ks[t*DH+ti];
        float4 vv = *(const float4*)&Vs[t*DH+tj];
        float kk[4]={kv.x,kv.y,kv.z,kv.w}, vf[4]={vv.x,vv.y,vv.z,vv.w};
#pragma unroll
        for (int i=0;i<4;i++)
#pragma unroll
            for (int j=0;j<4;j++) acc[i][j] += kk[i]*vf[j];
    }
    float* outp = ckv + (size_t)blk*DH*DH;
#pragma unroll
    for (int i=0;i<4;i++)
        *(float4*)&outp[(ti+i)*DH + tj] =
            make_float4(acc[i][0],acc[i][1],acc[i][2],acc[i][3]);
    if (tid < DH){
        float zsum = 0.f;
        for (int t=0;t<CHK;t++) zsum += Ks[t*DH+tid];
        cz[(size_t)blk*DH + tid] = zsum;
    }
}

// --------- parallel exclusive scan over chunk states ---------
__global__ __launch_bounds__(256) void scan_kernel(
    const float* __restrict__ ckv, const float* __restrict__ cz,
    float* __restrict__ Sp, float* __restrict__ zp)
{
    int bh = blockIdx.x >> 4;
    int e  = ((blockIdx.x & 15) << 8) + threadIdx.x;
    size_t base = ((size_t)bh*NC)*(DH*DH) + e;
    float v[NC];
#pragma unroll
    for (int c=0;c<NC;c++) v[c] = ckv[base + (size_t)c*(DH*DH)];
    float s = 0.f;
#pragma unroll
    for (int c=0;c<NC;c++){ Sp[base + (size_t)c*(DH*DH)] = s; s += v[c]; }

    if ((blockIdx.x & 15)==0 && threadIdx.x < DH){
        size_t zb = (size_t)bh*NC*DH + threadIdx.x;
        float zv[NC];
#pragma unroll
        for (int c=0;c<NC;c++) zv[c] = cz[zb + (size_t)c*DH];
        float z = 0.f;
#pragma unroll
        for (int c=0;c<NC;c++){ zp[zb + (size_t)c*DH] = z; z += zv[c]; }
    }
}

// ---------- intra-chunk attention (fp16 q/k/v in) -> dual fp16 out ----------
__global__ __launch_bounds__(256) void intra_kernel(
    const __half* __restrict__ Qf, const __half* __restrict__ Kf,
    const __half* __restrict__ Vf, const float* __restrict__ Sp,
    const float* __restrict__ zp, __half* __restrict__ attn2)
{
    extern __shared__ float smf[];
    float* Qt = smf;
    float* Kt = Qt + 64*STR;
    float* Vs = Kt + 64*STR;
    float* Ss = Vs + 64*STR;
    float* At = Ss + 64*STR;
    float* zs = At + 64*STR;
    float* dn = zs + 64;

    int blk = blockIdx.x;
    int c = blk % NC, bh = blk / NC;
    int b = bh / NH, h = bh % NH;
    int t0 = c*CHK;
    int tid = threadIdx.x;
    int lr = tid >> 4;
    int lc = (tid & 15) * 4;

    for (int r = lr; r < 64; r += 16){
        size_t gi = ((size_t)(b*TT + t0 + r))*DM + h*DH + lc;
        float4 q = h4_to_f4(*(const uint2*)(Qf+gi));
        float4 k = h4_to_f4(*(const uint2*)(Kf+gi));
        float4 v = h4_to_f4(*(const uint2*)(Vf+gi));
        Qt[(lc+0)*STR+r]=q.x; Qt[(lc+1)*STR+r]=q.y; Qt[(lc+2)*STR+r]=q.z; Qt[(lc+3)*STR+r]=q.w;
        Kt[(lc+0)*STR+r]=k.x; Kt[(lc+1)*STR+r]=k.y; Kt[(lc+2)*STR+r]=k.z; Kt[(lc+3)*STR+r]=k.w;
        *(float4*)&Vs[r*STR+lc] = v;
    }
    {
        size_t base = (size_t)blk*(DH*DH);
        for (int e = tid*4; e < DH*DH; e += 1024){
            float4 sv = *(const float4*)(Sp + base + e);
            int d = e >> 6, m = e & 63;
            *(float4*)&Ss[d*STR+m] = sv;
        }
    }
    if (tid < DH) zs[tid] = zp[(size_t)blk*DH + tid];
    __syncthreads();

    int ti = (tid>>4)*4;
    int tj = (tid&15)*4;

    float a[4][4];
#pragma unroll
    for (int i=0;i<4;i++)
#pragma unroll
        for (int j=0;j<4;j++) a[i][j]=0.f;
    for (int d=0; d<64; d++){
        float4 qv = *(const float4*)&Qt[d*STR+ti];
        float4 kv = *(const float4*)&Kt[d*STR+tj];
        float qq[4]={qv.x,qv.y,qv.z,qv.w}, kk[4]={kv.x,kv.y,kv.z,kv.w};
#pragma unroll
        for (int i=0;i<4;i++)
#pragma unroll
            for (int j=0;j<4;j++) a[i][j] += qq[i]*kk[j];
    }
#pragma unroll
    for (int i=0;i<4;i++)
#pragma unroll
        for (int j=0;j<4;j++)
            At[(tj+j)*STR + (ti+i)] = ((tj+j) <= (ti+i)) ? a[i][j] : 0.f;
    __syncthreads();

    if (tid < 64){
        int t = tid;
        float dsum = 0.f;
        for (int j=0;j<64;j++) dsum += At[j*STR + t];
        for (int d=0;d<64;d++) dsum += Qt[d*STR + t]*zs[d];
        dn[t] = fmaxf(dsum, 1e-6f);
    }
    __syncthreads();

    float nacc[4][4];
#pragma unroll
    for (int i=0;i<4;i++)
#pragma unroll
        for (int j=0;j<4;j++) nacc[i][j]=0.f;
    for (int j=0;j<64;j++){
        float4 av = *(const float4*)&At[j*STR+ti];
        float4 vv = *(const float4*)&Vs[j*STR+tj];
        float af[4]={av.x,av.y,av.z,av.w}, vf[4]={vv.x,vv.y,vv.z,vv.w};
#pragma unroll
        for (int i=0;i<4;i++)
#pragma unroll
            for (int m=0;m<4;m++) nacc[i][m] += af[i]*vf[m];
    }
    for (int d=0;d<64;d++){
        float4 qv = *(const float4*)&Qt[d*STR+ti];
        float4 sv = *(const float4*)&Ss[d*STR+tj];
        float qq[4]={qv.x,qv.y,qv.z,qv.w}, sf[4]={sv.x,sv.y,sv.z,sv.w};
#pragma unroll
        for (int i=0;i<4;i++)
#pragma unroll
            for (int m=0;m<4;m++) nacc[i][m] += qq[i]*sf[m];
    }
#pragma unroll
    for (int i=0;i<4;i++){
        float inv = 1.0f / dn[ti+i];
        size_t gm = (size_t)(b*TT + t0 + ti + i);
        __half* p = attn2 + gm*K2DM + h*DH + tj;
        uint32_t hw[2], lw[2];
#pragma unroll
        for (int q=0;q<2;q++){
            float a0 = nacc[i][2*q]*inv, a1 = nacc[i][2*q+1]*inv;
            __half h0,l0,h1,l1;
            hsplit(a0,h0,l0); hsplit(a1,h1,l1);
            hw[q] = pack2h(h0,h1);
            lw[q] = pack2h(l0,l1);
        }
        *(uint2*)(p)      = make_uint2(hw[0],hw[1]);
        *(uint2*)(p+DM)   = make_uint2(lw[0],lw[1]);
    }
}

// ---------------- launch ----------------
#define SMEM_INTRA ((5*64*STR + 128) * sizeof(float))

extern "C" void kernel_launch(void* const* d_in, const int* in_sizes, int n_in,
                              void* d_out, int out_size)
{
    (void)in_sizes; (void)n_in; (void)out_size;
    const float* x     = (const float*)d_in[0];
    const float* ln1_g = (const float*)d_in[1];
    const float* ln1_b = (const float*)d_in[2];
    const float* Wq    = (const float*)d_in[3];
    const float* bq    = (const float*)d_in[4];
    const float* Wk    = (const float*)d_in[5];
    const float* bk    = (const float*)d_in[6];
    const float* Wv    = (const float*)d_in[7];
    const float* bv    = (const float*)d_in[8];
    const float* Wo    = (const float*)d_in[9];
    const float* bo    = (const float*)d_in[10];
    const float* ln2_g = (const float*)d_in[11];
    const float* ln2_b = (const float*)d_in[12];
    const float* W1    = (const float*)d_in[13];
    const float* b1    = (const float*)d_in[14];
    const float* W2    = (const float*)d_in[15];
    const float* b2    = (const float*)d_in[16];
    float* out = (float*)d_out;

    static bool attr_done = false;
    if (!attr_done){
        cudaFuncSetAttribute(intra_kernel, cudaFuncAttributeMaxDynamicSharedMemorySize,
                             (int)SMEM_INTRA);
        cudaFuncSetAttribute(mm_kernel, cudaFuncAttributeMaxDynamicSharedMemorySize,
                             SMEM_MM);
        attr_done = true;
    }

    __half *h1b,*attn2b,*h22b,*ffn2b,*wqkvb,*wob,*w1b,*w2b,*qb,*kb,*vb;
    float *x2b,*partb,*ckvb,*czb,*Spb,*zpb;
    cudaGetSymbolAddress((void**)&h1b,   g_h1);
    cudaGetSymbolAddress((void**)&qb,    g_q);
    cudaGetSymbolAddress((void**)&kb,    g_k);
    cudaGetSymbolAddress((void**)&vb,    g_v);
    cudaGetSymbolAddress((void**)&attn2b,g_attn2);
    cudaGetSymbolAddress((void**)&x2b,   g_x2);
    cudaGetSymbolAddress((void**)&h22b,  g_h22);
    cudaGetSymbolAddress((void**)&ffn2b, g_ffn2);
    cudaGetSymbolAddress((void**)&partb, g_part);
    cudaGetSymbolAddress((void**)&wqkvb, g_wqkv);
    cudaGetSymbolAddress((void**)&wob,   g_wo);
    cudaGetSymbolAddress((void**)&w1b,   g_w1);
    cudaGetSymbolAddress((void**)&w2b,   g_w2);
    cudaGetSymbolAddress((void**)&ckvb,  g_ckv);
    cudaGetSymbolAddress((void**)&czb,   g_cz);
    cudaGetSymbolAddress((void**)&Spb,   g_Sp);
    cudaGetSymbolAddress((void**)&zpb,   g_zp);

    dim3 wcb(32,8);
    wconv_all_kernel<<<1536, wcb>>>(Wq, Wk, Wv, Wo, W1, W2,
                                    wqkvb, wob, w1b, w2b);

    dim3 gQKV(3*DM/TN, MM/TM);      // (12, 32)
    dim3 gFF(DFF/TN, MM/TM);        // (16, 32)
    dim3 gDMz(DM/TN, MM/TM, 2);     // (4, 32, 2) split-K=2
    const int CMB = (MM*DM/4)/256;

    // sublayer 1
    ln1h_kernel<<<MM, 256>>>(x, ln1_g, ln1_b, h1b);
    mm_kernel<<<gQKV, 256, SMEM_MM>>>(h1b, wqkvb, bq, bk, bv,
                                      nullptr, qb, kb, vb, nullptr,
                                      DM, DM, DM, 4);
    chunk_sums_kernel<<<BH*NC, 256>>>(kb, vb, ckvb, czb);
    scan_kernel<<<BH*16, 256>>>(ckvb, czb, Spb, zpb);
    intra_kernel<<<BH*NC, 256, SMEM_INTRA>>>(qb, kb, vb, Spb, zpb, attn2b);
    mm_kernel<<<gDMz, 256, SMEM_MM>>>(attn2b, wob, nullptr, nullptr, nullptr,
                                      partb, nullptr, nullptr, nullptr, nullptr,
                                      DM, K2DM, DM, 5);
    // fused combine + LN2
    ln2f_kernel<<<MM, 256>>>(partb, bo, x, ln2_g, ln2_b, x2b, h22b);

    // sublayer 2
    mm_kernel<<<gFF, 256, SMEM_MM>>>(h22b, w1b, b1, nullptr, nullptr,
                                     nullptr, nullptr, nullptr, nullptr, ffn2b,
                                     DFF, K2DM, DM, 3);
    mm_kernel<<<gDMz, 256, SMEM_MM>>>(ffn2b, w2b, nullptr, nullptr, nullptr,
                                      partb, nullptr, nullptr, nullptr, nullptr,
                                      DM, K2FF, DFF, 5);
    combine_kernel<<<CMB, 256>>>(partb, b2, x2b, out);
}

// round 11
// speedup vs baseline: 2.0855x; 1.3529x over previous
#include <cuda_runtime.h>
#include <cuda_fp16.h>
#include <math.h>
#include <stdint.h>

// ---------------- problem constants ----------------
#define BB   2
#define TT   2048
#define DM   512
#define NH   8
#define DH   64
#define DFF  2048
#define MM   (BB*TT)        // 4096 rows
#define CHK  64
#define NC   (TT/CHK)       // 32
#define BH   (BB*NH)        // 16
#define STR  68

// ---------------- scratch (device globals) ----------------
__device__ __align__(256) __half g_h1   [MM*DM];       // ln1 out fp16
__device__ __align__(256) __half g_q    [MM*DM];
__device__ __align__(256) __half g_k    [MM*DM];
__device__ __align__(256) __half g_v    [MM*DM];
__device__ __align__(256) __half g_attn1[MM*DM];       // attn out fp16
__device__ __align__(256) float  g_x2   [MM*DM];
__device__ __align__(256) __half g_h22  [MM*DM];       // ln2 out fp16
__device__ __align__(256) __half g_ffn1 [MM*DFF];      // relu out fp16
__device__ __align__(256) float  g_part [2*MM*DM];     // split-K partials
__device__ __align__(256) __half g_wqkv [3*DM*DM];     // [Wq|Wk|Wv] rows, K=512
__device__ __align__(256) __half g_wo   [DM*DM];
__device__ __align__(256) __half g_w1   [DFF*DM];
__device__ __align__(256) __half g_w2   [DM*DFF];
__device__ __align__(256) float g_ckv[BH*NC*DH*DH];
__device__ __align__(256) float g_cz [BH*NC*DH];
__device__ __align__(256) float g_Sp [BH*NC*DH*DH];
__device__ __align__(256) float g_zp [BH*NC*DH];

// ---------------- helpers ----------------
__device__ __forceinline__ uint32_t smem_u32(const void* p){
    uint32_t a;
    asm("{ .reg .u64 t; cvta.to.shared.u64 t, %1; cvt.u32.u64 %0, t; }"
        : "=r"(a) : "l"(p));
    return a;
}
__device__ __forceinline__ void cp16(uint32_t dst, const void* src){
    asm volatile("cp.async.cg.shared.global [%0], [%1], 16;" :: "r"(dst), "l"(src));
}
__device__ __forceinline__ void cp_commit(){
    asm volatile("cp.async.commit_group;");
}
template<int N> __device__ __forceinline__ void cp_wait(){
    asm volatile("cp.async.wait_group %0;" :: "n"(N));
}
__device__ __forceinline__ void mma_f16(float* d, const uint32_t* a, const uint32_t* b){
    asm volatile(
        "mma.sync.aligned.m16n8k16.row.col.f32.f16.f16.f32 "
        "{%0,%1,%2,%3}, {%4,%5,%6,%7}, {%8,%9}, {%0,%1,%2,%3};"
        : "+f"(d[0]), "+f"(d[1]), "+f"(d[2]), "+f"(d[3])
        : "r"(a[0]), "r"(a[1]), "r"(a[2]), "r"(a[3]), "r"(b[0]), "r"(b[1]));
}
__device__ __forceinline__ void ldsm4(uint32_t& r0, uint32_t& r1, uint32_t& r2,
                                      uint32_t& r3, uint32_t addr){
    asm volatile("ldmatrix.sync.aligned.m8n8.x4.shared.b16 {%0,%1,%2,%3}, [%4];"
                 : "=r"(r0), "=r"(r1), "=r"(r2), "=r"(r3) : "r"(addr));
}
__device__ __forceinline__ uint32_t pack2h(__half a, __half b){
    return ((uint32_t)__half_as_ushort(b) << 16) | __half_as_ushort(a);
}
__device__ __forceinline__ float4 h4_to_f4(uint2 u){
    __half2 p0 = *(__half2*)&u.x, p1 = *(__half2*)&u.y;
    float2 f0 = __half22float2(p0), f1 = __half22float2(p1);
    return make_float4(f0.x, f0.y, f1.x, f1.y);
}

// ---------------- layernorm 1 -> fp16 ----------------
__global__ __launch_bounds__(256) void ln1h_kernel(
    const float* __restrict__ x, const float* __restrict__ g,
    const float* __restrict__ b, __half* __restrict__ o)
{
    int row = blockIdx.x;
    const float* xr = x + (size_t)row*DM;
    int tid = threadIdx.x;
    float v0 = xr[tid], v1 = xr[tid+256];
    float s = v0+v1, s2 = v0*v0+v1*v1;
#pragma unroll
    for (int off=16; off; off>>=1){
        s  += __shfl_xor_sync(0xffffffffu, s,  off);
        s2 += __shfl_xor_sync(0xffffffffu, s2, off);
    }
    __shared__ float rs[8], rs2[8], mu_s, rstd_s;
    if ((tid&31)==0){ rs[tid>>5]=s; rs2[tid>>5]=s2; }
    __syncthreads();
    if (tid==0){
        float a=0.f,c=0.f;
#pragma unroll
        for (int i=0;i<8;i++){ a+=rs[i]; c+=rs2[i]; }
        float mu = a*(1.0f/DM);
        float var = c*(1.0f/DM) - mu*mu;
        mu_s = mu; rstd_s = rsqrtf(var + 1e-5f);
    }
    __syncthreads();
    float mu = mu_s, rstd = rstd_s;
    __half* orow = o + (size_t)row*DM;
    orow[tid]     = __float2half_rn((v0-mu)*rstd*g[tid]     + b[tid]);
    orow[tid+256] = __float2half_rn((v1-mu)*rstd*g[tid+256] + b[tid+256]);
}

// ------- fused: x2 = p0+p1+bo+x ; LN2(x2) -> fp16 ; also writes x2 -------
__global__ __launch_bounds__(256) void ln2f_kernel(
    const float* __restrict__ part, const float* __restrict__ bo,
    const float* __restrict__ x, const float* __restrict__ g,
    const float* __restrict__ b, float* __restrict__ x2o,
    __half* __restrict__ o2)
{
    int row = blockIdx.x;
    int tid = threadIdx.x;
    size_t i0 = (size_t)row*DM + tid, i1 = i0 + 256;
    float v0 = part[i0] + part[(size_t)MM*DM + i0] + bo[tid]     + x[i0];
    float v1 = part[i1] + part[(size_t)MM*DM + i1] + bo[tid+256] + x[i1];
    x2o[i0] = v0; x2o[i1] = v1;
    float s = v0+v1, s2 = v0*v0+v1*v1;
#pragma unroll
    for (int off=16; off; off>>=1){
        s  += __shfl_xor_sync(0xffffffffu, s,  off);
        s2 += __shfl_xor_sync(0xffffffffu, s2, off);
    }
    __shared__ float rs[8], rs2[8], mu_s, rstd_s;
    if ((tid&31)==0){ rs[tid>>5]=s; rs2[tid>>5]=s2; }
    __syncthreads();
    if (tid==0){
        float a=0.f,c=0.f;
#pragma unroll
        for (int i=0;i<8;i++){ a+=rs[i]; c+=rs2[i]; }
        float mu = a*(1.0f/DM);
        float var = c*(1.0f/DM) - mu*mu;
        mu_s = mu; rstd_s = rsqrtf(var + 1e-5f);
    }
    __syncthreads();
    float mu = mu_s, rstd = rstd_s;
    __half* orow = o2 + (size_t)row*DM;
    orow[tid]     = __float2half_rn((v0-mu)*rstd*g[tid]     + b[tid]);
    orow[tid+256] = __float2half_rn((v1-mu)*rstd*g[tid+256] + b[tid+256]);
}

// -------- fused weight transpose to fp16: all 6 weights, ONE launch ----------
__global__ __launch_bounds__(256) void wconv_all_kernel(
    const float* __restrict__ Wq, const float* __restrict__ Wk,
    const float* __restrict__ Wv, const float* __restrict__ Wo,
    const float* __restrict__ W1, const float* __restrict__ W2,
    __half* __restrict__ wqkv, __half* __restrict__ wo,
    __half* __restrict__ w1,   __half* __restrict__ w2)
{
    int bid = blockIdx.x;
    const float* W; __half* Bt;
    int Kd, Nd, nx, local;
    if (bid < 512){
        int seg = bid >> 7; local = bid & 127; nx = 16; Kd = 512; Nd = 512;
        W  = (seg==0)?Wq:(seg==1)?Wk:(seg==2)?Wv:Wo;
        Bt = (seg==0)?wqkv:(seg==1)?(wqkv+512*DM):(seg==2)?(wqkv+1024*DM):wo;
    } else if (bid < 1024){
        local = bid - 512; nx = 64; Kd = 512; Nd = 2048; W = W1; Bt = w1;
    } else {
        local = bid - 1024; nx = 16; Kd = 2048; Nd = 512; W = W2; Bt = w2;
    }
    int n0 = (local % nx)*32, k0 = (local / nx)*64;

    __shared__ float t[64][33];
    int tx = threadIdx.x, ty = threadIdx.y;
#pragma unroll
    for (int i=ty;i<64;i+=8)
        t[i][tx] = W[(size_t)(k0+i)*Nd + n0 + tx];
    __syncthreads();
#pragma unroll
    for (int i=ty;i<32;i+=8){
        __half ha = __float2half_rn(t[2*tx][i]);
        __half hb = __float2half_rn(t[2*tx+1][i]);
        size_t base = (size_t)(n0+i)*Kd + k0 + 2*tx;
        *(uint32_t*)&Bt[base] = pack2h(ha, hb);
    }
}

// ------------- mma.sync fp16 GEMM, 3-stage pipeline, 2 CTAs/SM -------------
// A[M,K], B[N,K]. gridDim.z = split-K.
// modes: 3 relu(+bias0) -> fp16 C3; 4 qkv split fp16 out; 5 raw partial -> C0+z*MM*Np
#define TM 128
#define TN 128
#define RS 72
#define ABY (TM*RS*2)
#define STGB (2*ABY)
#define NSTG 3
#define SMEM_MM (NSTG*STGB)

__global__ __launch_bounds__(256, 2) void mm_kernel(
    const __half* __restrict__ Ap, const __half* __restrict__ Bp,
    const float* __restrict__ bias0, const float* __restrict__ bias1,
    const float* __restrict__ bias2,
    float* __restrict__ C0, __half* __restrict__ H0, __half* __restrict__ H1,
    __half* __restrict__ H2, __half* __restrict__ C3,
    int Np, int Kp, int mode)
{
    extern __shared__ char smc[];
    uint32_t sb = smem_u32(smc);

    int tid = threadIdx.x;
    int lane = tid & 31, wid = tid >> 5;
    int wm = wid >> 1, wn = wid & 1;
    int g = lane >> 2, qp = lane & 3;
    int bm = blockIdx.y * TM;
    int bn = blockIdx.x * TN;
    int nch = (Kp >> 6) / (int)gridDim.z;
    int gc0 = blockIdx.z * nch;

    const char* Abase = (const char*)(Ap + (size_t)bm*Kp) + (size_t)gc0*128;
    const char* Bbase = (const char*)(Bp + (size_t)bn*Kp) + (size_t)gc0*128;
    const size_t rowb = (size_t)Kp*2;

    int lr_ = tid >> 3, lc_ = (tid & 7)*16;
    auto loadStage = [&](int c, int s){
        uint32_t da = sb + (uint32_t)s*STGB;
        uint32_t db = da + ABY;
        const char* sa = Abase + (size_t)c*128 + (size_t)lr_*rowb + lc_;
        const char* sbp= Bbase + (size_t)c*128 + (size_t)lr_*rowb + lc_;
        uint32_t so = (uint32_t)(lr_*(RS*2) + lc_);
#pragma unroll
        for (int t=0;t<4;t++){
            cp16(da + so + t*32*(RS*2), sa + (size_t)t*32*rowb);
            cp16(db + so + t*32*(RS*2), sbp + (size_t)t*32*rowb);
        }
        cp_commit();
    };

    uint32_t a_off[2], b_off[4];
#pragma unroll
    for (int mf=0; mf<2; mf++){
        int arow = wm*32 + mf*16 + (lane & 15);
        a_off[mf] = (uint32_t)(arow*(RS*2) + ((lane & 16) ? 16 : 0));
    }
#pragma unroll
    for (int p=0; p<4; p++){
        int nrow = wn*64 + p*16 + (lane & 7) + ((lane & 16) >> 1);
        b_off[p] = (uint32_t)(nrow*(RS*2) + ((lane & 8) ? 16 : 0)) + ABY;
    }

    float acc[2][8][4];
#pragma unroll
    for (int i=0;i<2;i++)
#pragma unroll
        for (int j=0;j<8;j++)
#pragma unroll
            for (int k=0;k<4;k++) acc[i][j][k]=0.f;

    loadStage(0,0); loadStage(1,1);

    int cur = 0, nxt = 2;
    for (int i=0;i<nch;i++){
        cp_wait<NSTG-2>();
        __syncthreads();
        if (i+2 < nch) loadStage(i+2, nxt);
        else cp_commit();
        uint32_t S = sb + (uint32_t)cur*STGB;
#pragma unroll
        for (int ks=0; ks<4; ks++){
            uint32_t koff = (uint32_t)(ks*32);
            uint32_t a[2][4];
            ldsm4(a[0][0],a[0][1],a[0][2],a[0][3], S + a_off[0] + koff);
            ldsm4(a[1][0],a[1][1],a[1][2],a[1][3], S + a_off[1] + koff);
            uint32_t b[8][2];
#pragma unroll
            for (int p=0; p<4; p++)
                ldsm4(b[2*p][0],b[2*p][1],b[2*p+1][0],b[2*p+1][1],
                      S + b_off[p] + koff);
#pragma unroll
            for (int mf=0; mf<2; mf++)
#pragma unroll
                for (int nf=0; nf<8; nf++)
                    mma_f16(acc[mf][nf], a[mf], b[nf]);
        }
        cur = (cur==NSTG-1) ? 0 : cur+1;
        nxt = (nxt==NSTG-1) ? 0 : nxt+1;
    }

    // ---- epilogue ----
    float* Cpart = C0 + (size_t)blockIdx.z*MM*Np;
#pragma unroll
    for (int mf=0; mf<2; mf++){
#pragma unroll
        for (int half=0; half<2; half++){
            int m = bm + wm*32 + mf*16 + g + half*8;
#pragma unroll
            for (int nf=0; nf<8; nf++){
                int n = bn + wn*64 + nf*8 + qp*2;
                float v0 = acc[mf][nf][half*2+0];
                float v1 = acc[mf][nf][half*2+1];
                if (mode==5){
                    *(float2*)&Cpart[(size_t)m*Np + n] = make_float2(v0, v1);
                } else if (mode==4){
                    int sel = n >> 9;
                    int col = n & 511;
                    const float* bs = (sel==0) ? bias0 : (sel==1) ? bias1 : bias2;
                    v0 += bs[col]; v1 += bs[col+1];
                    if (sel < 2){
                        v0 = (v0 > 0.f) ? (v0+1.f) : expf(v0);
                        v1 = (v1 > 0.f) ? (v1+1.f) : expf(v1);
                    }
                    __half* Hs = (sel==0) ? H0 : (sel==1) ? H1 : H2;
                    *(uint32_t*)&Hs[(size_t)m*512 + col] =
                        pack2h(__float2half_rn(v0), __float2half_rn(v1));
                } else { // mode 3: relu -> fp16
                    v0 = fmaxf(v0 + bias0[n],   0.f);
                    v1 = fmaxf(v1 + bias0[n+1], 0.f);
                    *(uint32_t*)&C3[(size_t)m*Np + n] =
                        pack2h(__float2half_rn(v0), __float2half_rn(v1));
                }
            }
        }
    }
}

// ------- split-K combine: out = p0 + p1 + bias + res  (N fixed at DM=512) -------
__global__ __launch_bounds__(256) void combine_kernel(
    const float* __restrict__ part, const float* __restrict__ bias,
    const float* __restrict__ res, float* __restrict__ outp)
{
    int idx = (blockIdx.x*256 + threadIdx.x)*4;
    int n = idx & (DM-1);
    float4 p0 = *(const float4*)&part[idx];
    float4 p1 = *(const float4*)&part[MM*DM + idx];
    float4 bv = *(const float4*)&bias[n];
    float4 rv = *(const float4*)&res[idx];
    float4 o;
    o.x = p0.x+p1.x+bv.x+rv.x;
    o.y = p0.y+p1.y+bv.y+rv.y;
    o.z = p0.z+p1.z+bv.z+rv.z;
    o.w = p0.w+p1.w+bv.w+rv.w;
    *(float4*)&outp[idx] = o;
}

// ---------------- per-chunk K^T V and K sums (fp16 inputs) ----------------
__global__ __launch_bounds__(256) void chunk_sums_kernel(
    const __half* __restrict__ Kf, const __half* __restrict__ Vf,
    float* __restrict__ ckv, float* __restrict__ cz)
{
    __shared__ float Ks[CHK*DH];
    __shared__ float Vs[CHK*DH];
    int blk = blockIdx.x;
    int c = blk % NC, bh = blk / NC;
    int b = bh / NH, h = bh % NH;
    int t0 = c*CHK;
    int tid = threadIdx.x;
    int lr = tid >> 4;
    int lc = (tid & 15) * 4;
    for (int r = lr; r < CHK; r += 16){
        size_t gi = ((size_t)(b*TT + t0 + r))*DM + h*DH + lc;
        *(float4*)&Ks[r*DH+lc] = h4_to_f4(*(const uint2*)(Kf+gi));
        *(float4*)&Vs[r*DH+lc] = h4_to_f4(*(const uint2*)(Vf+gi));
    }
    __syncthreads();
    int ti = (tid>>4)*4, tj = (tid&15)*4;
    float acc[4][4];
#pragma unroll
    for (int i=0;i<4;i++)
#pragma unroll
        for (int j=0;j<4;j++) acc[i][j]=0.f;
    for (int t=0;t<CHK;t++){
        float4 kv = *(const float4*)&Ks[t*DH+ti];
        float4 vv = *(const float4*)&Vs[t*DH+tj];
        float kk[4]={kv.x,kv.y,kv.z,kv.w}, vf[4]={vv.x,vv.y,vv.z,vv.w};
#pragma unroll
        for (int i=0;i<4;i++)
#pragma unroll
            for (int j=0;j<4;j++) acc[i][j] += kk[i]*vf[j];
    }
    float* outp = ckv + (size_t)blk*DH*DH;
#pragma unroll
    for (int i=0;i<4;i++)
        *(float4*)&outp[(ti+i)*DH + tj] =
            make_float4(acc[i][0],acc[i][1],acc[i][2],acc[i][3]);
    if (tid < DH){
        float zsum = 0.f;
        for (int t=0;t<CHK;t++) zsum += Ks[t*DH+tid];
        cz[(size_t)blk*DH + tid] = zsum;
    }
}

// --------- parallel exclusive scan over chunk states ---------
__global__ __launch_bounds__(256) void scan_kernel(
    const float* __restrict__ ckv, const float* __restrict__ cz,
    float* __restrict__ Sp, float* __restrict__ zp)
{
    int bh = blockIdx.x >> 4;
    int e  = ((blockIdx.x & 15) << 8) + threadIdx.x;
    size_t base = ((size_t)bh*NC)*(DH*DH) + e;
    float v[NC];
#pragma unroll
    for (int c=0;c<NC;c++) v[c] = ckv[base + (size_t)c*(DH*DH)];
    float s = 0.f;
#pragma unroll
    for (int c=0;c<NC;c++){ Sp[base + (size_t)c*(DH*DH)] = s; s += v[c]; }

    if ((blockIdx.x & 15)==0 && threadIdx.x < DH){
        size_t zb = (size_t)bh*NC*DH + threadIdx.x;
        float zv[NC];
#pragma unroll
        for (int c=0;c<NC;c++) zv[c] = cz[zb + (size_t)c*DH];
        float z = 0.f;
#pragma unroll
        for (int c=0;c<NC;c++){ zp[zb + (size_t)c*DH] = z; z += zv[c]; }
    }
}

// ---------- intra-chunk attention (fp16 q/k/v) -> fp16 out ----------
__global__ __launch_bounds__(256) void intra_kernel(
    const __half* __restrict__ Qf, const __half* __restrict__ Kf,
    const __half* __restrict__ Vf, const float* __restrict__ Sp,
    const float* __restrict__ zp, __half* __restrict__ attn1)
{
    extern __shared__ float smf[];
    float* Qt = smf;
    float* Kt = Qt + 64*STR;
    float* Vs = Kt + 64*STR;
    float* Ss = Vs + 64*STR;
    float* At = Ss + 64*STR;
    float* zs = At + 64*STR;
    float* dn = zs + 64;

    int blk = blockIdx.x;
    int c = blk % NC, bh = blk / NC;
    int b = bh / NH, h = bh % NH;
    int t0 = c*CHK;
    int tid = threadIdx.x;
    int lr = tid >> 4;
    int lc = (tid & 15) * 4;

    for (int r = lr; r < 64; r += 16){
        size_t gi = ((size_t)(b*TT + t0 + r))*DM + h*DH + lc;
        float4 q = h4_to_f4(*(const uint2*)(Qf+gi));
        float4 k = h4_to_f4(*(const uint2*)(Kf+gi));
        float4 v = h4_to_f4(*(const uint2*)(Vf+gi));
        Qt[(lc+0)*STR+r]=q.x; Qt[(lc+1)*STR+r]=q.y; Qt[(lc+2)*STR+r]=q.z; Qt[(lc+3)*STR+r]=q.w;
        Kt[(lc+0)*STR+r]=k.x; Kt[(lc+1)*STR+r]=k.y; Kt[(lc+2)*STR+r]=k.z; Kt[(lc+3)*STR+r]=k.w;
        *(float4*)&Vs[r*STR+lc] = v;
    }
    {
        size_t base = (size_t)blk*(DH*DH);
        for (int e = tid*4; e < DH*DH; e += 1024){
            float4 sv = *(const float4*)(Sp + base + e);
            int d = e >> 6, m = e & 63;
            *(float4*)&Ss[d*STR+m] = sv;
        }
    }
    if (tid < DH) zs[tid] = zp[(size_t)blk*DH + tid];
    __syncthreads();

    int ti = (tid>>4)*4;
    int tj = (tid&15)*4;

    float a[4][4];
#pragma unroll
    for (int i=0;i<4;i++)
#pragma unroll
        for (int j=0;j<4;j++) a[i][j]=0.f;
    for (int d=0; d<64; d++){
        float4 qv = *(const float4*)&Qt[d*STR+ti];
        float4 kv = *(const float4*)&Kt[d*STR+tj];
        float qq[4]={qv.x,qv.y,qv.z,qv.w}, kk[4]={kv.x,kv.y,kv.z,kv.w};
#pragma unroll
        for (int i=0;i<4;i++)
#pragma unroll
            for (int j=0;j<4;j++) a[i][j] += qq[i]*kk[j];
    }
#pragma unroll
    for (int i=0;i<4;i++)
#pragma unroll
        for (int j=0;j<4;j++)
            At[(tj+j)*STR + (ti+i)] = ((tj+j) <= (ti+i)) ? a[i][j] : 0.f;
    __syncthreads();

    if (tid < 64){
        int t = tid;
        float dsum = 0.f;
        for (int j=0;j<64;j++) dsum += At[j*STR + t];
        for (int d=0;d<64;d++) dsum += Qt[d*STR + t]*zs[d];
        dn[t] = fmaxf(dsum, 1e-6f);
    }
    __syncthreads();

    float nacc[4][4];
#pragma unroll
    for (int i=0;i<4;i++)
#pragma unroll
        for (int j=0;j<4;j++) nacc[i][j]=0.f;
    for (int j=0;j<64;j++){
        float4 av = *(const float4*)&At[j*STR+ti];
        float4 vv = *(const float4*)&Vs[j*STR+tj];
        float af[4]={av.x,av.y,av.z,av.w}, vf[4]={vv.x,vv.y,vv.z,vv.w};
#pragma unroll
        for (int i=0;i<4;i++)
#pragma unroll
            for (int m=0;m<4;m++) nacc[i][m] += af[i]*vf[m];
    }
    for (int d=0;d<64;d++){
        float4 qv = *(const float4*)&Qt[d*STR+ti];
        float4 sv = *(const float4*)&Ss[d*STR+tj];
        float qq[4]={qv.x,qv.y,qv.z,qv.w}, sf[4]={sv.x,sv.y,sv.z,sv.w};
#pragma unroll
        for (int i=0;i<4;i++)
#pragma unroll
            for (int m=0;m<4;m++) nacc[i][m] += qq[i]*sf[m];
    }
#pragma unroll
    for (int i=0;i<4;i++){
        float inv = 1.0f / dn[ti+i];
        size_t gm = (size_t)(b*TT + t0 + ti + i);
        __half* p = attn1 + gm*DM + h*DH + tj;
        uint32_t w0 = pack2h(__float2half_rn(nacc[i][0]*inv),
                             __float2half_rn(nacc[i][1]*inv));
        uint32_t w1 = pack2h(__float2half_rn(nacc[i][2]*inv),
                             __float2half_rn(nacc[i][3]*inv));
        *(uint2*)p = make_uint2(w0, w1);
    }
}

// ---------------- launch ----------------
#define SMEM_INTRA ((5*64*STR + 128) * sizeof(float))

extern "C" void kernel_launch(void* const* d_in, const int* in_sizes, int n_in,
                              void* d_out, int out_size)
{
    (void)in_sizes; (void)n_in; (void)out_size;
    const float* x     = (const float*)d_in[0];
    const float* ln1_g = (const float*)d_in[1];
    const float* ln1_b = (const float*)d_in[2];
    const float* Wq    = (const float*)d_in[3];
    const float* bq    = (const float*)d_in[4];
    const float* Wk    = (const float*)d_in[5];
    const float* bk    = (const float*)d_in[6];
    const float* Wv    = (const float*)d_in[7];
    const float* bv    = (const float*)d_in[8];
    const float* Wo    = (const float*)d_in[9];
    const float* bo    = (const float*)d_in[10];
    const float* ln2_g = (const float*)d_in[11];
    const float* ln2_b = (const float*)d_in[12];
    const float* W1    = (const float*)d_in[13];
    const float* b1    = (const float*)d_in[14];
    const float* W2    = (const float*)d_in[15];
    const float* b2    = (const float*)d_in[16];
    float* out = (float*)d_out;

    static bool attr_done = false;
    if (!attr_done){
        cudaFuncSetAttribute(intra_kernel, cudaFuncAttributeMaxDynamicSharedMemorySize,
                             (int)SMEM_INTRA);
        cudaFuncSetAttribute(mm_kernel, cudaFuncAttributeMaxDynamicSharedMemorySize,
                             SMEM_MM);
        attr_done = true;
    }

    __half *h1b,*attn1b,*h22b,*ffn1b,*wqkvb,*wob,*w1b,*w2b,*qb,*kb,*vb;
    float *x2b,*partb,*ckvb,*czb,*Spb,*zpb;
    cudaGetSymbolAddress((void**)&h1b,   g_h1);
    cudaGetSymbolAddress((void**)&qb,    g_q);
    cudaGetSymbolAddress((void**)&kb,    g_k);
    cudaGetSymbolAddress((void**)&vb,    g_v);
    cudaGetSymbolAddress((void**)&attn1b,g_attn1);
    cudaGetSymbolAddress((void**)&x2b,   g_x2);
    cudaGetSymbolAddress((void**)&h22b,  g_h22);
    cudaGetSymbolAddress((void**)&ffn1b, g_ffn1);
    cudaGetSymbolAddress((void**)&partb, g_part);
    cudaGetSymbolAddress((void**)&wqkvb, g_wqkv);
    cudaGetSymbolAddress((void**)&wob,   g_wo);
    cudaGetSymbolAddress((void**)&w1b,   g_w1);
    cudaGetSymbolAddress((void**)&w2b,   g_w2);
    cudaGetSymbolAddress((void**)&ckvb,  g_ckv);
    cudaGetSymbolAddress((void**)&czb,   g_cz);
    cudaGetSymbolAddress((void**)&Spb,   g_Sp);
    cudaGetSymbolAddress((void**)&zpb,   g_zp);

    dim3 wcb(32,8);
    wconv_all_kernel<<<1536, wcb>>>(Wq, Wk, Wv, Wo, W1, W2,
                                    wqkvb, wob, w1b, w2b);

    dim3 gQKV(3*DM/TN, MM/TM);      // (12, 32)
    dim3 gFF(DFF/TN, MM/TM);        // (16, 32)
    dim3 gDMz(DM/TN, MM/TM, 2);     // (4, 32, 2) split-K=2
    const int CMB = (MM*DM/4)/256;

    // sublayer 1
    ln1h_kernel<<<MM, 256>>>(x, ln1_g, ln1_b, h1b);
    mm_kernel<<<gQKV, 256, SMEM_MM>>>(h1b, wqkvb, bq, bk, bv,
                                      nullptr, qb, kb, vb, nullptr,
                                      DM, DM, 4);
    chunk_sums_kernel<<<BH*NC, 256>>>(kb, vb, ckvb, czb);
    scan_kernel<<<BH*16, 256>>>(ckvb, czb, Spb, zpb);
    intra_kernel<<<BH*NC, 256, SMEM_INTRA>>>(qb, kb, vb, Spb, zpb, attn1b);
    mm_kernel<<<gDMz, 256, SMEM_MM>>>(attn1b, wob, nullptr, nullptr, nullptr,
                                      partb, nullptr, nullptr, nullptr, nullptr,
                                      DM, DM, 5);
    ln2f_kernel<<<MM, 256>>>(partb, bo, x, ln2_g, ln2_b, x2b, h22b);

    // sublayer 2
    mm_kernel<<<gFF, 256, SMEM_MM>>>(h22b, w1b, b1, nullptr, nullptr,
                                     nullptr, nullptr, nullptr, nullptr, ffn1b,
                                     DFF, DM, 3);
    mm_kernel<<<gDMz, 256, SMEM_MM>>>(ffn1b, w2b, nullptr, nullptr, nullptr,
                                      partb, nullptr, nullptr, nullptr, nullptr,
                                      DM, DFF, 5);
    combine_kernel<<<CMB, 256>>>(partb, b2, x2b, out);
}

// round 12
// speedup vs baseline: 2.3414x; 1.1227x over previous
#include <cuda_runtime.h>
#include <cuda_fp16.h>
#include <math.h>
#include <stdint.h>

// ---------------- problem constants ----------------
#define BB   2
#define TT   2048
#define DM   512
#define NH   8
#define DH   64
#define DFF  2048
#define MM   (BB*TT)        // 4096 rows
#define CHK  64
#define NC   (TT/CHK)       // 32
#define BH   (BB*NH)        // 16
#define HRS  72             // fp16 smem row stride (elements)

// ---------------- scratch (device globals) ----------------
__device__ __align__(256) __half g_h1   [MM*DM];
__device__ __align__(256) __half g_q    [MM*DM];
__device__ __align__(256) __half g_k    [MM*DM];
__device__ __align__(256) __half g_v    [MM*DM];
__device__ __align__(256) __half g_attn1[MM*DM];
__device__ __align__(256) float  g_x2   [MM*DM];
__device__ __align__(256) __half g_h22  [MM*DM];
__device__ __align__(256) __half g_ffn1 [MM*DFF];
__device__ __align__(256) float  g_part [2*MM*DM];
__device__ __align__(256) __half g_wqkv [3*DM*DM];
__device__ __align__(256) __half g_wo   [DM*DM];
__device__ __align__(256) __half g_w1   [DFF*DM];
__device__ __align__(256) __half g_w2   [DM*DFF];
__device__ __align__(256) float g_ckv[BH*NC*DH*DH];
__device__ __align__(256) float g_cz [BH*NC*DH];
__device__ __align__(256) float g_Sp [BH*NC*DH*DH];
__device__ __align__(256) float g_zp [BH*NC*DH];

// ---------------- helpers ----------------
__device__ __forceinline__ uint32_t smem_u32(const void* p){
    uint32_t a;
    asm("{ .reg .u64 t; cvta.to.shared.u64 t, %1; cvt.u32.u64 %0, t; }"
        : "=r"(a) : "l"(p));
    return a;
}
__device__ __forceinline__ void cp16(uint32_t dst, const void* src){
    asm volatile("cp.async.cg.shared.global [%0], [%1], 16;" :: "r"(dst), "l"(src));
}
__device__ __forceinline__ void cp_commit(){
    asm volatile("cp.async.commit_group;");
}
template<int N> __device__ __forceinline__ void cp_wait(){
    asm volatile("cp.async.wait_group %0;" :: "n"(N));
}
__device__ __forceinline__ void mma_f16(float* d, const uint32_t* a, const uint32_t* b){
    asm volatile(
        "mma.sync.aligned.m16n8k16.row.col.f32.f16.f16.f32 "
        "{%0,%1,%2,%3}, {%4,%5,%6,%7}, {%8,%9}, {%0,%1,%2,%3};"
        : "+f"(d[0]), "+f"(d[1]), "+f"(d[2]), "+f"(d[3])
        : "r"(a[0]), "r"(a[1]), "r"(a[2]), "r"(a[3]), "r"(b[0]), "r"(b[1]));
}
__device__ __forceinline__ void ldsm4(uint32_t& r0, uint32_t& r1, uint32_t& r2,
                                      uint32_t& r3, uint32_t addr){
    asm volatile("ldmatrix.sync.aligned.m8n8.x4.shared.b16 {%0,%1,%2,%3}, [%4];"
                 : "=r"(r0), "=r"(r1), "=r"(r2), "=r"(r3) : "r"(addr));
}
__device__ __forceinline__ uint32_t pack2h(__half a, __half b){
    return ((uint32_t)__half_as_ushort(b) << 16) | __half_as_ushort(a);
}

// ---------------- layernorm 1 -> fp16 ----------------
__global__ __launch_bounds__(256) void ln1h_kernel(
    const float* __restrict__ x, const float* __restrict__ g,
    const float* __restrict__ b, __half* __restrict__ o)
{
    int row = blockIdx.x;
    const float* xr = x + (size_t)row*DM;
    int tid = threadIdx.x;
    float v0 = xr[tid], v1 = xr[tid+256];
    float s = v0+v1, s2 = v0*v0+v1*v1;
#pragma unroll
    for (int off=16; off; off>>=1){
        s  += __shfl_xor_sync(0xffffffffu, s,  off);
        s2 += __shfl_xor_sync(0xffffffffu, s2, off);
    }
    __shared__ float rs[8], rs2[8], mu_s, rstd_s;
    if ((tid&31)==0){ rs[tid>>5]=s; rs2[tid>>5]=s2; }
    __syncthreads();
    if (tid==0){
        float a=0.f,c=0.f;
#pragma unroll
        for (int i=0;i<8;i++){ a+=rs[i]; c+=rs2[i]; }
        float mu = a*(1.0f/DM);
        float var = c*(1.0f/DM) - mu*mu;
        mu_s = mu; rstd_s = rsqrtf(var + 1e-5f);
    }
    __syncthreads();
    float mu = mu_s, rstd = rstd_s;
    __half* orow = o + (size_t)row*DM;
    orow[tid]     = __float2half_rn((v0-mu)*rstd*g[tid]     + b[tid]);
    orow[tid+256] = __float2half_rn((v1-mu)*rstd*g[tid+256] + b[tid+256]);
}

// ------- fused: x2 = p0+p1+bo+x ; LN2(x2) -> fp16 ; also writes x2 -------
__global__ __launch_bounds__(256) void ln2f_kernel(
    const float* __restrict__ part, const float* __restrict__ bo,
    const float* __restrict__ x, const float* __restrict__ g,
    const float* __restrict__ b, float* __restrict__ x2o,
    __half* __restrict__ o2)
{
    int row = blockIdx.x;
    int tid = threadIdx.x;
    size_t i0 = (size_t)row*DM + tid, i1 = i0 + 256;
    float v0 = part[i0] + part[(size_t)MM*DM + i0] + bo[tid]     + x[i0];
    float v1 = part[i1] + part[(size_t)MM*DM + i1] + bo[tid+256] + x[i1];
    x2o[i0] = v0; x2o[i1] = v1;
    float s = v0+v1, s2 = v0*v0+v1*v1;
#pragma unroll
    for (int off=16; off; off>>=1){
        s  += __shfl_xor_sync(0xffffffffu, s,  off);
        s2 += __shfl_xor_sync(0xffffffffu, s2, off);
    }
    __shared__ float rs[8], rs2[8], mu_s, rstd_s;
    if ((tid&31)==0){ rs[tid>>5]=s; rs2[tid>>5]=s2; }
    __syncthreads();
    if (tid==0){
        float a=0.f,c=0.f;
#pragma unroll
        for (int i=0;i<8;i++){ a+=rs[i]; c+=rs2[i]; }
        float mu = a*(1.0f/DM);
        float var = c*(1.0f/DM) - mu*mu;
        mu_s = mu; rstd_s = rsqrtf(var + 1e-5f);
    }
    __syncthreads();
    float mu = mu_s, rstd = rstd_s;
    __half* orow = o2 + (size_t)row*DM;
    orow[tid]     = __float2half_rn((v0-mu)*rstd*g[tid]     + b[tid]);
    orow[tid+256] = __float2half_rn((v1-mu)*rstd*g[tid+256] + b[tid+256]);
}

// -------- fused weight transpose to fp16: all 6 weights, ONE launch ----------
__global__ __launch_bounds__(256) void wconv_all_kernel(
    const float* __restrict__ Wq, const float* __restrict__ Wk,
    const float* __restrict__ Wv, const float* __restrict__ Wo,
    const float* __restrict__ W1, const float* __restrict__ W2,
    __half* __restrict__ wqkv, __half* __restrict__ wo,
    __half* __restrict__ w1,   __half* __restrict__ w2)
{
    int bid = blockIdx.x;
    const float* W; __half* Bt;
    int Kd, Nd, nx, local;
    if (bid < 512){
        int seg = bid >> 7; local = bid & 127; nx = 16; Kd = 512; Nd = 512;
        W  = (seg==0)?Wq:(seg==1)?Wk:(seg==2)?Wv:Wo;
        Bt = (seg==0)?wqkv:(seg==1)?(wqkv+512*DM):(seg==2)?(wqkv+1024*DM):wo;
    } else if (bid < 1024){
        local = bid - 512; nx = 64; Kd = 512; Nd = 2048; W = W1; Bt = w1;
    } else {
        local = bid - 1024; nx = 16; Kd = 2048; Nd = 512; W = W2; Bt = w2;
    }
    int n0 = (local % nx)*32, k0 = (local / nx)*64;

    __shared__ float t[64][33];
    int tx = threadIdx.x, ty = threadIdx.y;
#pragma unroll
    for (int i=ty;i<64;i+=8)
        t[i][tx] = W[(size_t)(k0+i)*Nd + n0 + tx];
    __syncthreads();
#pragma unroll
    for (int i=ty;i<32;i+=8){
        __half ha = __float2half_rn(t[2*tx][i]);
        __half hb = __float2half_rn(t[2*tx+1][i]);
        size_t base = (size_t)(n0+i)*Kd + k0 + 2*tx;
        *(uint32_t*)&Bt[base] = pack2h(ha, hb);
    }
}

// ------------- mma.sync fp16 GEMM, 3-stage pipeline, 2 CTAs/SM -------------
#define TM 128
#define TN 128
#define RS 72
#define ABY (TM*RS*2)
#define STGB (2*ABY)
#define NSTG 3
#define SMEM_MM (NSTG*STGB)

__global__ __launch_bounds__(256, 2) void mm_kernel(
    const __half* __restrict__ Ap, const __half* __restrict__ Bp,
    const float* __restrict__ bias0, const float* __restrict__ bias1,
    const float* __restrict__ bias2,
    float* __restrict__ C0, __half* __restrict__ H0, __half* __restrict__ H1,
    __half* __restrict__ H2, __half* __restrict__ C3,
    int Np, int Kp, int mode)
{
    extern __shared__ char smc[];
    uint32_t sb = smem_u32(smc);

    int tid = threadIdx.x;
    int lane = tid & 31, wid = tid >> 5;
    int wm = wid >> 1, wn = wid & 1;
    int g = lane >> 2, qp = lane & 3;
    int bm = blockIdx.y * TM;
    int bn = blockIdx.x * TN;
    int nch = (Kp >> 6) / (int)gridDim.z;
    int gc0 = blockIdx.z * nch;

    const char* Abase = (const char*)(Ap + (size_t)bm*Kp) + (size_t)gc0*128;
    const char* Bbase = (const char*)(Bp + (size_t)bn*Kp) + (size_t)gc0*128;
    const size_t rowb = (size_t)Kp*2;

    int lr_ = tid >> 3, lc_ = (tid & 7)*16;
    auto loadStage = [&](int c, int s){
        uint32_t da = sb + (uint32_t)s*STGB;
        uint32_t db = da + ABY;
        const char* sa = Abase + (size_t)c*128 + (size_t)lr_*rowb + lc_;
        const char* sbp= Bbase + (size_t)c*128 + (size_t)lr_*rowb + lc_;
        uint32_t so = (uint32_t)(lr_*(RS*2) + lc_);
#pragma unroll
        for (int t=0;t<4;t++){
            cp16(da + so + t*32*(RS*2), sa + (size_t)t*32*rowb);
            cp16(db + so + t*32*(RS*2), sbp + (size_t)t*32*rowb);
        }
        cp_commit();
    };

    uint32_t a_off[2], b_off[4];
#pragma unroll
    for (int mf=0; mf<2; mf++){
        int arow = wm*32 + mf*16 + (lane & 15);
        a_off[mf] = (uint32_t)(arow*(RS*2) + ((lane & 16) ? 16 : 0));
    }
#pragma unroll
    for (int p=0; p<4; p++){
        int nrow = wn*64 + p*16 + (lane & 7) + ((lane & 16) >> 1);
        b_off[p] = (uint32_t)(nrow*(RS*2) + ((lane & 8) ? 16 : 0)) + ABY;
    }

    float acc[2][8][4];
#pragma unroll
    for (int i=0;i<2;i++)
#pragma unroll
        for (int j=0;j<8;j++)
#pragma unroll
            for (int k=0;k<4;k++) acc[i][j][k]=0.f;

    loadStage(0,0); loadStage(1,1);

    int cur = 0, nxt = 2;
    for (int i=0;i<nch;i++){
        cp_wait<NSTG-2>();
        __syncthreads();
        if (i+2 < nch) loadStage(i+2, nxt);
        else cp_commit();
        uint32_t S = sb + (uint32_t)cur*STGB;
#pragma unroll
        for (int ks=0; ks<4; ks++){
            uint32_t koff = (uint32_t)(ks*32);
            uint32_t a[2][4];
            ldsm4(a[0][0],a[0][1],a[0][2],a[0][3], S + a_off[0] + koff);
            ldsm4(a[1][0],a[1][1],a[1][2],a[1][3], S + a_off[1] + koff);
            uint32_t b[8][2];
#pragma unroll
            for (int p=0; p<4; p++)
                ldsm4(b[2*p][0],b[2*p][1],b[2*p+1][0],b[2*p+1][1],
                      S + b_off[p] + koff);
#pragma unroll
            for (int mf=0; mf<2; mf++)
#pragma unroll
                for (int nf=0; nf<8; nf++)
                    mma_f16(acc[mf][nf], a[mf], b[nf]);
        }
        cur = (cur==NSTG-1) ? 0 : cur+1;
        nxt = (nxt==NSTG-1) ? 0 : nxt+1;
    }

    float* Cpart = C0 + (size_t)blockIdx.z*MM*Np;
#pragma unroll
    for (int mf=0; mf<2; mf++){
#pragma unroll
        for (int half=0; half<2; half++){
            int m = bm + wm*32 + mf*16 + g + half*8;
#pragma unroll
            for (int nf=0; nf<8; nf++){
                int n = bn + wn*64 + nf*8 + qp*2;
                float v0 = acc[mf][nf][half*2+0];
                float v1 = acc[mf][nf][half*2+1];
                if (mode==5){
                    *(float2*)&Cpart[(size_t)m*Np + n] = make_float2(v0, v1);
                } else if (mode==4){
                    int sel = n >> 9;
                    int col = n & 511;
                    const float* bs = (sel==0) ? bias0 : (sel==1) ? bias1 : bias2;
                    v0 += bs[col]; v1 += bs[col+1];
                    if (sel < 2){
                        v0 = (v0 > 0.f) ? (v0+1.f) : expf(v0);
                        v1 = (v1 > 0.f) ? (v1+1.f) : expf(v1);
                    }
                    __half* Hs = (sel==0) ? H0 : (sel==1) ? H1 : H2;
                    *(uint32_t*)&Hs[(size_t)m*512 + col] =
                        pack2h(__float2half_rn(v0), __float2half_rn(v1));
                } else { // mode 3: relu -> fp16
                    v0 = fmaxf(v0 + bias0[n],   0.f);
                    v1 = fmaxf(v1 + bias0[n+1], 0.f);
                    *(uint32_t*)&C3[(size_t)m*Np + n] =
                        pack2h(__float2half_rn(v0), __float2half_rn(v1));
                }
            }
        }
    }
}

// ------- split-K combine: out = p0 + p1 + bias + res -------
__global__ __launch_bounds__(256) void combine_kernel(
    const float* __restrict__ part, const float* __restrict__ bias,
    const float* __restrict__ res, float* __restrict__ outp)
{
    int idx = (blockIdx.x*256 + threadIdx.x)*4;
    int n = idx & (DM-1);
    float4 p0 = *(const float4*)&part[idx];
    float4 p1 = *(const float4*)&part[MM*DM + idx];
    float4 bv = *(const float4*)&bias[n];
    float4 rv = *(const float4*)&res[idx];
    float4 o;
    o.x = p0.x+p1.x+bv.x+rv.x;
    o.y = p0.y+p1.y+bv.y+rv.y;
    o.z = p0.z+p1.z+bv.z+rv.z;
    o.w = p0.w+p1.w+bv.w+rv.w;
    *(float4*)&outp[idx] = o;
}

// ---------- per-chunk K^T V and K sums via tensor cores ----------
// C[d][m] = sum_t K[t][d] V[t][m].  Kt[d][t], Vt[m][t] fp16 smem.
__global__ __launch_bounds__(256, 2) void chunk_sums_kernel(
    const __half* __restrict__ Kf, const __half* __restrict__ Vf,
    float* __restrict__ ckv, float* __restrict__ cz)
{
    __shared__ __half Kt[64*HRS];
    __shared__ __half Vt[64*HRS];
    int blk = blockIdx.x;
    int c = blk % NC, bh = blk / NC;
    int b = bh / NH, h = bh % NH;
    int t0 = c*CHK;
    int tid = threadIdx.x;
    int lr = tid >> 4, lc = (tid & 15)*4;
    for (int r = lr; r < 64; r += 16){
        size_t gi = ((size_t)(b*TT + t0 + r))*DM + h*DH + lc;
        uint2 kv = *(const uint2*)(Kf+gi);
        uint2 vv = *(const uint2*)(Vf+gi);
        const __half* kp = (const __half*)&kv;
        const __half* vp = (const __half*)&vv;
#pragma unroll
        for (int i=0;i<4;i++){
            Kt[(lc+i)*HRS + r] = kp[i];
            Vt[(lc+i)*HRS + r] = vp[i];
        }
    }
    __syncthreads();

    int lane = tid & 31, wid = tid >> 5;
    int mr = (wid & 3)*16, nb = (wid >> 2)*32;
    int g = lane >> 2, qp = lane & 3;
    uint32_t sbK = smem_u32(Kt), sbV = smem_u32(Vt);
    uint32_t aoff = sbK + (uint32_t)((mr + (lane & 15))*(HRS*2) + ((lane & 16) ? 16 : 0));
    uint32_t boff[2];
#pragma unroll
    for (int p=0;p<2;p++){
        int nrow = nb + p*16 + (lane & 7) + ((lane & 16) >> 1);
        boff[p] = sbV + (uint32_t)(nrow*(HRS*2) + ((lane & 8) ? 16 : 0));
    }
    float acc[4][4];
#pragma unroll
    for (int i=0;i<4;i++)
#pragma unroll
        for (int j=0;j<4;j++) acc[i][j]=0.f;
#pragma unroll
    for (int ks=0; ks<4; ks++){
        uint32_t koff = (uint32_t)(ks*32);
        uint32_t a[4];
        ldsm4(a[0],a[1],a[2],a[3], aoff + koff);
        uint32_t bfr[4][2];
#pragma unroll
        for (int p=0;p<2;p++)
            ldsm4(bfr[2*p][0],bfr[2*p][1],bfr[2*p+1][0],bfr[2*p+1][1],
                  boff[p] + koff);
#pragma unroll
        for (int nf=0;nf<4;nf++) mma_f16(acc[nf], a, bfr[nf]);
    }
    float* outp = ckv + (size_t)blk*DH*DH;
#pragma unroll
    for (int nf=0;nf<4;nf++){
        int m = nb + nf*8 + qp*2;
        *(float2*)&outp[(mr+g)*DH + m]   = make_float2(acc[nf][0], acc[nf][1]);
        *(float2*)&outp[(mr+g+8)*DH + m] = make_float2(acc[nf][2], acc[nf][3]);
    }
    if (tid < DH){
        float z = 0.f;
#pragma unroll 8
        for (int t=0;t<64;t++) z += __half2float(Kt[tid*HRS + t]);
        cz[(size_t)blk*DH + tid] = z;
    }
}

// --------- parallel exclusive scan over chunk states ---------
__global__ __launch_bounds__(256) void scan_kernel(
    const float* __restrict__ ckv, const float* __restrict__ cz,
    float* __restrict__ Sp, float* __restrict__ zp)
{
    int bh = blockIdx.x >> 4;
    int e  = ((blockIdx.x & 15) << 8) + threadIdx.x;
    size_t base = ((size_t)bh*NC)*(DH*DH) + e;
    float v[NC];
#pragma unroll
    for (int c=0;c<NC;c++) v[c] = ckv[base + (size_t)c*(DH*DH)];
    float s = 0.f;
#pragma unroll
    for (int c=0;c<NC;c++){ Sp[base + (size_t)c*(DH*DH)] = s; s += v[c]; }

    if ((blockIdx.x & 15)==0 && threadIdx.x < DH){
        size_t zb = (size_t)bh*NC*DH + threadIdx.x;
        float zv[NC];
#pragma unroll
        for (int c=0;c<NC;c++) zv[c] = cz[zb + (size_t)c*DH];
        float z = 0.f;
#pragma unroll
        for (int c=0;c<NC;c++){ zp[zb + (size_t)c*DH] = z; z += zv[c]; }
    }
}

// ---------- intra-chunk attention via tensor cores ----------
// S = mask(Q K^T); den = rowsum(S) + Q.z; num = S V + Q Sp; out = num/den
__global__ __launch_bounds__(256, 2) void intra_kernel(
    const __half* __restrict__ Qf, const __half* __restrict__ Kf,
    const __half* __restrict__ Vf, const float* __restrict__ Sp,
    const float* __restrict__ zp, __half* __restrict__ attn1)
{
    __shared__ __half Qs[64*HRS];   // [t][d]
    __shared__ __half Ks[64*HRS];   // [j][d]
    __shared__ __half Vt[64*HRS];   // [m][j]
    __shared__ __half St[64*HRS];   // [m][d]  (Sp transposed, fp16)
    __shared__ __half Ss[64*HRS];   // [t][j]  masked scores fp16
    __shared__ float zs[64], dn[64], dnp[2][64];

    int blk = blockIdx.x;
    int c = blk % NC, bh = blk / NC;
    int b = bh / NH, h = bh % NH;
    int t0 = c*CHK;
    int tid = threadIdx.x;
    int lr = tid >> 4, lc = (tid & 15)*4;

    for (int r = lr; r < 64; r += 16){
        size_t gi = ((size_t)(b*TT + t0 + r))*DM + h*DH + lc;
        uint2 q = *(const uint2*)(Qf+gi);
        uint2 k = *(const uint2*)(Kf+gi);
        uint2 v = *(const uint2*)(Vf+gi);
        *(uint2*)&Qs[r*HRS + lc] = q;
        *(uint2*)&Ks[r*HRS + lc] = k;
        const __half* vp = (const __half*)&v;
#pragma unroll
        for (int i=0;i<4;i++) Vt[(lc+i)*HRS + r] = vp[i];
    }
    {
        size_t base = (size_t)blk*(DH*DH);
        for (int e = tid*4; e < DH*DH; e += 1024){
            float4 sv = *(const float4*)(Sp + base + e);
            int d = e >> 6, m = e & 63;
            St[(m+0)*HRS + d] = __float2half_rn(sv.x);
            St[(m+1)*HRS + d] = __float2half_rn(sv.y);
            St[(m+2)*HRS + d] = __float2half_rn(sv.z);
            St[(m+3)*HRS + d] = __float2half_rn(sv.w);
        }
    }
    if (tid < DH) zs[tid] = zp[(size_t)blk*DH + tid];
    __syncthreads();

    int lane = tid & 31, wid = tid >> 5;
    int mr = (wid & 3)*16, nb = (wid >> 2)*32;
    int g = lane >> 2, qp = lane & 3;
    uint32_t sbQ = smem_u32(Qs), sbK = smem_u32(Ks);
    uint32_t sbV = smem_u32(Vt), sbSt = smem_u32(St), sbSs = smem_u32(Ss);

    uint32_t a_lane = (uint32_t)((mr + (lane & 15))*(HRS*2) + ((lane & 16) ? 16 : 0));
    uint32_t b_lane[2];
#pragma unroll
    for (int p=0;p<2;p++){
        int nrow = nb + p*16 + (lane & 7) + ((lane & 16) >> 1);
        b_lane[p] = (uint32_t)(nrow*(HRS*2) + ((lane & 8) ? 16 : 0));
    }

    // ---- GEMM1: S = Q K^T ----
    float acc[4][4];
#pragma unroll
    for (int i=0;i<4;i++)
#pragma unroll
        for (int j=0;j<4;j++) acc[i][j]=0.f;
#pragma unroll
    for (int ks=0; ks<4; ks++){
        uint32_t koff = (uint32_t)(ks*32);
        uint32_t a[4];
        ldsm4(a[0],a[1],a[2],a[3], sbQ + a_lane + koff);
        uint32_t bfr[4][2];
#pragma unroll
        for (int p=0;p<2;p++)
            ldsm4(bfr[2*p][0],bfr[2*p][1],bfr[2*p+1][0],bfr[2*p+1][1],
                  sbK + b_lane[p] + koff);
#pragma unroll
        for (int nf=0;nf<4;nf++) mma_f16(acc[nf], a, bfr[nf]);
    }

    // ---- mask, den partials, store Ss ----
    int r0 = mr + g, r1 = mr + g + 8;
    float slo = 0.f, shi = 0.f;
#pragma unroll
    for (int nf=0;nf<4;nf++){
        int col = nb + nf*8 + qp*2;
        float c0 = (col   <= r0) ? acc[nf][0] : 0.f;
        float c1 = (col+1 <= r0) ? acc[nf][1] : 0.f;
        float c2 = (col   <= r1) ? acc[nf][2] : 0.f;
        float c3 = (col+1 <= r1) ? acc[nf][3] : 0.f;
        slo += c0 + c1; shi += c2 + c3;
        *(uint32_t*)&Ss[r0*HRS + col] = pack2h(__float2half_rn(c0), __float2half_rn(c1));
        *(uint32_t*)&Ss[r1*HRS + col] = pack2h(__float2half_rn(c2), __float2half_rn(c3));
    }
    slo += __shfl_xor_sync(0xffffffffu, slo, 1);
    slo += __shfl_xor_sync(0xffffffffu, slo, 2);
    shi += __shfl_xor_sync(0xffffffffu, shi, 1);
    shi += __shfl_xor_sync(0xffffffffu, shi, 2);
    if (qp == 0){
        dnp[wid>>2][r0] = slo;
        dnp[wid>>2][r1] = shi;
    }
    __syncthreads();
    if (tid < 64){
        float dsum = dnp[0][tid] + dnp[1][tid];
#pragma unroll 8
        for (int d=0; d<64; d++)
            dsum += __half2float(Qs[tid*HRS + d]) * zs[d];
        dn[tid] = fmaxf(dsum, 1e-6f);
    }
    __syncthreads();

    // ---- GEMM2: num = Ss@Vt + Qs@St ----
    float acc2[4][4];
#pragma unroll
    for (int i=0;i<4;i++)
#pragma unroll
        for (int j=0;j<4;j++) acc2[i][j]=0.f;
#pragma unroll
    for (int ks=0; ks<4; ks++){
        uint32_t koff = (uint32_t)(ks*32);
        uint32_t a[4];
        ldsm4(a[0],a[1],a[2],a[3], sbSs + a_lane + koff);
        uint32_t bfr[4][2];
#pragma unroll
        for (int p=0;p<2;p++)
            ldsm4(bfr[2*p][0],bfr[2*p][1],bfr[2*p+1][0],bfr[2*p+1][1],
                  sbV + b_lane[p] + koff);
#pragma unroll
        for (int nf=0;nf<4;nf++) mma_f16(acc2[nf], a, bfr[nf]);
    }
#pragma unroll
    for (int ks=0; ks<4; ks++){
        uint32_t koff = (uint32_t)(ks*32);
        uint32_t a[4];
        ldsm4(a[0],a[1],a[2],a[3], sbQ + a_lane + koff);
        uint32_t bfr[4][2];
#pragma unroll
        for (int p=0;p<2;p++)
            ldsm4(bfr[2*p][0],bfr[2*p][1],bfr[2*p+1][0],bfr[2*p+1][1],
                  sbSt + b_lane[p] + koff);
#pragma unroll
        for (int nf=0;nf<4;nf++) mma_f16(acc2[nf], a, bfr[nf]);
    }

    // ---- write out ----
    float inv0 = 1.0f / dn[r0];
    float inv1 = 1.0f / dn[r1];
#pragma unroll
    for (int nf=0;nf<4;nf++){
        int col = nb + nf*8 + qp*2;
        size_t g0 = ((size_t)(b*TT + t0 + r0))*DM + h*DH + col;
        size_t g1 = ((size_t)(b*TT + t0 + r1))*DM + h*DH + col;
        *(uint32_t*)&attn1[g0] = pack2h(__float2half_rn(acc2[nf][0]*inv0),
                                        __float2half_rn(acc2[nf][1]*inv0));
        *(uint32_t*)&attn1[g1] = pack2h(__float2half_rn(acc2[nf][2]*inv1),
                                        __float2half_rn(acc2[nf][3]*inv1));
    }
}

// ---------------- launch ----------------
extern "C" void kernel_launch(void* const* d_in, const int* in_sizes, int n_in,
                              void* d_out, int out_size)
{
    (void)in_sizes; (void)n_in; (void)out_size;
    const float* x     = (const float*)d_in[0];
    const float* ln1_g = (const float*)d_in[1];
    const float* ln1_b = (const float*)d_in[2];
    const float* Wq    = (const float*)d_in[3];
    const float* bq    = (const float*)d_in[4];
    const float* Wk    = (const float*)d_in[5];
    const float* bk    = (const float*)d_in[6];
    const float* Wv    = (const float*)d_in[7];
    const float* bv    = (const float*)d_in[8];
    const float* Wo    = (const float*)d_in[9];
    const float* bo    = (const float*)d_in[10];
    const float* ln2_g = (const float*)d_in[11];
    const float* ln2_b = (const float*)d_in[12];
    const float* W1    = (const float*)d_in[13];
    const float* b1    = (const float*)d_in[14];
    const float* W2    = (const float*)d_in[15];
    const float* b2    = (const float*)d_in[16];
    float* out = (float*)d_out;

    static bool attr_done = false;
    if (!attr_done){
        cudaFuncSetAttribute(mm_kernel, cudaFuncAttributeMaxDynamicSharedMemorySize,
                             SMEM_MM);
        attr_done = true;
    }

    __half *h1b,*attn1b,*h22b,*ffn1b,*wqkvb,*wob,*w1b,*w2b,*qb,*kb,*vb;
    float *x2b,*partb,*ckvb,*czb,*Spb,*zpb;
    cudaGetSymbolAddress((void**)&h1b,   g_h1);
    cudaGetSymbolAddress((void**)&qb,    g_q);
    cudaGetSymbolAddress((void**)&kb,    g_k);
    cudaGetSymbolAddress((void**)&vb,    g_v);
    cudaGetSymbolAddress((void**)&attn1b,g_attn1);
    cudaGetSymbolAddress((void**)&x2b,   g_x2);
    cudaGetSymbolAddress((void**)&h22b,  g_h22);
    cudaGetSymbolAddress((void**)&ffn1b, g_ffn1);
    cudaGetSymbolAddress((void**)&partb, g_part);
    cudaGetSymbolAddress((void**)&wqkvb, g_wqkv);
    cudaGetSymbolAddress((void**)&wob,   g_wo);
    cudaGetSymbolAddress((void**)&w1b,   g_w1);
    cudaGetSymbolAddress((void**)&w2b,   g_w2);
    cudaGetSymbolAddress((void**)&ckvb,  g_ckv);
    cudaGetSymbolAddress((void**)&czb,   g_cz);
    cudaGetSymbolAddress((void**)&Spb,   g_Sp);
    cudaGetSymbolAddress((void**)&zpb,   g_zp);

    dim3 wcb(32,8);
    wconv_all_kernel<<<1536, wcb>>>(Wq, Wk, Wv, Wo, W1, W2,
                                    wqkvb, wob, w1b, w2b);

    dim3 gQKV(3*DM/TN, MM/TM);      // (12, 32)
    dim3 gFF(DFF/TN, MM/TM);        // (16, 32)
    dim3 gDMz(DM/TN, MM/TM, 2);     // (4, 32, 2) split-K=2
    const int CMB = (MM*DM/4)/256;

    // sublayer 1
    ln1h_kernel<<<MM, 256>>>(x, ln1_g, ln1_b, h1b);
    mm_kernel<<<gQKV, 256, SMEM_MM>>>(h1b, wqkvb, bq, bk, bv,
                                      nullptr, qb, kb, vb, nullptr,
                                      DM, DM, 4);
    chunk_sums_kernel<<<BH*NC, 256>>>(kb, vb, ckvb, czb);
    scan_kernel<<<BH*16, 256>>>(ckvb, czb, Spb, zpb);
    intra_kernel<<<BH*NC, 256>>>(qb, kb, vb, Spb, zpb, attn1b);
    mm_kernel<<<gDMz, 256, SMEM_MM>>>(attn1b, wob, nullptr, nullptr, nullptr,
                                      partb, nullptr, nullptr, nullptr, nullptr,
                                      DM, DM, 5);
    ln2f_kernel<<<MM, 256>>>(partb, bo, x, ln2_g, ln2_b, x2b, h22b);

    // sublayer 2
    mm_kernel<<<gFF, 256, SMEM_MM>>>(h22b, w1b, b1, nullptr, nullptr,
                                     nullptr, nullptr, nullptr, nullptr, ffn1b,
                                     DFF, DM, 3);
    mm_kernel<<<gDMz, 256, SMEM_MM>>>(ffn1b, w2b, nullptr, nullptr, nullptr,
                                      partb, nullptr, nullptr, nullptr, nullptr,
                                      DM, DFF, 5);
    combine_kernel<<<CMB, 256>>>(partb, b2, x2b, out);
}

// round 13
// speedup vs baseline: 2.3928x; 1.0219x over previous
#include <cuda_runtime.h>
#include <cuda_fp16.h>
#include <math.h>
#include <stdint.h>

// ---------------- problem constants ----------------
#define BB   2
#define TT   2048
#define DM   512
#define NH   8
#define DH   64
#define DFF  2048
#define MM   (BB*TT)        // 4096 rows
#define CHK  64
#define NC   (TT/CHK)       // 32
#define BH   (BB*NH)        // 16
#define HRS  72             // fp16 smem row stride (elements)

// ---------------- scratch (device globals) ----------------
__device__ __align__(256) __half g_h1   [MM*DM];
__device__ __align__(256) __half g_q    [MM*DM];
__device__ __align__(256) __half g_k    [MM*DM];
__device__ __align__(256) __half g_v    [MM*DM];
__device__ __align__(256) __half g_attn1[MM*DM];
__device__ __align__(256) float  g_x2   [MM*DM];
__device__ __align__(256) __half g_h22  [MM*DM];
__device__ __align__(256) __half g_ffn1 [MM*DFF];
__device__ __align__(256) __half g_wqkv [3*DM*DM];
__device__ __align__(256) __half g_wo   [DM*DM];
__device__ __align__(256) __half g_w1   [DFF*DM];
__device__ __align__(256) __half g_w2   [DM*DFF];
__device__ __align__(256) float g_ckv[BH*NC*DH*DH];
__device__ __align__(256) float g_cz [BH*NC*DH];
__device__ __align__(256) float g_Sp [BH*NC*DH*DH];
__device__ __align__(256) float g_zp [BH*NC*DH];

// ---------------- helpers ----------------
__device__ __forceinline__ uint32_t smem_u32(const void* p){
    uint32_t a;
    asm("{ .reg .u64 t; cvta.to.shared.u64 t, %1; cvt.u32.u64 %0, t; }"
        : "=r"(a) : "l"(p));
    return a;
}
__device__ __forceinline__ void cp16(uint32_t dst, const void* src){
    asm volatile("cp.async.cg.shared.global [%0], [%1], 16;" :: "r"(dst), "l"(src));
}
__device__ __forceinline__ void cp_commit(){
    asm volatile("cp.async.commit_group;");
}
template<int N> __device__ __forceinline__ void cp_wait(){
    asm volatile("cp.async.wait_group %0;" :: "n"(N));
}
__device__ __forceinline__ void mma_f16(float* d, const uint32_t* a, const uint32_t* b){
    asm volatile(
        "mma.sync.aligned.m16n8k16.row.col.f32.f16.f16.f32 "
        "{%0,%1,%2,%3}, {%4,%5,%6,%7}, {%8,%9}, {%0,%1,%2,%3};"
        : "+f"(d[0]), "+f"(d[1]), "+f"(d[2]), "+f"(d[3])
        : "r"(a[0]), "r"(a[1]), "r"(a[2]), "r"(a[3]), "r"(b[0]), "r"(b[1]));
}
__device__ __forceinline__ void ldsm4(uint32_t& r0, uint32_t& r1, uint32_t& r2,
                                      uint32_t& r3, uint32_t addr){
    asm volatile("ldmatrix.sync.aligned.m8n8.x4.shared.b16 {%0,%1,%2,%3}, [%4];"
                 : "=r"(r0), "=r"(r1), "=r"(r2), "=r"(r3) : "r"(addr));
}
__device__ __forceinline__ uint32_t pack2h(__half a, __half b){
    return ((uint32_t)__half_as_ushort(b) << 16) | __half_as_ushort(a);
}

// ---------------- layernorm (fp32 in) -> fp16 out ----------------
__global__ __launch_bounds__(256) void lnh_kernel(
    const float* __restrict__ x, const float* __restrict__ g,
    const float* __restrict__ b, __half* __restrict__ o)
{
    int row = blockIdx.x;
    const float* xr = x + (size_t)row*DM;
    int tid = threadIdx.x;
    float v0 = xr[tid], v1 = xr[tid+256];
    float s = v0+v1, s2 = v0*v0+v1*v1;
#pragma unroll
    for (int off=16; off; off>>=1){
        s  += __shfl_xor_sync(0xffffffffu, s,  off);
        s2 += __shfl_xor_sync(0xffffffffu, s2, off);
    }
    __shared__ float rs[8], rs2[8], mu_s, rstd_s;
    if ((tid&31)==0){ rs[tid>>5]=s; rs2[tid>>5]=s2; }
    __syncthreads();
    if (tid==0){
        float a=0.f,c=0.f;
#pragma unroll
        for (int i=0;i<8;i++){ a+=rs[i]; c+=rs2[i]; }
        float mu = a*(1.0f/DM);
        float var = c*(1.0f/DM) - mu*mu;
        mu_s = mu; rstd_s = rsqrtf(var + 1e-5f);
    }
    __syncthreads();
    float mu = mu_s, rstd = rstd_s;
    __half* orow = o + (size_t)row*DM;
    orow[tid]     = __float2half_rn((v0-mu)*rstd*g[tid]     + b[tid]);
    orow[tid+256] = __float2half_rn((v1-mu)*rstd*g[tid+256] + b[tid+256]);
}

// -------- fused weight transpose to fp16: all 6 weights, ONE launch ----------
__global__ __launch_bounds__(256) void wconv_all_kernel(
    const float* __restrict__ Wq, const float* __restrict__ Wk,
    const float* __restrict__ Wv, const float* __restrict__ Wo,
    const float* __restrict__ W1, const float* __restrict__ W2,
    __half* __restrict__ wqkv, __half* __restrict__ wo,
    __half* __restrict__ w1,   __half* __restrict__ w2)
{
    int bid = blockIdx.x;
    const float* W; __half* Bt;
    int Kd, Nd, nx, local;
    if (bid < 512){
        int seg = bid >> 7; local = bid & 127; nx = 16; Kd = 512; Nd = 512;
        W  = (seg==0)?Wq:(seg==1)?Wk:(seg==2)?Wv:Wo;
        Bt = (seg==0)?wqkv:(seg==1)?(wqkv+512*DM):(seg==2)?(wqkv+1024*DM):wo;
    } else if (bid < 1024){
        local = bid - 512; nx = 64; Kd = 512; Nd = 2048; W = W1; Bt = w1;
    } else {
        local = bid - 1024; nx = 16; Kd = 2048; Nd = 512; W = W2; Bt = w2;
    }
    int n0 = (local % nx)*32, k0 = (local / nx)*64;

    __shared__ float t[64][33];
    int tx = threadIdx.x, ty = threadIdx.y;
#pragma unroll
    for (int i=ty;i<64;i+=8)
        t[i][tx] = W[(size_t)(k0+i)*Nd + n0 + tx];
    __syncthreads();
#pragma unroll
    for (int i=ty;i<32;i+=8){
        __half ha = __float2half_rn(t[2*tx][i]);
        __half hb = __float2half_rn(t[2*tx+1][i]);
        size_t base = (size_t)(n0+i)*Kd + k0 + 2*tx;
        *(uint32_t*)&Bt[base] = pack2h(ha, hb);
    }
}

// ------------- mma.sync fp16 GEMM, 3-stage pipeline, 2 CTAs/SM -------------
// A[M,K], B[N,K].
// modes: 2 +bias0+res -> fp32 C0; 3 relu(+bias0) -> fp16 C3; 4 qkv split fp16 out
#define TM 128
#define TN 128
#define RS 72
#define ABY (TM*RS*2)
#define STGB (2*ABY)
#define NSTG 3
#define SMEM_MM (NSTG*STGB)

__global__ __launch_bounds__(256, 2) void mm_kernel(
    const __half* __restrict__ Ap, const __half* __restrict__ Bp,
    const float* __restrict__ bias0, const float* __restrict__ bias1,
    const float* __restrict__ bias2, const float* __restrict__ res,
    float* __restrict__ C0, __half* __restrict__ H0, __half* __restrict__ H1,
    __half* __restrict__ H2, __half* __restrict__ C3,
    int Np, int Kp, int mode)
{
    extern __shared__ char smc[];
    uint32_t sb = smem_u32(smc);

    int tid = threadIdx.x;
    int lane = tid & 31, wid = tid >> 5;
    int wm = wid >> 1, wn = wid & 1;
    int g = lane >> 2, qp = lane & 3;
    int bm = blockIdx.y * TM;
    int bn = blockIdx.x * TN;
    int nch = Kp >> 6;

    const char* Abase = (const char*)(Ap + (size_t)bm*Kp);
    const char* Bbase = (const char*)(Bp + (size_t)bn*Kp);
    const size_t rowb = (size_t)Kp*2;

    int lr_ = tid >> 3, lc_ = (tid & 7)*16;
    auto loadStage = [&](int c, int s){
        uint32_t da = sb + (uint32_t)s*STGB;
        uint32_t db = da + ABY;
        const char* sa = Abase + (size_t)c*128 + (size_t)lr_*rowb + lc_;
        const char* sbp= Bbase + (size_t)c*128 + (size_t)lr_*rowb + lc_;
        uint32_t so = (uint32_t)(lr_*(RS*2) + lc_);
#pragma unroll
        for (int t=0;t<4;t++){
            cp16(da + so + t*32*(RS*2), sa + (size_t)t*32*rowb);
            cp16(db + so + t*32*(RS*2), sbp + (size_t)t*32*rowb);
        }
        cp_commit();
    };

    uint32_t a_off[2], b_off[4];
#pragma unroll
    for (int mf=0; mf<2; mf++){
        int arow = wm*32 + mf*16 + (lane & 15);
        a_off[mf] = (uint32_t)(arow*(RS*2) + ((lane & 16) ? 16 : 0));
    }
#pragma unroll
    for (int p=0; p<4; p++){
        int nrow = wn*64 + p*16 + (lane & 7) + ((lane & 16) >> 1);
        b_off[p] = (uint32_t)(nrow*(RS*2) + ((lane & 8) ? 16 : 0)) + ABY;
    }

    float acc[2][8][4];
#pragma unroll
    for (int i=0;i<2;i++)
#pragma unroll
        for (int j=0;j<8;j++)
#pragma unroll
            for (int k=0;k<4;k++) acc[i][j][k]=0.f;

    loadStage(0,0); loadStage(1,1);

    int cur = 0, nxt = 2;
    for (int i=0;i<nch;i++){
        cp_wait<NSTG-2>();
        __syncthreads();
        if (i+2 < nch) loadStage(i+2, nxt);
        else cp_commit();
        uint32_t S = sb + (uint32_t)cur*STGB;
#pragma unroll
        for (int ks=0; ks<4; ks++){
            uint32_t koff = (uint32_t)(ks*32);
            uint32_t a[2][4];
            ldsm4(a[0][0],a[0][1],a[0][2],a[0][3], S + a_off[0] + koff);
            ldsm4(a[1][0],a[1][1],a[1][2],a[1][3], S + a_off[1] + koff);
            uint32_t b[8][2];
#pragma unroll
            for (int p=0; p<4; p++)
                ldsm4(b[2*p][0],b[2*p][1],b[2*p+1][0],b[2*p+1][1],
                      S + b_off[p] + koff);
#pragma unroll
            for (int mf=0; mf<2; mf++)
#pragma unroll
                for (int nf=0; nf<8; nf++)
                    mma_f16(acc[mf][nf], a[mf], b[nf]);
        }
        cur = (cur==NSTG-1) ? 0 : cur+1;
        nxt = (nxt==NSTG-1) ? 0 : nxt+1;
    }

    // ---- epilogue ----
#pragma unroll
    for (int mf=0; mf<2; mf++){
#pragma unroll
        for (int half=0; half<2; half++){
            int m = bm + wm*32 + mf*16 + g + half*8;
#pragma unroll
            for (int nf=0; nf<8; nf++){
                int n = bn + wn*64 + nf*8 + qp*2;
                float v0 = acc[mf][nf][half*2+0];
                float v1 = acc[mf][nf][half*2+1];
                if (mode==2){
                    float2 rr = *(const float2*)&res[(size_t)m*Np + n];
                    v0 += bias0[n]   + rr.x;
                    v1 += bias0[n+1] + rr.y;
                    *(float2*)&C0[(size_t)m*Np + n] = make_float2(v0, v1);
                } else if (mode==4){
                    int sel = n >> 9;
                    int col = n & 511;
                    const float* bs = (sel==0) ? bias0 : (sel==1) ? bias1 : bias2;
                    v0 += bs[col]; v1 += bs[col+1];
                    if (sel < 2){
                        v0 = (v0 > 0.f) ? (v0+1.f) : expf(v0);
                        v1 = (v1 > 0.f) ? (v1+1.f) : expf(v1);
                    }
                    __half* Hs = (sel==0) ? H0 : (sel==1) ? H1 : H2;
                    *(uint32_t*)&Hs[(size_t)m*512 + col] =
                        pack2h(__float2half_rn(v0), __float2half_rn(v1));
                } else { // mode 3: relu -> fp16
                    v0 = fmaxf(v0 + bias0[n],   0.f);
                    v1 = fmaxf(v1 + bias0[n+1], 0.f);
                    *(uint32_t*)&C3[(size_t)m*Np + n] =
                        pack2h(__float2half_rn(v0), __float2half_rn(v1));
                }
            }
        }
    }
}

// ---------- per-chunk K^T V and K sums via tensor cores ----------
__global__ __launch_bounds__(256, 2) void chunk_sums_kernel(
    const __half* __restrict__ Kf, const __half* __restrict__ Vf,
    float* __restrict__ ckv, float* __restrict__ cz)
{
    __shared__ __half Kt[64*HRS];
    __shared__ __half Vt[64*HRS];
    int blk = blockIdx.x;
    int c = blk % NC, bh = blk / NC;
    int b = bh / NH, h = bh % NH;
    int t0 = c*CHK;
    int tid = threadIdx.x;
    int lr = tid >> 4, lc = (tid & 15)*4;
    for (int r = lr; r < 64; r += 16){
        size_t gi = ((size_t)(b*TT + t0 + r))*DM + h*DH + lc;
        uint2 kv = *(const uint2*)(Kf+gi);
        uint2 vv = *(const uint2*)(Vf+gi);
        const __half* kp = (const __half*)&kv;
        const __half* vp = (const __half*)&vv;
#pragma unroll
        for (int i=0;i<4;i++){
            Kt[(lc+i)*HRS + r] = kp[i];
            Vt[(lc+i)*HRS + r] = vp[i];
        }
    }
    __syncthreads();

    int lane = tid & 31, wid = tid >> 5;
    int mr = (wid & 3)*16, nb = (wid >> 2)*32;
    int g = lane >> 2, qp = lane & 3;
    uint32_t sbK = smem_u32(Kt), sbV = smem_u32(Vt);
    uint32_t aoff = sbK + (uint32_t)((mr + (lane & 15))*(HRS*2) + ((lane & 16) ? 16 : 0));
    uint32_t boff[2];
#pragma unroll
    for (int p=0;p<2;p++){
        int nrow = nb + p*16 + (lane & 7) + ((lane & 16) >> 1);
        boff[p] = sbV + (uint32_t)(nrow*(HRS*2) + ((lane & 8) ? 16 : 0));
    }
    float acc[4][4];
#pragma unroll
    for (int i=0;i<4;i++)
#pragma unroll
        for (int j=0;j<4;j++) acc[i][j]=0.f;
#pragma unroll
    for (int ks=0; ks<4; ks++){
        uint32_t koff = (uint32_t)(ks*32);
        uint32_t a[4];
        ldsm4(a[0],a[1],a[2],a[3], aoff + koff);
        uint32_t bfr[4][2];
#pragma unroll
        for (int p=0;p<2;p++)
            ldsm4(bfr[2*p][0],bfr[2*p][1],bfr[2*p+1][0],bfr[2*p+1][1],
                  boff[p] + koff);
#pragma unroll
        for (int nf=0;nf<4;nf++) mma_f16(acc[nf], a, bfr[nf]);
    }
    float* outp = ckv + (size_t)blk*DH*DH;
#pragma unroll
    for (int nf=0;nf<4;nf++){
        int m = nb + nf*8 + qp*2;
        *(float2*)&outp[(mr+g)*DH + m]   = make_float2(acc[nf][0], acc[nf][1]);
        *(float2*)&outp[(mr+g+8)*DH + m] = make_float2(acc[nf][2], acc[nf][3]);
    }
    if (tid < DH){
        float z = 0.f;
#pragma unroll 8
        for (int t=0;t<64;t++) z += __half2float(Kt[tid*HRS + t]);
        cz[(size_t)blk*DH + tid] = z;
    }
}

// --------- parallel exclusive scan over chunk states ---------
__global__ __launch_bounds__(256) void scan_kernel(
    const float* __restrict__ ckv, const float* __restrict__ cz,
    float* __restrict__ Sp, float* __restrict__ zp)
{
    int bh = blockIdx.x >> 4;
    int e  = ((blockIdx.x & 15) << 8) + threadIdx.x;
    size_t base = ((size_t)bh*NC)*(DH*DH) + e;
    float v[NC];
#pragma unroll
    for (int c=0;c<NC;c++) v[c] = ckv[base + (size_t)c*(DH*DH)];
    float s = 0.f;
#pragma unroll
    for (int c=0;c<NC;c++){ Sp[base + (size_t)c*(DH*DH)] = s; s += v[c]; }

    if ((blockIdx.x & 15)==0 && threadIdx.x < DH){
        size_t zb = (size_t)bh*NC*DH + threadIdx.x;
        float zv[NC];
#pragma unroll
        for (int c=0;c<NC;c++) zv[c] = cz[zb + (size_t)c*DH];
        float z = 0.f;
#pragma unroll
        for (int c=0;c<NC;c++){ zp[zb + (size_t)c*DH] = z; z += zv[c]; }
    }
}

// ---------- intra-chunk attention via tensor cores ----------
__global__ __launch_bounds__(256, 2) void intra_kernel(
    const __half* __restrict__ Qf, const __half* __restrict__ Kf,
    const __half* __restrict__ Vf, const float* __restrict__ Sp,
    const float* __restrict__ zp, __half* __restrict__ attn1)
{
    __shared__ __half Qs[64*HRS];   // [t][d]
    __shared__ __half Ks[64*HRS];   // [j][d]
    __shared__ __half Vt[64*HRS];   // [m][j]
    __shared__ __half St[64*HRS];   // [m][d]
    __shared__ __half Ss[64*HRS];   // [t][j]
    __shared__ float zs[64], dn[64], dnp[2][64];

    int blk = blockIdx.x;
    int c = blk % NC, bh = blk / NC;
    int b = bh / NH, h = bh % NH;
    int t0 = c*CHK;
    int tid = threadIdx.x;
    int lr = tid >> 4, lc = (tid & 15)*4;

    for (int r = lr; r < 64; r += 16){
        size_t gi = ((size_t)(b*TT + t0 + r))*DM + h*DH + lc;
        uint2 q = *(const uint2*)(Qf+gi);
        uint2 k = *(const uint2*)(Kf+gi);
        uint2 v = *(const uint2*)(Vf+gi);
        *(uint2*)&Qs[r*HRS + lc] = q;
        *(uint2*)&Ks[r*HRS + lc] = k;
        const __half* vp = (const __half*)&v;
#pragma unroll
        for (int i=0;i<4;i++) Vt[(lc+i)*HRS + r] = vp[i];
    }
    {
        size_t base = (size_t)blk*(DH*DH);
        for (int e = tid*4; e < DH*DH; e += 1024){
            float4 sv = *(const float4*)(Sp + base + e);
            int d = e >> 6, m = e & 63;
            St[(m+0)*HRS + d] = __float2half_rn(sv.x);
            St[(m+1)*HRS + d] = __float2half_rn(sv.y);
            St[(m+2)*HRS + d] = __float2half_rn(sv.z);
            St[(m+3)*HRS + d] = __float2half_rn(sv.w);
        }
    }
    if (tid < DH) zs[tid] = zp[(size_t)blk*DH + tid];
    __syncthreads();

    int lane = tid & 31, wid = tid >> 5;
    int mr = (wid & 3)*16, nb = (wid >> 2)*32;
    int g = lane >> 2, qp = lane & 3;
    uint32_t sbQ = smem_u32(Qs), sbK = smem_u32(Ks);
    uint32_t sbV = smem_u32(Vt), sbSt = smem_u32(St), sbSs = smem_u32(Ss);

    uint32_t a_lane = (uint32_t)((mr + (lane & 15))*(HRS*2) + ((lane & 16) ? 16 : 0));
    uint32_t b_lane[2];
#pragma unroll
    for (int p=0;p<2;p++){
        int nrow = nb + p*16 + (lane & 7) + ((lane & 16) >> 1);
        b_lane[p] = (uint32_t)(nrow*(HRS*2) + ((lane & 8) ? 16 : 0));
    }

    // ---- GEMM1: S = Q K^T ----
    float acc[4][4];
#pragma unroll
    for (int i=0;i<4;i++)
#pragma unroll
        for (int j=0;j<4;j++) acc[i][j]=0.f;
#pragma unroll
    for (int ks=0; ks<4; ks++){
        uint32_t koff = (uint32_t)(ks*32);
        uint32_t a[4];
        ldsm4(a[0],a[1],a[2],a[3], sbQ + a_lane + koff);
        uint32_t bfr[4][2];
#pragma unroll
        for (int p=0;p<2;p++)
            ldsm4(bfr[2*p][0],bfr[2*p][1],bfr[2*p+1][0],bfr[2*p+1][1],
                  sbK + b_lane[p] + koff);
#pragma unroll
        for (int nf=0;nf<4;nf++) mma_f16(acc[nf], a, bfr[nf]);
    }

    // ---- mask, den partials, store Ss ----
    int r0 = mr + g, r1 = mr + g + 8;
    float slo = 0.f, shi = 0.f;
#pragma unroll
    for (int nf=0;nf<4;nf++){
        int col = nb + nf*8 + qp*2;
        float c0 = (col   <= r0) ? acc[nf][0] : 0.f;
        float c1 = (col+1 <= r0) ? acc[nf][1] : 0.f;
        float c2 = (col   <= r1) ? acc[nf][2] : 0.f;
        float c3 = (col+1 <= r1) ? acc[nf][3] : 0.f;
        slo += c0 + c1; shi += c2 + c3;
        *(uint32_t*)&Ss[r0*HRS + col] = pack2h(__float2half_rn(c0), __float2half_rn(c1));
        *(uint32_t*)&Ss[r1*HRS + col] = pack2h(__float2half_rn(c2), __float2half_rn(c3));
    }
    slo += __shfl_xor_sync(0xffffffffu, slo, 1);
    slo += __shfl_xor_sync(0xffffffffu, slo, 2);
    shi += __shfl_xor_sync(0xffffffffu, shi, 1);
    shi += __shfl_xor_sync(0xffffffffu, shi, 2);
    if (qp == 0){
        dnp[wid>>2][r0] = slo;
        dnp[wid>>2][r1] = shi;
    }
    __syncthreads();
    if (tid < 64){
        float dsum = dnp[0][tid] + dnp[1][tid];
#pragma unroll 8
        for (int d=0; d<64; d++)
            dsum += __half2float(Qs[tid*HRS + d]) * zs[d];
        dn[tid] = fmaxf(dsum, 1e-6f);
    }
    __syncthreads();

    // ---- GEMM2: num = Ss@Vt + Qs@St ----
    float acc2[4][4];
#pragma unroll
    for (int i=0;i<4;i++)
#pragma unroll
        for (int j=0;j<4;j++) acc2[i][j]=0.f;
#pragma unroll
    for (int ks=0; ks<4; ks++){
        uint32_t koff = (uint32_t)(ks*32);
        uint32_t a[4];
        ldsm4(a[0],a[1],a[2],a[3], sbSs + a_lane + koff);
        uint32_t bfr[4][2];
#pragma unroll
        for (int p=0;p<2;p++)
            ldsm4(bfr[2*p][0],bfr[2*p][1],bfr[2*p+1][0],bfr[2*p+1][1],
                  sbV + b_lane[p] + koff);
#pragma unroll
        for (int nf=0;nf<4;nf++) mma_f16(acc2[nf], a, bfr[nf]);
    }
#pragma unroll
    for (int ks=0; ks<4; ks++){
        uint32_t koff = (uint32_t)(ks*32);
        uint32_t a[4];
        ldsm4(a[0],a[1],a[2],a[3], sbQ + a_lane + koff);
        uint32_t bfr[4][2];
#pragma unroll
        for (int p=0;p<2;p++)
            ldsm4(bfr[2*p][0],bfr[2*p][1],bfr[2*p+1][0],bfr[2*p+1][1],
                  sbSt + b_lane[p] + koff);
#pragma unroll
        for (int nf=0;nf<4;nf++) mma_f16(acc2[nf], a, bfr[nf]);
    }

    float inv0 = 1.0f / dn[r0];
    float inv1 = 1.0f / dn[r1];
#pragma unroll
    for (int nf=0;nf<4;nf++){
        int col = nb + nf*8 + qp*2;
        size_t g0 = ((size_t)(b*TT + t0 + r0))*DM + h*DH + col;
        size_t g1 = ((size_t)(b*TT + t0 + r1))*DM + h*DH + col;
        *(uint32_t*)&attn1[g0] = pack2h(__float2half_rn(acc2[nf][0]*inv0),
                                        __float2half_rn(acc2[nf][1]*inv0));
        *(uint32_t*)&attn1[g1] = pack2h(__float2half_rn(acc2[nf][2]*inv1),
                                        __float2half_rn(acc2[nf][3]*inv1));
    }
}

// ---------------- launch ----------------
extern "C" void kernel_launch(void* const* d_in, const int* in_sizes, int n_in,
                              void* d_out, int out_size)
{
    (void)in_sizes; (void)n_in; (void)out_size;
    const float* x     = (const float*)d_in[0];
    const float* ln1_g = (const float*)d_in[1];
    const float* ln1_b = (const float*)d_in[2];
    const float* Wq    = (const float*)d_in[3];
    const float* bq    = (const float*)d_in[4];
    const float* Wk    = (const float*)d_in[5];
    const float* bk    = (const float*)d_in[6];
    const float* Wv    = (const float*)d_in[7];
    const float* bv    = (const float*)d_in[8];
    const float* Wo    = (const float*)d_in[9];
    const float* bo    = (const float*)d_in[10];
    const float* ln2_g = (const float*)d_in[11];
    const float* ln2_b = (const float*)d_in[12];
    const float* W1    = (const float*)d_in[13];
    const float* b1    = (const float*)d_in[14];
    const float* W2    = (const float*)d_in[15];
    const float* b2    = (const float*)d_in[16];
    float* out = (float*)d_out;

    static bool attr_done = false;
    if (!attr_done){
        cudaFuncSetAttribute(mm_kernel, cudaFuncAttributeMaxDynamicSharedMemorySize,
                             SMEM_MM);
        attr_done = true;
    }

    __half *h1b,*attn1b,*h22b,*ffn1b,*wqkvb,*wob,*w1b,*w2b,*qb,*kb,*vb;
    float *x2b,*ckvb,*czb,*Spb,*zpb;
    cudaGetSymbolAddress((void**)&h1b,   g_h1);
    cudaGetSymbolAddress((void**)&qb,    g_q);
    cudaGetSymbolAddress((void**)&kb,    g_k);
    cudaGetSymbolAddress((void**)&vb,    g_v);
    cudaGetSymbolAddress((void**)&attn1b,g_attn1);
    cudaGetSymbolAddress((void**)&x2b,   g_x2);
    cudaGetSymbolAddress((void**)&h22b,  g_h22);
    cudaGetSymbolAddress((void**)&ffn1b, g_ffn1);
    cudaGetSymbolAddress((void**)&wqkvb, g_wqkv);
    cudaGetSymbolAddress((void**)&wob,   g_wo);
    cudaGetSymbolAddress((void**)&w1b,   g_w1);
    cudaGetSymbolAddress((void**)&w2b,   g_w2);
    cudaGetSymbolAddress((void**)&ckvb,  g_ckv);
    cudaGetSymbolAddress((void**)&czb,   g_cz);
    cudaGetSymbolAddress((void**)&Spb,   g_Sp);
    cudaGetSymbolAddress((void**)&zpb,   g_zp);

    dim3 wcb(32,8);
    wconv_all_kernel<<<1536, wcb>>>(Wq, Wk, Wv, Wo, W1, W2,
                                    wqkvb, wob, w1b, w2b);

    dim3 gQKV(3*DM/TN, MM/TM);      // (12, 32)
    dim3 gFF(DFF/TN, MM/TM);        // (16, 32)
    dim3 gDM(DM/TN, MM/TM);         // (4, 32)

    // sublayer 1
    lnh_kernel<<<MM, 256>>>(x, ln1_g, ln1_b, h1b);
    mm_kernel<<<gQKV, 256, SMEM_MM>>>(h1b, wqkvb, bq, bk, bv, nullptr,
                                      nullptr, qb, kb, vb, nullptr,
                                      DM, DM, 4);
    chunk_sums_kernel<<<BH*NC, 256>>>(kb, vb, ckvb, czb);
    scan_kernel<<<BH*16, 256>>>(ckvb, czb, Spb, zpb);
    intra_kernel<<<BH*NC, 256>>>(qb, kb, vb, Spb, zpb, attn1b);
    mm_kernel<<<gDM, 256, SMEM_MM>>>(attn1b, wob, bo, nullptr, nullptr, x,
                                     x2b, nullptr, nullptr, nullptr, nullptr,
                                     DM, DM, 2);
    lnh_kernel<<<MM, 256>>>(x2b, ln2_g, ln2_b, h22b);

    // sublayer 2
    mm_kernel<<<gFF, 256, SMEM_MM>>>(h22b, w1b, b1, nullptr, nullptr, nullptr,
                                     nullptr, nullptr, nullptr, nullptr, ffn1b,
                                     DFF, DM, 3);
    mm_kernel<<<gDM, 256, SMEM_MM>>>(ffn1b, w2b, b2, nullptr, nullptr, x2b,
                                     out, nullptr, nullptr, nullptr, nullptr,
                                     DM, DFF, 2);
}

// round 14
// speedup vs baseline: 2.4801x; 1.0365x over previous
#include <cuda_runtime.h>
#include <cuda_fp16.h>
#include <math.h>
#include <stdint.h>

// ---------------- problem constants ----------------
#define BB   2
#define TT   2048
#define DM   512
#define NH   8
#define DH   64
#define DFF  2048
#define MM   (BB*TT)        // 4096 rows
#define CHK  64
#define NC   (TT/CHK)       // 32
#define BH   (BB*NH)        // 16
#define HRS  72             // fp16 smem row stride (elements)

// ---------------- scratch (device globals) ----------------
__device__ __align__(256) __half g_h1   [MM*DM];
__device__ __align__(256) __half g_q    [MM*DM];
__device__ __align__(256) __half g_k    [MM*DM];
__device__ __align__(256) __half g_v    [MM*DM];
__device__ __align__(256) __half g_attn1[MM*DM];
__device__ __align__(256) float  g_x2   [MM*DM];
__device__ __align__(256) __half g_h22  [MM*DM];
__device__ __align__(256) __half g_ffn1 [MM*DFF];
__device__ __align__(256) __half g_wqkv [3*DM*DM];
__device__ __align__(256) __half g_wo   [DM*DM];
__device__ __align__(256) __half g_w1   [DFF*DM];
__device__ __align__(256) __half g_w2   [DM*DFF];
__device__ __align__(256) float g_ckv[BH*NC*DH*DH];
__device__ __align__(256) float g_cz [BH*NC*DH];
__device__ __align__(256) float g_Sp [BH*NC*DH*DH];
__device__ __align__(256) float g_zp [BH*NC*DH];

// ---------------- helpers ----------------
__device__ __forceinline__ uint32_t smem_u32(const void* p){
    uint32_t a;
    asm("{ .reg .u64 t; cvta.to.shared.u64 t, %1; cvt.u32.u64 %0, t; }"
        : "=r"(a) : "l"(p));
    return a;
}
__device__ __forceinline__ void cp16(uint32_t dst, const void* src){
    asm volatile("cp.async.cg.shared.global [%0], [%1], 16;" :: "r"(dst), "l"(src));
}
__device__ __forceinline__ void cp_commit(){
    asm volatile("cp.async.commit_group;");
}
template<int N> __device__ __forceinline__ void cp_wait(){
    asm volatile("cp.async.wait_group %0;" :: "n"(N));
}
__device__ __forceinline__ void mma_f16(float* d, const uint32_t* a, const uint32_t* b){
    asm volatile(
        "mma.sync.aligned.m16n8k16.row.col.f32.f16.f16.f32 "
        "{%0,%1,%2,%3}, {%4,%5,%6,%7}, {%8,%9}, {%0,%1,%2,%3};"
        : "+f"(d[0]), "+f"(d[1]), "+f"(d[2]), "+f"(d[3])
        : "r"(a[0]), "r"(a[1]), "r"(a[2]), "r"(a[3]), "r"(b[0]), "r"(b[1]));
}
__device__ __forceinline__ void ldsm4(uint32_t& r0, uint32_t& r1, uint32_t& r2,
                                      uint32_t& r3, uint32_t addr){
    asm volatile("ldmatrix.sync.aligned.m8n8.x4.shared.b16 {%0,%1,%2,%3}, [%4];"
                 : "=r"(r0), "=r"(r1), "=r"(r2), "=r"(r3) : "r"(addr));
}
__device__ __forceinline__ uint32_t pack2h(__half a, __half b){
    return ((uint32_t)__half_as_ushort(b) << 16) | __half_as_ushort(a);
}

// ---------------- layernorm (fp32 in) -> fp16 out ----------------
__global__ __launch_bounds__(256) void lnh_kernel(
    const float* __restrict__ x, const float* __restrict__ g,
    const float* __restrict__ b, __half* __restrict__ o)
{
    int row = blockIdx.x;
    const float* xr = x + (size_t)row*DM;
    int tid = threadIdx.x;
    float v0 = xr[tid], v1 = xr[tid+256];
    float s = v0+v1, s2 = v0*v0+v1*v1;
#pragma unroll
    for (int off=16; off; off>>=1){
        s  += __shfl_xor_sync(0xffffffffu, s,  off);
        s2 += __shfl_xor_sync(0xffffffffu, s2, off);
    }
    __shared__ float rs[8], rs2[8], mu_s, rstd_s;
    if ((tid&31)==0){ rs[tid>>5]=s; rs2[tid>>5]=s2; }
    __syncthreads();
    if (tid==0){
        float a=0.f,c=0.f;
#pragma unroll
        for (int i=0;i<8;i++){ a+=rs[i]; c+=rs2[i]; }
        float mu = a*(1.0f/DM);
        float var = c*(1.0f/DM) - mu*mu;
        mu_s = mu; rstd_s = rsqrtf(var + 1e-5f);
    }
    __syncthreads();
    float mu = mu_s, rstd = rstd_s;
    __half* orow = o + (size_t)row*DM;
    orow[tid]     = __float2half_rn((v0-mu)*rstd*g[tid]     + b[tid]);
    orow[tid+256] = __float2half_rn((v1-mu)*rstd*g[tid+256] + b[tid+256]);
}

// ------ fused pre-kernel: blocks [0,4096) = LN1 rows; [4096,5632) = wconv ------
__global__ __launch_bounds__(256) void pre_kernel(
    const float* __restrict__ x, const float* __restrict__ ln1_g,
    const float* __restrict__ ln1_b, __half* __restrict__ h1,
    const float* __restrict__ Wq, const float* __restrict__ Wk,
    const float* __restrict__ Wv, const float* __restrict__ Wo,
    const float* __restrict__ W1, const float* __restrict__ W2,
    __half* __restrict__ wqkv, __half* __restrict__ wo,
    __half* __restrict__ w1,   __half* __restrict__ w2)
{
    int tid = threadIdx.x;
    if (blockIdx.x < MM){
        // ---- LN1 row ----
        int row = blockIdx.x;
        const float* xr = x + (size_t)row*DM;
        float v0 = xr[tid], v1 = xr[tid+256];
        float s = v0+v1, s2 = v0*v0+v1*v1;
#pragma unroll
        for (int off=16; off; off>>=1){
            s  += __shfl_xor_sync(0xffffffffu, s,  off);
            s2 += __shfl_xor_sync(0xffffffffu, s2, off);
        }
        __shared__ float rs[8], rs2[8], mu_s, rstd_s;
        if ((tid&31)==0){ rs[tid>>5]=s; rs2[tid>>5]=s2; }
        __syncthreads();
        if (tid==0){
            float a=0.f,c=0.f;
#pragma unroll
            for (int i=0;i<8;i++){ a+=rs[i]; c+=rs2[i]; }
            float mu = a*(1.0f/DM);
            float var = c*(1.0f/DM) - mu*mu;
            mu_s = mu; rstd_s = rsqrtf(var + 1e-5f);
        }
        __syncthreads();
        float mu = mu_s, rstd = rstd_s;
        __half* orow = h1 + (size_t)row*DM;
        orow[tid]     = __float2half_rn((v0-mu)*rstd*ln1_g[tid]     + ln1_b[tid]);
        orow[tid+256] = __float2half_rn((v1-mu)*rstd*ln1_g[tid+256] + ln1_b[tid+256]);
    } else {
        // ---- weight transpose+convert tile ----
        int bid = blockIdx.x - MM;
        const float* W; __half* Bt;
        int Kd, Nd, nx, local;
        if (bid < 512){
            int seg = bid >> 7; local = bid & 127; nx = 16; Kd = 512; Nd = 512;
            W  = (seg==0)?Wq:(seg==1)?Wk:(seg==2)?Wv:Wo;
            Bt = (seg==0)?wqkv:(seg==1)?(wqkv+512*DM):(seg==2)?(wqkv+1024*DM):wo;
        } else if (bid < 1024){
            local = bid - 512; nx = 64; Kd = 512; Nd = 2048; W = W1; Bt = w1;
        } else {
            local = bid - 1024; nx = 16; Kd = 2048; Nd = 512; W = W2; Bt = w2;
        }
        int n0 = (local % nx)*32, k0 = (local / nx)*64;
        __shared__ float t[64][33];
        int tx = tid & 31, ty = tid >> 5;
#pragma unroll
        for (int i=ty;i<64;i+=8)
            t[i][tx] = W[(size_t)(k0+i)*Nd + n0 + tx];
        __syncthreads();
#pragma unroll
        for (int i=ty;i<32;i+=8){
            __half ha = __float2half_rn(t[2*tx][i]);
            __half hb = __float2half_rn(t[2*tx+1][i]);
            size_t base = (size_t)(n0+i)*Kd + k0 + 2*tx;
            *(uint32_t*)&Bt[base] = pack2h(ha, hb);
        }
    }
}

// ------------- mma.sync fp16 GEMM, 3-stage pipeline, 2 CTAs/SM -------------
// A[M,K], B[N,K].
// modes: 2 +bias0+res -> fp32 C0; 3 relu(+bias0) -> fp16 C3; 4 qkv split fp16 out
#define TM 128
#define TN 128
#define RS 72
#define ABY (TM*RS*2)
#define STGB (2*ABY)
#define NSTG 3
#define SMEM_MM (NSTG*STGB)

__global__ __launch_bounds__(256, 2) void mm_kernel(
    const __half* __restrict__ Ap, const __half* __restrict__ Bp,
    const float* __restrict__ bias0, const float* __restrict__ bias1,
    const float* __restrict__ bias2, const float* __restrict__ res,
    float* __restrict__ C0, __half* __restrict__ H0, __half* __restrict__ H1,
    __half* __restrict__ H2, __half* __restrict__ C3,
    int Np, int Kp, int mode)
{
    extern __shared__ char smc[];
    uint32_t sb = smem_u32(smc);

    int tid = threadIdx.x;
    int lane = tid & 31, wid = tid >> 5;
    int wm = wid >> 1, wn = wid & 1;
    int g = lane >> 2, qp = lane & 3;
    int bm = blockIdx.y * TM;
    int bn = blockIdx.x * TN;
    int nch = Kp >> 6;

    const char* Abase = (const char*)(Ap + (size_t)bm*Kp);
    const char* Bbase = (const char*)(Bp + (size_t)bn*Kp);
    const size_t rowb = (size_t)Kp*2;

    int lr_ = tid >> 3, lc_ = (tid & 7)*16;
    auto loadStage = [&](int c, int s){
        uint32_t da = sb + (uint32_t)s*STGB;
        uint32_t db = da + ABY;
        const char* sa = Abase + (size_t)c*128 + (size_t)lr_*rowb + lc_;
        const char* sbp= Bbase + (size_t)c*128 + (size_t)lr_*rowb + lc_;
        uint32_t so = (uint32_t)(lr_*(RS*2) + lc_);
#pragma unroll
        for (int t=0;t<4;t++){
            cp16(da + so + t*32*(RS*2), sa + (size_t)t*32*rowb);
            cp16(db + so + t*32*(RS*2), sbp + (size_t)t*32*rowb);
        }
        cp_commit();
    };

    uint32_t a_off[2], b_off[4];
#pragma unroll
    for (int mf=0; mf<2; mf++){
        int arow = wm*32 + mf*16 + (lane & 15);
        a_off[mf] = (uint32_t)(arow*(RS*2) + ((lane & 16) ? 16 : 0));
    }
#pragma unroll
    for (int p=0; p<4; p++){
        int nrow = wn*64 + p*16 + (lane & 7) + ((lane & 16) >> 1);
        b_off[p] = (uint32_t)(nrow*(RS*2) + ((lane & 8) ? 16 : 0)) + ABY;
    }

    float acc[2][8][4];
#pragma unroll
    for (int i=0;i<2;i++)
#pragma unroll
        for (int j=0;j<8;j++)
#pragma unroll
            for (int k=0;k<4;k++) acc[i][j][k]=0.f;

    loadStage(0,0); loadStage(1,1);

    int cur = 0, nxt = 2;
    for (int i=0;i<nch;i++){
        cp_wait<NSTG-2>();
        __syncthreads();
        if (i+2 < nch) loadStage(i+2, nxt);
        else cp_commit();
        uint32_t S = sb + (uint32_t)cur*STGB;
#pragma unroll
        for (int ks=0; ks<4; ks++){
            uint32_t koff = (uint32_t)(ks*32);
            uint32_t a[2][4];
            ldsm4(a[0][0],a[0][1],a[0][2],a[0][3], S + a_off[0] + koff);
            ldsm4(a[1][0],a[1][1],a[1][2],a[1][3], S + a_off[1] + koff);
            uint32_t b[8][2];
#pragma unroll
            for (int p=0; p<4; p++)
                ldsm4(b[2*p][0],b[2*p][1],b[2*p+1][0],b[2*p+1][1],
                      S + b_off[p] + koff);
#pragma unroll
            for (int mf=0; mf<2; mf++)
#pragma unroll
                for (int nf=0; nf<8; nf++)
                    mma_f16(acc[mf][nf], a[mf], b[nf]);
        }
        cur = (cur==NSTG-1) ? 0 : cur+1;
        nxt = (nxt==NSTG-1) ? 0 : nxt+1;
    }

    // ---- epilogue ----
#pragma unroll
    for (int mf=0; mf<2; mf++){
#pragma unroll
        for (int half=0; half<2; half++){
            int m = bm + wm*32 + mf*16 + g + half*8;
#pragma unroll
            for (int nf=0; nf<8; nf++){
                int n = bn + wn*64 + nf*8 + qp*2;
                float v0 = acc[mf][nf][half*2+0];
                float v1 = acc[mf][nf][half*2+1];
                if (mode==2){
                    float2 rr = *(const float2*)&res[(size_t)m*Np + n];
                    v0 += bias0[n]   + rr.x;
                    v1 += bias0[n+1] + rr.y;
                    *(float2*)&C0[(size_t)m*Np + n] = make_float2(v0, v1);
                } else if (mode==4){
                    int sel = n >> 9;
                    int col = n & 511;
                    const float* bs = (sel==0) ? bias0 : (sel==1) ? bias1 : bias2;
                    v0 += bs[col]; v1 += bs[col+1];
                    if (sel < 2){
                        v0 = (v0 > 0.f) ? (v0+1.f) : expf(v0);
                        v1 = (v1 > 0.f) ? (v1+1.f) : expf(v1);
                    }
                    __half* Hs = (sel==0) ? H0 : (sel==1) ? H1 : H2;
                    *(uint32_t*)&Hs[(size_t)m*512 + col] =
                        pack2h(__float2half_rn(v0), __float2half_rn(v1));
                } else { // mode 3: relu -> fp16
                    v0 = fmaxf(v0 + bias0[n],   0.f);
                    v1 = fmaxf(v1 + bias0[n+1], 0.f);
                    *(uint32_t*)&C3[(size_t)m*Np + n] =
                        pack2h(__float2half_rn(v0), __float2half_rn(v1));
                }
            }
        }
    }
}

// ---------- per-chunk K^T V and K sums via tensor cores (4 CTAs/SM) ----------
__global__ __launch_bounds__(256, 4) void chunk_sums_kernel(
    const __half* __restrict__ Kf, const __half* __restrict__ Vf,
    float* __restrict__ ckv, float* __restrict__ cz)
{
    __shared__ __half Kt[64*HRS];
    __shared__ __half Vt[64*HRS];
    int blk = blockIdx.x;
    int c = blk % NC, bh = blk / NC;
    int b = bh / NH, h = bh % NH;
    int t0 = c*CHK;
    int tid = threadIdx.x;
    int lr = tid >> 4, lc = (tid & 15)*4;
    for (int r = lr; r < 64; r += 16){
        size_t gi = ((size_t)(b*TT + t0 + r))*DM + h*DH + lc;
        uint2 kv = *(const uint2*)(Kf+gi);
        uint2 vv = *(const uint2*)(Vf+gi);
        const __half* kp = (const __half*)&kv;
        const __half* vp = (const __half*)&vv;
#pragma unroll
        for (int i=0;i<4;i++){
            Kt[(lc+i)*HRS + r] = kp[i];
            Vt[(lc+i)*HRS + r] = vp[i];
        }
    }
    __syncthreads();

    int lane = tid & 31, wid = tid >> 5;
    int mr = (wid & 3)*16, nb = (wid >> 2)*32;
    int g = lane >> 2, qp = lane & 3;
    uint32_t sbK = smem_u32(Kt), sbV = smem_u32(Vt);
    uint32_t aoff = sbK + (uint32_t)((mr + (lane & 15))*(HRS*2) + ((lane & 16) ? 16 : 0));
    uint32_t boff[2];
#pragma unroll
    for (int p=0;p<2;p++){
        int nrow = nb + p*16 + (lane & 7) + ((lane & 16) >> 1);
        boff[p] = sbV + (uint32_t)(nrow*(HRS*2) + ((lane & 8) ? 16 : 0));
    }
    float acc[4][4];
#pragma unroll
    for (int i=0;i<4;i++)
#pragma unroll
        for (int j=0;j<4;j++) acc[i][j]=0.f;
#pragma unroll
    for (int ks=0; ks<4; ks++){
        uint32_t koff = (uint32_t)(ks*32);
        uint32_t a[4];
        ldsm4(a[0],a[1],a[2],a[3], aoff + koff);
        uint32_t bfr[4][2];
#pragma unroll
        for (int p=0;p<2;p++)
            ldsm4(bfr[2*p][0],bfr[2*p][1],bfr[2*p+1][0],bfr[2*p+1][1],
                  boff[p] + koff);
#pragma unroll
        for (int nf=0;nf<4;nf++) mma_f16(acc[nf], a, bfr[nf]);
    }
    float* outp = ckv + (size_t)blk*DH*DH;
#pragma unroll
    for (int nf=0;nf<4;nf++){
        int m = nb + nf*8 + qp*2;
        *(float2*)&outp[(mr+g)*DH + m]   = make_float2(acc[nf][0], acc[nf][1]);
        *(float2*)&outp[(mr+g+8)*DH + m] = make_float2(acc[nf][2], acc[nf][3]);
    }
    if (tid < DH){
        float z = 0.f;
#pragma unroll 8
        for (int t=0;t<64;t++) z += __half2float(Kt[tid*HRS + t]);
        cz[(size_t)blk*DH + tid] = z;
    }
}

// --------- parallel exclusive scan over chunk states ---------
__global__ __launch_bounds__(256) void scan_kernel(
    const float* __restrict__ ckv, const float* __restrict__ cz,
    float* __restrict__ Sp, float* __restrict__ zp)
{
    int bh = blockIdx.x >> 4;
    int e  = ((blockIdx.x & 15) << 8) + threadIdx.x;
    size_t base = ((size_t)bh*NC)*(DH*DH) + e;
    float v[NC];
#pragma unroll
    for (int c=0;c<NC;c++) v[c] = ckv[base + (size_t)c*(DH*DH)];
    float s = 0.f;
#pragma unroll
    for (int c=0;c<NC;c++){ Sp[base + (size_t)c*(DH*DH)] = s; s += v[c]; }

    if ((blockIdx.x & 15)==0 && threadIdx.x < DH){
        size_t zb = (size_t)bh*NC*DH + threadIdx.x;
        float zv[NC];
#pragma unroll
        for (int c=0;c<NC;c++) zv[c] = cz[zb + (size_t)c*DH];
        float z = 0.f;
#pragma unroll
        for (int c=0;c<NC;c++){ zp[zb + (size_t)c*DH] = z; z += zv[c]; }
    }
}

// ---------- intra-chunk attention via tensor cores (3 CTAs/SM) ----------
__global__ __launch_bounds__(256, 3) void intra_kernel(
    const __half* __restrict__ Qf, const __half* __restrict__ Kf,
    const __half* __restrict__ Vf, const float* __restrict__ Sp,
    const float* __restrict__ zp, __half* __restrict__ attn1)
{
    __shared__ __half Qs[64*HRS];   // [t][d]
    __shared__ __half Ks[64*HRS];   // [j][d]
    __shared__ __half Vt[64*HRS];   // [m][j]
    __shared__ __half St[64*HRS];   // [m][d]
    __shared__ __half Ss[64*HRS];   // [t][j]
    __shared__ float zs[64], dn[64], dnp[2][64];

    int blk = blockIdx.x;
    int c = blk % NC, bh = blk / NC;
    int b = bh / NH, h = bh % NH;
    int t0 = c*CHK;
    int tid = threadIdx.x;
    int lr = tid >> 4, lc = (tid & 15)*4;

    for (int r = lr; r < 64; r += 16){
        size_t gi = ((size_t)(b*TT + t0 + r))*DM + h*DH + lc;
        uint2 q = *(const uint2*)(Qf+gi);
        uint2 k = *(const uint2*)(Kf+gi);
        uint2 v = *(const uint2*)(Vf+gi);
        *(uint2*)&Qs[r*HRS + lc] = q;
        *(uint2*)&Ks[r*HRS + lc] = k;
        const __half* vp = (const __half*)&v;
#pragma unroll
        for (int i=0;i<4;i++) Vt[(lc+i)*HRS + r] = vp[i];
    }
    {
        size_t base = (size_t)blk*(DH*DH);
        for (int e = tid*4; e < DH*DH; e += 1024){
            float4 sv = *(const float4*)(Sp + base + e);
            int d = e >> 6, m = e & 63;
            St[(m+0)*HRS + d] = __float2half_rn(sv.x);
            St[(m+1)*HRS + d] = __float2half_rn(sv.y);
            St[(m+2)*HRS + d] = __float2half_rn(sv.z);
            St[(m+3)*HRS + d] = __float2half_rn(sv.w);
        }
    }
    if (tid < DH) zs[tid] = zp[(size_t)blk*DH + tid];
    __syncthreads();

    int lane = tid & 31, wid = tid >> 5;
    int mr = (wid & 3)*16, nb = (wid >> 2)*32;
    int g = lane >> 2, qp = lane & 3;
    uint32_t sbQ = smem_u32(Qs), sbK = smem_u32(Ks);
    uint32_t sbV = smem_u32(Vt), sbSt = smem_u32(St), sbSs = smem_u32(Ss);

    uint32_t a_lane = (uint32_t)((mr + (lane & 15))*(HRS*2) + ((lane & 16) ? 16 : 0));
    uint32_t b_lane[2];
#pragma unroll
    for (int p=0;p<2;p++){
        int nrow = nb + p*16 + (lane & 7) + ((lane & 16) >> 1);
        b_lane[p] = (uint32_t)(nrow*(HRS*2) + ((lane & 8) ? 16 : 0));
    }

    // ---- GEMM1: S = Q K^T ----
    float acc[4][4];
#pragma unroll
    for (int i=0;i<4;i++)
#pragma unroll
        for (int j=0;j<4;j++) acc[i][j]=0.f;
#pragma unroll
    for (int ks=0; ks<4; ks++){
        uint32_t koff = (uint32_t)(ks*32);
        uint32_t a[4];
        ldsm4(a[0],a[1],a[2],a[3], sbQ + a_lane + koff);
        uint32_t bfr[4][2];
#pragma unroll
        for (int p=0;p<2;p++)
            ldsm4(bfr[2*p][0],bfr[2*p][1],bfr[2*p+1][0],bfr[2*p+1][1],
                  sbK + b_lane[p] + koff);
#pragma unroll
        for (int nf=0;nf<4;nf++) mma_f16(acc[nf], a, bfr[nf]);
    }

    // ---- mask, den partials, store Ss ----
    int r0 = mr + g, r1 = mr + g + 8;
    float slo = 0.f, shi = 0.f;
#pragma unroll
    for (int nf=0;nf<4;nf++){
        int col = nb + nf*8 + qp*2;
        float c0 = (col   <= r0) ? acc[nf][0] : 0.f;
        float c1 = (col+1 <= r0) ? acc[nf][1] : 0.f;
        float c2 = (col   <= r1) ? acc[nf][2] : 0.f;
        float c3 = (col+1 <= r1) ? acc[nf][3] : 0.f;
        slo += c0 + c1; shi += c2 + c3;
        *(uint32_t*)&Ss[r0*HRS + col] = pack2h(__float2half_rn(c0), __float2half_rn(c1));
        *(uint32_t*)&Ss[r1*HRS + col] = pack2h(__float2half_rn(c2), __float2half_rn(c3));
    }
    slo += __shfl_xor_sync(0xffffffffu, slo, 1);
    slo += __shfl_xor_sync(0xffffffffu, slo, 2);
    shi += __shfl_xor_sync(0xffffffffu, shi, 1);
    shi += __shfl_xor_sync(0xffffffffu, shi, 2);
    if (qp == 0){
        dnp[wid>>2][r0] = slo;
        dnp[wid>>2][r1] = shi;
    }
    __syncthreads();
    if (tid < 64){
        float dsum = dnp[0][tid] + dnp[1][tid];
#pragma unroll 8
        for (int d=0; d<64; d++)
            dsum += __half2float(Qs[tid*HRS + d]) * zs[d];
        dn[tid] = fmaxf(dsum, 1e-6f);
    }
    __syncthreads();

    // ---- GEMM2: num = Ss@Vt + Qs@St ----
    float acc2[4][4];
#pragma unroll
    for (int i=0;i<4;i++)
#pragma unroll
        for (int j=0;j<4;j++) acc2[i][j]=0.f;
#pragma unroll
    for (int ks=0; ks<4; ks++){
        uint32_t koff = (uint32_t)(ks*32);
        uint32_t a[4];
        ldsm4(a[0],a[1],a[2],a[3], sbSs + a_lane + koff);
        uint32_t bfr[4][2];
#pragma unroll
        for (int p=0;p<2;p++)
            ldsm4(bfr[2*p][0],bfr[2*p][1],bfr[2*p+1][0],bfr[2*p+1][1],
                  sbV + b_lane[p] + koff);
#pragma unroll
        for (int nf=0;nf<4;nf++) mma_f16(acc2[nf], a, bfr[nf]);
    }
#pragma unroll
    for (int ks=0; ks<4; ks++){
        uint32_t koff = (uint32_t)(ks*32);
        uint32_t a[4];
        ldsm4(a[0],a[1],a[2],a[3], sbQ + a_lane + koff);
        uint32_t bfr[4][2];
#pragma unroll
        for (int p=0;p<2;p++)
            ldsm4(bfr[2*p][0],bfr[2*p][1],bfr[2*p+1][0],bfr[2*p+1][1],
                  sbSt + b_lane[p] + koff);
#pragma unroll
        for (int nf=0;nf<4;nf++) mma_f16(acc2[nf], a, bfr[nf]);
    }

    float inv0 = 1.0f / dn[r0];
    float inv1 = 1.0f / dn[r1];
#pragma unroll
    for (int nf=0;nf<4;nf++){
        int col = nb + nf*8 + qp*2;
        size_t g0 = ((size_t)(b*TT + t0 + r0))*DM + h*DH + col;
        size_t g1 = ((size_t)(b*TT + t0 + r1))*DM + h*DH + col;
        *(uint32_t*)&attn1[g0] = pack2h(__float2half_rn(acc2[nf][0]*inv0),
                                        __float2half_rn(acc2[nf][1]*inv0));
        *(uint32_t*)&attn1[g1] = pack2h(__float2half_rn(acc2[nf][2]*inv1),
                                        __float2half_rn(acc2[nf][3]*inv1));
    }
}

// ---------------- launch ----------------
extern "C" void kernel_launch(void* const* d_in, const int* in_sizes, int n_in,
                              void* d_out, int out_size)
{
    (void)in_sizes; (void)n_in; (void)out_size;
    const float* x     = (const float*)d_in[0];
    const float* ln1_g = (const float*)d_in[1];
    const float* ln1_b = (const float*)d_in[2];
    const float* Wq    = (const float*)d_in[3];
    const float* bq    = (const float*)d_in[4];
    const float* Wk    = (const float*)d_in[5];
    const float* bk    = (const float*)d_in[6];
    const float* Wv    = (const float*)d_in[7];
    const float* bv    = (const float*)d_in[8];
    const float* Wo    = (const float*)d_in[9];
    const float* bo    = (const float*)d_in[10];
    const float* ln2_g = (const float*)d_in[11];
    const float* ln2_b = (const float*)d_in[12];
    const float* W1    = (const float*)d_in[13];
    const float* b1    = (const float*)d_in[14];
    const float* W2    = (const float*)d_in[15];
    const float* b2    = (const float*)d_in[16];
    float* out = (float*)d_out;

    static bool attr_done = false;
    if (!attr_done){
        cudaFuncSetAttribute(mm_kernel, cudaFuncAttributeMaxDynamicSharedMemorySize,
                             SMEM_MM);
        attr_done = true;
    }

    __half *h1b,*attn1b,*h22b,*ffn1b,*wqkvb,*wob,*w1b,*w2b,*qb,*kb,*vb;
    float *x2b,*ckvb,*czb,*Spb,*zpb;
    cudaGetSymbolAddress((void**)&h1b,   g_h1);
    cudaGetSymbolAddress((void**)&qb,    g_q);
    cudaGetSymbolAddress((void**)&kb,    g_k);
    cudaGetSymbolAddress((void**)&vb,    g_v);
    cudaGetSymbolAddress((void**)&attn1b,g_attn1);
    cudaGetSymbolAddress((void**)&x2b,   g_x2);
    cudaGetSymbolAddress((void**)&h22b,  g_h22);
    cudaGetSymbolAddress((void**)&ffn1b, g_ffn1);
    cudaGetSymbolAddress((void**)&wqkvb, g_wqkv);
    cudaGetSymbolAddress((void**)&wob,   g_wo);
    cudaGetSymbolAddress((void**)&w1b,   g_w1);
    cudaGetSymbolAddress((void**)&w2b,   g_w2);
    cudaGetSymbolAddress((void**)&ckvb,  g_ckv);
    cudaGetSymbolAddress((void**)&czb,   g_cz);
    cudaGetSymbolAddress((void**)&Spb,   g_Sp);
    cudaGetSymbolAddress((void**)&zpb,   g_zp);

    dim3 gQKV(3*DM/TN, MM/TM);      // (12, 32)
    dim3 gFF(DFF/TN, MM/TM);        // (16, 32)
    dim3 gDM(DM/TN, MM/TM);         // (4, 32)

    // sublayer 1 (LN1 + weight conversion fused into one launch)
    pre_kernel<<<MM + 1536, 256>>>(x, ln1_g, ln1_b, h1b,
                                   Wq, Wk, Wv, Wo, W1, W2,
                                   wqkvb, wob, w1b, w2b);
    mm_kernel<<<gQKV, 256, SMEM_MM>>>(h1b, wqkvb, bq, bk, bv, nullptr,
                                      nullptr, qb, kb, vb, nullptr,
                                      DM, DM, 4);
    chunk_sums_kernel<<<BH*NC, 256>>>(kb, vb, ckvb, czb);
    scan_kernel<<<BH*16, 256>>>(ckvb, czb, Spb, zpb);
    intra_kernel<<<BH*NC, 256>>>(qb, kb, vb, Spb, zpb, attn1b);
    mm_kernel<<<gDM, 256, SMEM_MM>>>(attn1b, wob, bo, nullptr, nullptr, x,
                                     x2b, nullptr, nullptr, nullptr, nullptr,
                                     DM, DM, 2);
    lnh_kernel<<<MM, 256>>>(x2b, ln2_g, ln2_b, h22b);

    // sublayer 2
    mm_kernel<<<gFF, 256, SMEM_MM>>>(h22b, w1b, b1, nullptr, nullptr, nullptr,
                                     nullptr, nullptr, nullptr, nullptr, ffn1b,
                                     DFF, DM, 3);
    mm_kernel<<<gDM, 256, SMEM_MM>>>(ffn1b, w2b, b2, nullptr, nullptr, x2b,
                                     out, nullptr, nullptr, nullptr, nullptr,
                                     DM, DFF, 2);
}

// round 15
// speedup vs baseline: 2.5121x; 1.0129x over previous
#include <cuda_runtime.h>
#include <cuda_fp16.h>
#include <math.h>
#include <stdint.h>

// ---------------- problem constants ----------------
#define BB   2
#define TT   2048
#define DM   512
#define NH   8
#define DH   64
#define DFF  2048
#define MM   (BB*TT)        // 4096 rows
#define CHK  64
#define NC   (TT/CHK)       // 32
#define BH   (BB*NH)        // 16
#define HRS  72             // fp16 smem row stride (elements)

// ---------------- scratch (device globals) ----------------
__device__ __align__(256) __half g_h1   [MM*DM];
__device__ __align__(256) __half g_q    [MM*DM];
__device__ __align__(256) __half g_k    [MM*DM];
__device__ __align__(256) __half g_v    [MM*DM];
__device__ __align__(256) __half g_attn1[MM*DM];
__device__ __align__(256) float  g_x2   [MM*DM];
__device__ __align__(256) __half g_h22  [MM*DM];
__device__ __align__(256) __half g_ffn1 [MM*DFF];
__device__ __align__(256) __half g_wqkv [3*DM*DM];
__device__ __align__(256) __half g_wo   [DM*DM];
__device__ __align__(256) __half g_w1   [DFF*DM];
__device__ __align__(256) __half g_w2   [DM*DFF];
__device__ __align__(256) float  g_ckv[BH*NC*DH*DH];
__device__ __align__(256) float  g_cz [BH*NC*DH];
__device__ __align__(256) __half g_Sp [BH*NC*DH*DH];
__device__ __align__(256) float  g_zp [BH*NC*DH];

// ---------------- helpers ----------------
__device__ __forceinline__ uint32_t smem_u32(const void* p){
    uint32_t a;
    asm("{ .reg .u64 t; cvta.to.shared.u64 t, %1; cvt.u32.u64 %0, t; }"
        : "=r"(a) : "l"(p));
    return a;
}
__device__ __forceinline__ void cp16(uint32_t dst, const void* src){
    asm volatile("cp.async.cg.shared.global [%0], [%1], 16;" :: "r"(dst), "l"(src));
}
__device__ __forceinline__ void cp_commit(){
    asm volatile("cp.async.commit_group;");
}
template<int N> __device__ __forceinline__ void cp_wait(){
    asm volatile("cp.async.wait_group %0;" :: "n"(N));
}
__device__ __forceinline__ void mma_f16(float* d, const uint32_t* a, const uint32_t* b){
    asm volatile(
        "mma.sync.aligned.m16n8k16.row.col.f32.f16.f16.f32 "
        "{%0,%1,%2,%3}, {%4,%5,%6,%7}, {%8,%9}, {%0,%1,%2,%3};"
        : "+f"(d[0]), "+f"(d[1]), "+f"(d[2]), "+f"(d[3])
        : "r"(a[0]), "r"(a[1]), "r"(a[2]), "r"(a[3]), "r"(b[0]), "r"(b[1]));
}
__device__ __forceinline__ void ldsm4(uint32_t& r0, uint32_t& r1, uint32_t& r2,
                                      uint32_t& r3, uint32_t addr){
    asm volatile("ldmatrix.sync.aligned.m8n8.x4.shared.b16 {%0,%1,%2,%3}, [%4];"
                 : "=r"(r0), "=r"(r1), "=r"(r2), "=r"(r3) : "r"(addr));
}
__device__ __forceinline__ uint32_t pack2h(__half a, __half b){
    return ((uint32_t)__half_as_ushort(b) << 16) | __half_as_ushort(a);
}

// ---------------- layernorm (fp32 in) -> fp16 out ----------------
__global__ __launch_bounds__(256) void lnh_kernel(
    const float* __restrict__ x, const float* __restrict__ g,
    const float* __restrict__ b, __half* __restrict__ o)
{
    int row = blockIdx.x;
    const float* xr = x + (size_t)row*DM;
    int tid = threadIdx.x;
    float v0 = xr[tid], v1 = xr[tid+256];
    float s = v0+v1, s2 = v0*v0+v1*v1;
#pragma unroll
    for (int off=16; off; off>>=1){
        s  += __shfl_xor_sync(0xffffffffu, s,  off);
        s2 += __shfl_xor_sync(0xffffffffu, s2, off);
    }
    __shared__ float rs[8], rs2[8], mu_s, rstd_s;
    if ((tid&31)==0){ rs[tid>>5]=s; rs2[tid>>5]=s2; }
    __syncthreads();
    if (tid==0){
        float a=0.f,c=0.f;
#pragma unroll
        for (int i=0;i<8;i++){ a+=rs[i]; c+=rs2[i]; }
        float mu = a*(1.0f/DM);
        float var = c*(1.0f/DM) - mu*mu;
        mu_s = mu; rstd_s = rsqrtf(var + 1e-5f);
    }
    __syncthreads();
    float mu = mu_s, rstd = rstd_s;
    __half* orow = o + (size_t)row*DM;
    orow[tid]     = __float2half_rn((v0-mu)*rstd*g[tid]     + b[tid]);
    orow[tid+256] = __float2half_rn((v1-mu)*rstd*g[tid+256] + b[tid+256]);
}

// ------ fused pre-kernel: blocks [0,4096) = LN1 rows; [4096,5632) = wconv ------
__global__ __launch_bounds__(256) void pre_kernel(
    const float* __restrict__ x, const float* __restrict__ ln1_g,
    const float* __restrict__ ln1_b, __half* __restrict__ h1,
    const float* __restrict__ Wq, const float* __restrict__ Wk,
    const float* __restrict__ Wv, const float* __restrict__ Wo,
    const float* __restrict__ W1, const float* __restrict__ W2,
    __half* __restrict__ wqkv, __half* __restrict__ wo,
    __half* __restrict__ w1,   __half* __restrict__ w2)
{
    int tid = threadIdx.x;
    if (blockIdx.x < MM){
        int row = blockIdx.x;
        const float* xr = x + (size_t)row*DM;
        float v0 = xr[tid], v1 = xr[tid+256];
        float s = v0+v1, s2 = v0*v0+v1*v1;
#pragma unroll
        for (int off=16; off; off>>=1){
            s  += __shfl_xor_sync(0xffffffffu, s,  off);
            s2 += __shfl_xor_sync(0xffffffffu, s2, off);
        }
        __shared__ float rs[8], rs2[8], mu_s, rstd_s;
        if ((tid&31)==0){ rs[tid>>5]=s; rs2[tid>>5]=s2; }
        __syncthreads();
        if (tid==0){
            float a=0.f,c=0.f;
#pragma unroll
            for (int i=0;i<8;i++){ a+=rs[i]; c+=rs2[i]; }
            float mu = a*(1.0f/DM);
            float var = c*(1.0f/DM) - mu*mu;
            mu_s = mu; rstd_s = rsqrtf(var + 1e-5f);
        }
        __syncthreads();
        float mu = mu_s, rstd = rstd_s;
        __half* orow = h1 + (size_t)row*DM;
        orow[tid]     = __float2half_rn((v0-mu)*rstd*ln1_g[tid]     + ln1_b[tid]);
        orow[tid+256] = __float2half_rn((v1-mu)*rstd*ln1_g[tid+256] + ln1_b[tid+256]);
    } else {
        int bid = blockIdx.x - MM;
        const float* W; __half* Bt;
        int Kd, Nd, nx, local;
        if (bid < 512){
            int seg = bid >> 7; local = bid & 127; nx = 16; Kd = 512; Nd = 512;
            W  = (seg==0)?Wq:(seg==1)?Wk:(seg==2)?Wv:Wo;
            Bt = (seg==0)?wqkv:(seg==1)?(wqkv+512*DM):(seg==2)?(wqkv+1024*DM):wo;
        } else if (bid < 1024){
            local = bid - 512; nx = 64; Kd = 512; Nd = 2048; W = W1; Bt = w1;
        } else {
            local = bid - 1024; nx = 16; Kd = 2048; Nd = 512; W = W2; Bt = w2;
        }
        int n0 = (local % nx)*32, k0 = (local / nx)*64;
        __shared__ float t[64][33];
        int tx = tid & 31, ty = tid >> 5;
#pragma unroll
        for (int i=ty;i<64;i+=8)
            t[i][tx] = W[(size_t)(k0+i)*Nd + n0 + tx];
        __syncthreads();
#pragma unroll
        for (int i=ty;i<32;i+=8){
            __half ha = __float2half_rn(t[2*tx][i]);
            __half hb = __float2half_rn(t[2*tx+1][i]);
            size_t base = (size_t)(n0+i)*Kd + k0 + 2*tx;
            *(uint32_t*)&Bt[base] = pack2h(ha, hb);
        }
    }
}

// ------------- mma.sync fp16 GEMM, 3-stage pipeline, 2 CTAs/SM -------------
#define TM 128
#define TN 128
#define RS 72
#define ABY (TM*RS*2)
#define STGB (2*ABY)
#define NSTG 3
#define SMEM_MM (NSTG*STGB)

__global__ __launch_bounds__(256, 2) void mm_kernel(
    const __half* __restrict__ Ap, const __half* __restrict__ Bp,
    const float* __restrict__ bias0, const float* __restrict__ bias1,
    const float* __restrict__ bias2, const float* __restrict__ res,
    float* __restrict__ C0, __half* __restrict__ H0, __half* __restrict__ H1,
    __half* __restrict__ H2, __half* __restrict__ C3,
    int Np, int Kp, int mode)
{
    extern __shared__ char smc[];
    uint32_t sb = smem_u32(smc);

    int tid = threadIdx.x;
    int lane = tid & 31, wid = tid >> 5;
    int wm = wid >> 1, wn = wid & 1;
    int g = lane >> 2, qp = lane & 3;
    int bm = blockIdx.y * TM;
    int bn = blockIdx.x * TN;
    int nch = Kp >> 6;

    const char* Abase = (const char*)(Ap + (size_t)bm*Kp);
    const char* Bbase = (const char*)(Bp + (size_t)bn*Kp);
    const size_t rowb = (size_t)Kp*2;

    int lr_ = tid >> 3, lc_ = (tid & 7)*16;
    auto loadStage = [&](int c, int s){
        uint32_t da = sb + (uint32_t)s*STGB;
        uint32_t db = da + ABY;
        const char* sa = Abase + (size_t)c*128 + (size_t)lr_*rowb + lc_;
        const char* sbp= Bbase + (size_t)c*128 + (size_t)lr_*rowb + lc_;
        uint32_t so = (uint32_t)(lr_*(RS*2) + lc_);
#pragma unroll
        for (int t=0;t<4;t++){
            cp16(da + so + t*32*(RS*2), sa + (size_t)t*32*rowb);
            cp16(db + so + t*32*(RS*2), sbp + (size_t)t*32*rowb);
        }
        cp_commit();
    };

    uint32_t a_off[2], b_off[4];
#pragma unroll
    for (int mf=0; mf<2; mf++){
        int arow = wm*32 + mf*16 + (lane & 15);
        a_off[mf] = (uint32_t)(arow*(RS*2) + ((lane & 16) ? 16 : 0));
    }
#pragma unroll
    for (int p=0; p<4; p++){
        int nrow = wn*64 + p*16 + (lane & 7) + ((lane & 16) >> 1);
        b_off[p] = (uint32_t)(nrow*(RS*2) + ((lane & 8) ? 16 : 0)) + ABY;
    }

    float acc[2][8][4];
#pragma unroll
    for (int i=0;i<2;i++)
#pragma unroll
        for (int j=0;j<8;j++)
#pragma unroll
            for (int k=0;k<4;k++) acc[i][j][k]=0.f;

    loadStage(0,0); loadStage(1,1);

    int cur = 0, nxt = 2;
    for (int i=0;i<nch;i++){
        cp_wait<NSTG-2>();
        __syncthreads();
        if (i+2 < nch) loadStage(i+2, nxt);
        else cp_commit();
        uint32_t S = sb + (uint32_t)cur*STGB;
#pragma unroll
        for (int ks=0; ks<4; ks++){
            uint32_t koff = (uint32_t)(ks*32);
            uint32_t a[2][4];
            ldsm4(a[0][0],a[0][1],a[0][2],a[0][3], S + a_off[0] + koff);
            ldsm4(a[1][0],a[1][1],a[1][2],a[1][3], S + a_off[1] + koff);
            uint32_t b[8][2];
#pragma unroll
            for (int p=0; p<4; p++)
                ldsm4(b[2*p][0],b[2*p][1],b[2*p+1][0],b[2*p+1][1],
                      S + b_off[p] + koff);
#pragma unroll
            for (int mf=0; mf<2; mf++)
#pragma unroll
                for (int nf=0; nf<8; nf++)
                    mma_f16(acc[mf][nf], a[mf], b[nf]);
        }
        cur = (cur==NSTG-1) ? 0 : cur+1;
        nxt = (nxt==NSTG-1) ? 0 : nxt+1;
    }

    // ---- epilogue ----
#pragma unroll
    for (int mf=0; mf<2; mf++){
#pragma unroll
        for (int half=0; half<2; half++){
            int m = bm + wm*32 + mf*16 + g + half*8;
#pragma unroll
            for (int nf=0; nf<8; nf++){
                int n = bn + wn*64 + nf*8 + qp*2;
                float v0 = acc[mf][nf][half*2+0];
                float v1 = acc[mf][nf][half*2+1];
                if (mode==2){
                    float2 rr = *(const float2*)&res[(size_t)m*Np + n];
                    v0 += bias0[n]   + rr.x;
                    v1 += bias0[n+1] + rr.y;
                    *(float2*)&C0[(size_t)m*Np + n] = make_float2(v0, v1);
                } else if (mode==4){
                    int sel = n >> 9;
                    int col = n & 511;
                    const float* bs = (sel==0) ? bias0 : (sel==1) ? bias1 : bias2;
                    v0 += bs[col]; v1 += bs[col+1];
                    if (sel < 2){
                        v0 = (v0 > 0.f) ? (v0+1.f) : expf(v0);
                        v1 = (v1 > 0.f) ? (v1+1.f) : expf(v1);
                    }
                    __half* Hs = (sel==0) ? H0 : (sel==1) ? H1 : H2;
                    *(uint32_t*)&Hs[(size_t)m*512 + col] =
                        pack2h(__float2half_rn(v0), __float2half_rn(v1));
                } else { // mode 3: relu -> fp16
                    v0 = fmaxf(v0 + bias0[n],   0.f);
                    v1 = fmaxf(v1 + bias0[n+1], 0.f);
                    *(uint32_t*)&C3[(size_t)m*Np + n] =
                        pack2h(__float2half_rn(v0), __float2half_rn(v1));
                }
            }
        }
    }
}

// ---------- per-chunk K^T V and K sums via tensor cores (4 CTAs/SM) ----------
__global__ __launch_bounds__(256, 4) void chunk_sums_kernel(
    const __half* __restrict__ Kf, const __half* __restrict__ Vf,
    float* __restrict__ ckv, float* __restrict__ cz)
{
    __shared__ __half Kt[64*HRS];
    __shared__ __half Vt[64*HRS];
    int blk = blockIdx.x;
    int c = blk % NC, bh = blk / NC;
    int b = bh / NH, h = bh % NH;
    int t0 = c*CHK;
    int tid = threadIdx.x;
    int lr = tid >> 4, lc = (tid & 15)*4;
    for (int r = lr; r < 64; r += 16){
        size_t gi = ((size_t)(b*TT + t0 + r))*DM + h*DH + lc;
        uint2 kv = *(const uint2*)(Kf+gi);
        uint2 vv = *(const uint2*)(Vf+gi);
        const __half* kp = (const __half*)&kv;
        const __half* vp = (const __half*)&vv;
#pragma unroll
        for (int i=0;i<4;i++){
            Kt[(lc+i)*HRS + r] = kp[i];
            Vt[(lc+i)*HRS + r] = vp[i];
        }
    }
    __syncthreads();

    int lane = tid & 31, wid = tid >> 5;
    int mr = (wid & 3)*16, nb = (wid >> 2)*32;
    int g = lane >> 2, qp = lane & 3;
    uint32_t sbK = smem_u32(Kt), sbV = smem_u32(Vt);
    uint32_t aoff = sbK + (uint32_t)((mr + (lane & 15))*(HRS*2) + ((lane & 16) ? 16 : 0));
    uint32_t boff[2];
#pragma unroll
    for (int p=0;p<2;p++){
        int nrow = nb + p*16 + (lane & 7) + ((lane & 16) >> 1);
        boff[p] = sbV + (uint32_t)(nrow*(HRS*2) + ((lane & 8) ? 16 : 0));
    }
    float acc[4][4];
#pragma unroll
    for (int i=0;i<4;i++)
#pragma unroll
        for (int j=0;j<4;j++) acc[i][j]=0.f;
#pragma unroll
    for (int ks=0; ks<4; ks++){
        uint32_t koff = (uint32_t)(ks*32);
        uint32_t a[4];
        ldsm4(a[0],a[1],a[2],a[3], aoff + koff);
        uint32_t bfr[4][2];
#pragma unroll
        for (int p=0;p<2;p++)
            ldsm4(bfr[2*p][0],bfr[2*p][1],bfr[2*p+1][0],bfr[2*p+1][1],
                  boff[p] + koff);
#pragma unroll
        for (int nf=0;nf<4;nf++) mma_f16(acc[nf], a, bfr[nf]);
    }
    float* outp = ckv + (size_t)blk*DH*DH;
#pragma unroll
    for (int nf=0;nf<4;nf++){
        int m = nb + nf*8 + qp*2;
        *(float2*)&outp[(mr+g)*DH + m]   = make_float2(acc[nf][0], acc[nf][1]);
        *(float2*)&outp[(mr+g+8)*DH + m] = make_float2(acc[nf][2], acc[nf][3]);
    }
    if (tid < DH){
        float z = 0.f;
#pragma unroll 8
        for (int t=0;t<64;t++) z += __half2float(Kt[tid*HRS + t]);
        cz[(size_t)blk*DH + tid] = z;
    }
}

// --- parallel exclusive scan: 2 threads/element, fp16 Sp output ---
// grid = BH*32 blocks, 256 threads. Block covers 128 elements x 2 halves.
__global__ __launch_bounds__(256) void scan_kernel(
    const float* __restrict__ ckv, const float* __restrict__ cz,
    __half* __restrict__ Sp, float* __restrict__ zp)
{
    int bh  = blockIdx.x >> 5;
    int seg = blockIdx.x & 31;
    int tid = threadIdx.x;
    int e   = seg*128 + (tid & 127);
    int hf  = tid >> 7;
    size_t base = ((size_t)bh*NC)*(DH*DH) + e;
    const size_t cs = (size_t)DH*DH;

    float v[16];
#pragma unroll
    for (int c=0;c<16;c++) v[c] = ckv[base + (size_t)c*cs];
    if (hf == 0){
        float s = 0.f;
#pragma unroll
        for (int c=0;c<16;c++){
            Sp[base + (size_t)c*cs] = __float2half_rn(s);
            s += v[c];
        }
    } else {
        float s = 0.f;
#pragma unroll
        for (int c=0;c<16;c++) s += v[c];
        float v2[16];
#pragma unroll
        for (int c=0;c<16;c++) v2[c] = ckv[base + (size_t)(16+c)*cs];
#pragma unroll
        for (int c=0;c<16;c++){
            Sp[base + (size_t)(16+c)*cs] = __float2half_rn(s);
            s += v2[c];
        }
    }

    if (seg==0 && tid < DH){
        size_t zb = (size_t)bh*NC*DH + tid;
        float zv[NC];
#pragma unroll
        for (int c=0;c<NC;c++) zv[c] = cz[zb + (size_t)c*DH];
        float z = 0.f;
#pragma unroll
        for (int c=0;c<NC;c++){ zp[zb + (size_t)c*DH] = z; z += zv[c]; }
    }
}

// ---------- intra-chunk attention via tensor cores (3 CTAs/SM) ----------
__global__ __launch_bounds__(256, 3) void intra_kernel(
    const __half* __restrict__ Qf, const __half* __restrict__ Kf,
    const __half* __restrict__ Vf, const __half* __restrict__ Sp,
    const float* __restrict__ zp, __half* __restrict__ attn1)
{
    __shared__ __half Qs[64*HRS];   // [t][d]
    __shared__ __half Ks[64*HRS];   // [j][d]
    __shared__ __half Vt[64*HRS];   // [m][j]
    __shared__ __half St[64*HRS];   // [m][d]
    __shared__ __half Ss[64*HRS];   // [t][j]
    __shared__ float zs[64], dn[64], dnp[2][64];

    int blk = blockIdx.x;
    int c = blk % NC, bh = blk / NC;
    int b = bh / NH, h = bh % NH;
    int t0 = c*CHK;
    int tid = threadIdx.x;
    int lr = tid >> 4, lc = (tid & 15)*4;

    for (int r = lr; r < 64; r += 16){
        size_t gi = ((size_t)(b*TT + t0 + r))*DM + h*DH + lc;
        uint2 q = *(const uint2*)(Qf+gi);
        uint2 k = *(const uint2*)(Kf+gi);
        uint2 v = *(const uint2*)(Vf+gi);
        *(uint2*)&Qs[r*HRS + lc] = q;
        *(uint2*)&Ks[r*HRS + lc] = k;
        const __half* vp = (const __half*)&v;
#pragma unroll
        for (int i=0;i<4;i++) Vt[(lc+i)*HRS + r] = vp[i];
    }
    {
        size_t base = (size_t)blk*(DH*DH);
        for (int e = tid*4; e < DH*DH; e += 1024){
            uint2 sv = *(const uint2*)(Sp + base + e);
            const __half* sp = (const __half*)&sv;
            int d = e >> 6, m = e & 63;
            St[(m+0)*HRS + d] = sp[0];
            St[(m+1)*HRS + d] = sp[1];
            St[(m+2)*HRS + d] = sp[2];
            St[(m+3)*HRS + d] = sp[3];
        }
    }
    if (tid < DH) zs[tid] = zp[(size_t)blk*DH + tid];
    __syncthreads();

    int lane = tid & 31, wid = tid >> 5;
    int mr = (wid & 3)*16, nb = (wid >> 2)*32;
    int g = lane >> 2, qp = lane & 3;
    uint32_t sbQ = smem_u32(Qs), sbK = smem_u32(Ks);
    uint32_t sbV = smem_u32(Vt), sbSt = smem_u32(St), sbSs = smem_u32(Ss);

    uint32_t a_lane = (uint32_t)((mr + (lane & 15))*(HRS*2) + ((lane & 16) ? 16 : 0));
    uint32_t b_lane[2];
#pragma unroll
    for (int p=0;p<2;p++){
        int nrow = nb + p*16 + (lane & 7) + ((lane & 16) >> 1);
        b_lane[p] = (uint32_t)(nrow*(HRS*2) + ((lane & 8) ? 16 : 0));
    }

    // ---- GEMM1: S = Q K^T ----
    float acc[4][4];
#pragma unroll
    for (int i=0;i<4;i++)
#pragma unroll
        for (int j=0;j<4;j++) acc[i][j]=0.f;
#pragma unroll
    for (int ks=0; ks<4; ks++){
        uint32_t koff = (uint32_t)(ks*32);
        uint32_t a[4];
        ldsm4(a[0],a[1],a[2],a[3], sbQ + a_lane + koff);
        uint32_t bfr[4][2];
#pragma unroll
        for (int p=0;p<2;p++)
            ldsm4(bfr[2*p][0],bfr[2*p][1],bfr[2*p+1][0],bfr[2*p+1][1],
                  sbK + b_lane[p] + koff);
#pragma unroll
        for (int nf=0;nf<4;nf++) mma_f16(acc[nf], a, bfr[nf]);
    }

    // ---- mask, den partials, store Ss ----
    int r0 = mr + g, r1 = mr + g + 8;
    float slo = 0.f, shi = 0.f;
#pragma unroll
    for (int nf=0;nf<4;nf++){
        int col = nb + nf*8 + qp*2;
        float c0 = (col   <= r0) ? acc[nf][0] : 0.f;
        float c1 = (col+1 <= r0) ? acc[nf][1] : 0.f;
        float c2 = (col   <= r1) ? acc[nf][2] : 0.f;
        float c3 = (col+1 <= r1) ? acc[nf][3] : 0.f;
        slo += c0 + c1; shi += c2 + c3;
        *(uint32_t*)&Ss[r0*HRS + col] = pack2h(__float2half_rn(c0), __float2half_rn(c1));
        *(uint32_t*)&Ss[r1*HRS + col] = pack2h(__float2half_rn(c2), __float2half_rn(c3));
    }
    slo += __shfl_xor_sync(0xffffffffu, slo, 1);
    slo += __shfl_xor_sync(0xffffffffu, slo, 2);
    shi += __shfl_xor_sync(0xffffffffu, shi, 1);
    shi += __shfl_xor_sync(0xffffffffu, shi, 2);
    if (qp == 0){
        dnp[wid>>2][r0] = slo;
        dnp[wid>>2][r1] = shi;
    }
    __syncthreads();
    if (tid < 64){
        float dsum = dnp[0][tid] + dnp[1][tid];
#pragma unroll 8
        for (int d=0; d<64; d++)
            dsum += __half2float(Qs[tid*HRS + d]) * zs[d];
        dn[tid] = fmaxf(dsum, 1e-6f);
    }
    __syncthreads();

    // ---- GEMM2: num = Ss@Vt + Qs@St ----
    float acc2[4][4];
#pragma unroll
    for (int i=0;i<4;i++)
#pragma unroll
        for (int j=0;j<4;j++) acc2[i][j]=0.f;
#pragma unroll
    for (int ks=0; ks<4; ks++){
        uint32_t koff = (uint32_t)(ks*32);
        uint32_t a[4];
        ldsm4(a[0],a[1],a[2],a[3], sbSs + a_lane + koff);
        uint32_t bfr[4][2];
#pragma unroll
        for (int p=0;p<2;p++)
            ldsm4(bfr[2*p][0],bfr[2*p][1],bfr[2*p+1][0],bfr[2*p+1][1],
                  sbV + b_lane[p] + koff);
#pragma unroll
        for (int nf=0;nf<4;nf++) mma_f16(acc2[nf], a, bfr[nf]);
    }
#pragma unroll
    for (int ks=0; ks<4; ks++){
        uint32_t koff = (uint32_t)(ks*32);
        uint32_t a[4];
        ldsm4(a[0],a[1],a[2],a[3], sbQ + a_lane + koff);
        uint32_t bfr[4][2];
#pragma unroll
        for (int p=0;p<2;p++)
            ldsm4(bfr[2*p][0],bfr[2*p][1],bfr[2*p+1][0],bfr[2*p+1][1],
                  sbSt + b_lane[p] + koff);
#pragma unroll
        for (int nf=0;nf<4;nf++) mma_f16(acc2[nf], a, bfr[nf]);
    }

    float inv0 = 1.0f / dn[r0];
    float inv1 = 1.0f / dn[r1];
#pragma unroll
    for (int nf=0;nf<4;nf++){
        int col = nb + nf*8 + qp*2;
        size_t g0 = ((size_t)(b*TT + t0 + r0))*DM + h*DH + col;
        size_t g1 = ((size_t)(b*TT + t0 + r1))*DM + h*DH + col;
        *(uint32_t*)&attn1[g0] = pack2h(__float2half_rn(acc2[nf][0]*inv0),
                                        __float2half_rn(acc2[nf][1]*inv0));
        *(uint32_t*)&attn1[g1] = pack2h(__float2half_rn(acc2[nf][2]*inv1),
                                        __float2half_rn(acc2[nf][3]*inv1));
    }
}

// ---------------- launch ----------------
extern "C" void kernel_launch(void* const* d_in, const int* in_sizes, int n_in,
                              void* d_out, int out_size)
{
    (void)in_sizes; (void)n_in; (void)out_size;
    const float* x     = (const float*)d_in[0];
    const float* ln1_g = (const float*)d_in[1];
    const float* ln1_b = (const float*)d_in[2];
    const float* Wq    = (const float*)d_in[3];
    const float* bq    = (const float*)d_in[4];
    const float* Wk    = (const float*)d_in[5];
    const float* bk    = (const float*)d_in[6];
    const float* Wv    = (const float*)d_in[7];
    const float* bv    = (const float*)d_in[8];
    const float* Wo    = (const float*)d_in[9];
    const float* bo    = (const float*)d_in[10];
    const float* ln2_g = (const float*)d_in[11];
    const float* ln2_b = (const float*)d_in[12];
    const float* W1    = (const float*)d_in[13];
    const float* b1    = (const float*)d_in[14];
    const float* W2    = (const float*)d_in[15];
    const float* b2    = (const float*)d_in[16];
    float* out = (float*)d_out;

    static bool attr_done = false;
    if (!attr_done){
        cudaFuncSetAttribute(mm_kernel, cudaFuncAttributeMaxDynamicSharedMemorySize,
                             SMEM_MM);
        attr_done = true;
    }

    __half *h1b,*attn1b,*h22b,*ffn1b,*wqkvb,*wob,*w1b,*w2b,*qb,*kb,*vb,*Spb;
    float *x2b,*ckvb,*czb,*zpb;
    cudaGetSymbolAddress((void**)&h1b,   g_h1);
    cudaGetSymbolAddress((void**)&qb,    g_q);
    cudaGetSymbolAddress((void**)&kb,    g_k);
    cudaGetSymbolAddress((void**)&vb,    g_v);
    cudaGetSymbolAddress((void**)&attn1b,g_attn1);
    cudaGetSymbolAddress((void**)&x2b,   g_x2);
    cudaGetSymbolAddress((void**)&h22b,  g_h22);
    cudaGetSymbolAddress((void**)&ffn1b, g_ffn1);
    cudaGetSymbolAddress((void**)&wqkvb, g_wqkv);
    cudaGetSymbolAddress((void**)&wob,   g_wo);
    cudaGetSymbolAddress((void**)&w1b,   g_w1);
    cudaGetSymbolAddress((void**)&w2b,   g_w2);
    cudaGetSymbolAddress((void**)&ckvb,  g_ckv);
    cudaGetSymbolAddress((void**)&czb,   g_cz);
    cudaGetSymbolAddress((void**)&Spb,   g_Sp);
    cudaGetSymbolAddress((void**)&zpb,   g_zp);

    dim3 gQKV(3*DM/TN, MM/TM);      // (12, 32)
    dim3 gFF(DFF/TN, MM/TM);        // (16, 32)
    dim3 gDM(DM/TN, MM/TM);         // (4, 32)

    // sublayer 1 (LN1 + weight conversion fused into one launch)
    pre_kernel<<<MM + 1536, 256>>>(x, ln1_g, ln1_b, h1b,
                                   Wq, Wk, Wv, Wo, W1, W2,
                                   wqkvb, wob, w1b, w2b);
    mm_kernel<<<gQKV, 256, SMEM_MM>>>(h1b, wqkvb, bq, bk, bv, nullptr,
                                      nullptr, qb, kb, vb, nullptr,
                                      DM, DM, 4);
    chunk_sums_kernel<<<BH*NC, 256>>>(kb, vb, ckvb, czb);
    scan_kernel<<<BH*32, 256>>>(ckvb, czb, Spb, zpb);
    intra_kernel<<<BH*NC, 256>>>(qb, kb, vb, Spb, zpb, attn1b);
    mm_kernel<<<gDM, 256, SMEM_MM>>>(attn1b, wob, bo, nullptr, nullptr, x,
                                     x2b, nullptr, nullptr, nullptr, nullptr,
                                     DM, DM, 2);
    lnh_kernel<<<MM, 256>>>(x2b, ln2_g, ln2_b, h22b);

    // sublayer 2
    mm_kernel<<<gFF, 256, SMEM_MM>>>(h22b, w1b, b1, nullptr, nullptr, nullptr,
                                     nullptr, nullptr, nullptr, nullptr, ffn1b,
                                     DFF, DM, 3);
    mm_kernel<<<gDM, 256, SMEM_MM>>>(ffn1b, w2b, b2, nullptr, nullptr, x2b,
                                     out, nullptr, nullptr, nullptr, nullptr,
                                     DM, DFF, 2);
}